// round 5
// baseline (speedup 1.0000x reference)
#include <cuda_runtime.h>
#include <cuda_bf16.h>
#include <cstdint>

#define B_ 32768
#define D_ 768
#define H_ 1024
#define L_ 256

// ---------------- GEMM tiling ----------------
#define TM 128
#define TN 128
#define TK 32                        // fp32 per K-chunk
#define PAD 36                       // smem floats per row (conflict-free)
#define ROW_BYTES (PAD * 4)          // 144
#define TILE_BYTES (128 * ROW_BYTES) // 18432
#define STAGE_BYTES (2 * TILE_BYTES) // A tile + W tile
#define NSTAGE 4
#define SM_TOTAL (NSTAGE * STAGE_BYTES)  // 147456

// ---------------- scratch ----------------
static __device__ float g_buf0[(size_t)B_ * 2048];
static __device__ float g_buf1[(size_t)B_ * 2048];

// ---------------- helpers ----------------
__device__ __forceinline__ uint32_t smem_u32(const void* p) {
    uint32_t a;
    asm("{ .reg .u64 t; cvta.to.shared.u64 t, %1; cvt.u32.u64 %0, t; }" : "=r"(a) : "l"(p));
    return a;
}
__device__ __forceinline__ void cp16(uint32_t sa, const void* g) {
    asm volatile("cp.async.cg.shared.global [%0], [%1], 16;" :: "r"(sa), "l"(g));
}
__device__ __forceinline__ uint32_t f2tf32(float f) {
    uint32_t r;
    asm("cvt.rna.tf32.f32 %0, %1;" : "=r"(r) : "f"(f));
    return r;
}
__device__ __forceinline__ void mma8(float* c, uint32_t a0, uint32_t a1, uint32_t a2, uint32_t a3,
                                     uint32_t b0, uint32_t b1) {
    asm volatile("mma.sync.aligned.m16n8k8.row.col.f32.tf32.tf32.f32 "
                 "{%0,%1,%2,%3}, {%4,%5,%6,%7}, {%8,%9}, {%0,%1,%2,%3};"
                 : "+f"(c[0]), "+f"(c[1]), "+f"(c[2]), "+f"(c[3])
                 : "r"(a0), "r"(a1), "r"(a2), "r"(a3), "r"(b0), "r"(b1));
}

// ===================================================================
// GEMM: C[B, Nt] = A[B, K] @ W[Nt, K]^T + bias ; mode=1 -> leaky relu
// Tile: CTA 128x128, warp 64x32 (warps 2x4), k-chunk 32, 4-stage cp.async.
// ===================================================================
extern "C" __global__ void __launch_bounds__(256, 1)
gemm_tf32(const float* __restrict__ A, const float* __restrict__ W,
          const float* __restrict__ bias, float* __restrict__ C,
          int K, int Nt, int mode)
{
    extern __shared__ char smem[];
    const uint32_t sb = smem_u32(smem);
    const int tid = threadIdx.x;
    const int wid = tid >> 5;
    const int lid = tid & 31;
    const int g = lid >> 2;     // groupID (0..7)
    const int t = lid & 3;      // thread-in-group (0..3)
    const int m0 = blockIdx.y * TM;
    const int n0 = blockIdx.x * TN;
    const int wm = (wid & 1) * 64;    // warp M offset
    const int wn = (wid >> 1) * 32;   // warp N offset

    // per-thread cp.async mapping: 2048 16B chunks/stage, 8 per thread.
    // chunks 0..1023: A tile rows, 1024..2047: W tile rows. 8 chunks per row.
    const char* srcp[8]; uint32_t dstp[8];
#pragma unroll
    for (int i = 0; i < 8; i++) {
        int c = tid + i * 256;
        if (c < 1024) {
            int row = c >> 3, seg = c & 7;
            srcp[i] = (const char*)A + (size_t)(m0 + row) * K * 4 + seg * 16;
            dstp[i] = sb + row * ROW_BYTES + seg * 16;
        } else {
            int row = (c - 1024) >> 3, seg = c & 7;
            srcp[i] = (const char*)W + (size_t)(n0 + row) * K * 4 + seg * 16;
            dstp[i] = sb + TILE_BYTES + row * ROW_BYTES + seg * 16;
        }
    }

    const int KC = K >> 5;   // K-chunks; all layer K's are multiples of 32, KC >= NSTAGE

    // prologue: fill all stages
#pragma unroll
    for (int s = 0; s < NSTAGE; s++) {
#pragma unroll
        for (int i = 0; i < 8; i++) cp16(dstp[i] + s * STAGE_BYTES, srcp[i] + (size_t)s * (TK * 4));
        asm volatile("cp.async.commit_group;" ::: "memory");
    }

    float acc[4][4][4];
#pragma unroll
    for (int mf = 0; mf < 4; mf++)
#pragma unroll
        for (int nf = 0; nf < 4; nf++)
#pragma unroll
            for (int j = 0; j < 4; j++) acc[mf][nf][j] = 0.f;

    for (int kc = 0; kc < KC; kc++) {
        int pend = KC - 1 - kc;
        if (pend >= 3)      asm volatile("cp.async.wait_group 3;" ::: "memory");
        else if (pend == 2) asm volatile("cp.async.wait_group 2;" ::: "memory");
        else if (pend == 1) asm volatile("cp.async.wait_group 1;" ::: "memory");
        else                asm volatile("cp.async.wait_group 0;" ::: "memory");
        __syncthreads();

        const int slot = kc & (NSTAGE - 1);
        const float* sA = (const float*)(smem + slot * STAGE_BYTES);
        const float* sW = (const float*)(smem + slot * STAGE_BYTES + TILE_BYTES);

#pragma unroll
        for (int ks = 0; ks < 4; ks++) {
            const int kb = ks * 8;
            uint32_t a[4][4], b[4][2];
#pragma unroll
            for (int mf = 0; mf < 4; mf++) {
                const int mb = wm + mf * 16;
                a[mf][0] = f2tf32(sA[(mb + g) * PAD + kb + t]);
                a[mf][1] = f2tf32(sA[(mb + 8 + g) * PAD + kb + t]);
                a[mf][2] = f2tf32(sA[(mb + g) * PAD + kb + t + 4]);
                a[mf][3] = f2tf32(sA[(mb + 8 + g) * PAD + kb + t + 4]);
            }
#pragma unroll
            for (int nf = 0; nf < 4; nf++) {
                const int nb = wn + nf * 8;
                b[nf][0] = f2tf32(sW[(nb + g) * PAD + kb + t]);
                b[nf][1] = f2tf32(sW[(nb + g) * PAD + kb + t + 4]);
            }
#pragma unroll
            for (int mf = 0; mf < 4; mf++)
#pragma unroll
                for (int nf = 0; nf < 4; nf++)
                    mma8(acc[mf][nf], a[mf][0], a[mf][1], a[mf][2], a[mf][3],
                         b[nf][0], b[nf][1]);
        }
        __syncthreads();   // all warps done reading slot before refill

        if (kc + NSTAGE < KC) {
            size_t ko = (size_t)(kc + NSTAGE) * (TK * 4);
#pragma unroll
            for (int i = 0; i < 8; i++) cp16(dstp[i] + slot * STAGE_BYTES, srcp[i] + ko);
            asm volatile("cp.async.commit_group;" ::: "memory");
        }
    }

    // ---- epilogue: bias (+lrelu), coalesced float2 stores ----
#pragma unroll
    for (int nf = 0; nf < 4; nf++) {
        const int n = n0 + wn + nf * 8 + t * 2;
        const float2 bn = *(const float2*)(bias + n);
#pragma unroll
        for (int mf = 0; mf < 4; mf++) {
            const int m = m0 + wm + mf * 16 + g;
            float v0 = acc[mf][nf][0] + bn.x;
            float v1 = acc[mf][nf][1] + bn.y;
            float v2 = acc[mf][nf][2] + bn.x;
            float v3 = acc[mf][nf][3] + bn.y;
            if (mode) {
                v0 = v0 >= 0.f ? v0 : 0.2f * v0;
                v1 = v1 >= 0.f ? v1 : 0.2f * v1;
                v2 = v2 >= 0.f ? v2 : 0.2f * v2;
                v3 = v3 >= 0.f ? v3 : 0.2f * v3;
            }
            *(float2*)(C + (size_t)m * Nt + n)       = make_float2(v0, v1);
            *(float2*)(C + (size_t)(m + 8) * Nt + n) = make_float2(v2, v3);
        }
    }
}

// ===================================================================
// LayerNorm + leaky relu; one 256-thread block per row, H in {1024, 2048}
// ===================================================================
extern "C" __global__ void __launch_bounds__(256)
ln_lrelu(const float* __restrict__ X, float* __restrict__ Y,
         const float* __restrict__ g, const float* __restrict__ b, int H)
{
    __shared__ float red[16];
    const int r = blockIdx.x;
    const int t = threadIdx.x;
    const float* x = X + (size_t)r * H;
    float* y = Y + (size_t)r * H;
    const int V = H >> 8;         // 4 or 8
    float v[8];
    float s = 0.f, s2 = 0.f;
#pragma unroll 8
    for (int i = 0; i < V; i++) {
        v[i] = x[t + (i << 8)];
        s += v[i]; s2 += v[i] * v[i];
    }
#pragma unroll
    for (int o = 16; o; o >>= 1) {
        s  += __shfl_xor_sync(~0u, s,  o);
        s2 += __shfl_xor_sync(~0u, s2, o);
    }
    if ((t & 31) == 0) { red[t >> 5] = s; red[8 + (t >> 5)] = s2; }
    __syncthreads();
    if (t < 32) {
        float a  = (t < 8) ? red[t]     : 0.f;
        float a2 = (t < 8) ? red[8 + t] : 0.f;
#pragma unroll
        for (int o = 4; o; o >>= 1) {
            a  += __shfl_xor_sync(~0u, a,  o);
            a2 += __shfl_xor_sync(~0u, a2, o);
        }
        if (t == 0) { red[0] = a; red[8] = a2; }
    }
    __syncthreads();
    const float inv = 1.f / (float)H;
    const float mu = red[0] * inv;
    const float var = red[8] * inv - mu * mu;
    const float rs = rsqrtf(var + 1e-5f);
#pragma unroll 8
    for (int i = 0; i < V; i++) {
        int c = t + (i << 8);
        float o = (v[i] - mu) * rs * g[c] + b[c];
        y[c] = o >= 0.f ? o : 0.2f * o;
    }
}

// ===================================================================
// Reparameterize + context-memory attention. One warp per row.
// z = mu + eps*exp(0.5 lv); attn = softmax(z@ctx^T); zout = z + 0.1*attn@ctx
// ===================================================================
extern "C" __global__ void __launch_bounds__(256)
reparam_attn(const float* __restrict__ mu, const float* __restrict__ lv,
             const float* __restrict__ eps, const float* __restrict__ ctx,
             float* __restrict__ zout)
{
    __shared__ float sctx[32 * 257];
    __shared__ float sz[8][256];
    __shared__ float sat[8][32];
    const int t = threadIdx.x, w = t >> 5, l = t & 31;
    for (int i = t; i < 32 * 256; i += 256) {
        int m = i >> 8, k = i & 255;
        sctx[m * 257 + k] = ctx[i];
    }
    __syncthreads();
    const size_t r = (size_t)blockIdx.x * 8 + w;
    const float* murow = mu + r * 256;
    const float* lvrow = lv + r * 256;
    const float* erow  = eps + r * 256;
    float z[8];
#pragma unroll
    for (int i = 0; i < 8; i++) {
        int k = l + (i << 5);
        z[i] = murow[k] + erow[k] * expf(0.5f * lvrow[k]);
        sz[w][k] = z[i];
    }
    __syncwarp();
    // lane l = context slot m
    float dot = 0.f;
    const float* cm = &sctx[l * 257];
#pragma unroll 8
    for (int k = 0; k < 256; k++) dot += sz[w][k] * cm[k];
    float mx = dot;
#pragma unroll
    for (int o = 16; o; o >>= 1) mx = fmaxf(mx, __shfl_xor_sync(~0u, mx, o));
    float e = expf(dot - mx);
    float sum = e;
#pragma unroll
    for (int o = 16; o; o >>= 1) sum += __shfl_xor_sync(~0u, sum, o);
    sat[w][l] = e / sum;
    __syncwarp();
    float* zo = zout + r * 256;
#pragma unroll
    for (int i = 0; i < 8; i++) {
        int k = l + (i << 5);
        float acc = 0.f;
#pragma unroll
        for (int m = 0; m < 32; m++) acc += sat[w][m] * sctx[m * 257 + k];
        zo[k] = z[i] + 0.1f * acc;
    }
}

// ===================================================================
extern "C" void kernel_launch(void* const* d_in, const int* in_sizes, int n_in,
                              void* d_out, int out_size)
{
    (void)in_sizes; (void)n_in; (void)out_size;
    const float* x      = (const float*)d_in[0];
    const float* eps    = (const float*)d_in[1];
    const float* enc_w1 = (const float*)d_in[2];
    const float* enc_b1 = (const float*)d_in[3];
    const float* ln1_g  = (const float*)d_in[4];
    const float* ln1_b  = (const float*)d_in[5];
    const float* enc_w2 = (const float*)d_in[6];
    const float* enc_b2 = (const float*)d_in[7];
    const float* ln2_g  = (const float*)d_in[8];
    const float* ln2_b  = (const float*)d_in[9];
    const float* mu_w   = (const float*)d_in[10];
    const float* mu_b   = (const float*)d_in[11];
    const float* lv_w   = (const float*)d_in[12];
    const float* lv_b   = (const float*)d_in[13];
    const float* di_w   = (const float*)d_in[14];
    const float* di_b   = (const float*)d_in[15];
    const float* dec_w1 = (const float*)d_in[16];
    const float* dec_b1 = (const float*)d_in[17];
    const float* dln1_g = (const float*)d_in[18];
    const float* dln1_b = (const float*)d_in[19];
    const float* dec_w2 = (const float*)d_in[20];
    const float* dec_b2 = (const float*)d_in[21];
    const float* dln2_g = (const float*)d_in[22];
    const float* dln2_b = (const float*)d_in[23];
    const float* dec_w3 = (const float*)d_in[24];
    const float* dec_b3 = (const float*)d_in[25];
    const float* ctx    = (const float*)d_in[26];

    float* out    = (float*)d_out;
    float* out_mu = out + (size_t)B_ * D_;
    float* out_lv = out_mu + (size_t)B_ * L_;

    float* buf0 = nullptr; float* buf1 = nullptr;
    cudaGetSymbolAddress((void**)&buf0, g_buf0);
    cudaGetSymbolAddress((void**)&buf1, g_buf1);

    cudaFuncSetAttribute(gemm_tf32, cudaFuncAttributeMaxDynamicSharedMemorySize, SM_TOTAL);

    const dim3 blk(256);
    const dim3 gH(H_ / TN, B_ / TM);        // (8, 256)
    const dim3 gL(L_ / TN, B_ / TM);        // (2, 256)
    const dim3 g2H(2 * H_ / TN, B_ / TM);   // (16, 256)
    const dim3 gD(D_ / TN, B_ / TM);        // (6, 256)

    // encoder
    gemm_tf32<<<gH, blk, SM_TOTAL>>>(x, enc_w1, enc_b1, buf0, D_, H_, 0);
    ln_lrelu<<<B_, 256>>>(buf0, buf1, ln1_g, ln1_b, H_);
    gemm_tf32<<<gH, blk, SM_TOTAL>>>(buf1, enc_w2, enc_b2, buf0, H_, H_, 0);
    ln_lrelu<<<B_, 256>>>(buf0, buf1, ln2_g, ln2_b, H_);
    gemm_tf32<<<gL, blk, SM_TOTAL>>>(buf1, mu_w, mu_b, out_mu, H_, L_, 0);
    gemm_tf32<<<gL, blk, SM_TOTAL>>>(buf1, lv_w, lv_b, out_lv, H_, L_, 0);
    // reparameterize + context attention
    reparam_attn<<<B_ / 8, 256>>>(out_mu, out_lv, eps, ctx, buf0);
    // decoder
    gemm_tf32<<<gH, blk, SM_TOTAL>>>(buf0, di_w, di_b, buf1, L_, H_, 1);
    gemm_tf32<<<gH, blk, SM_TOTAL>>>(buf1, dec_w1, dec_b1, buf0, H_, H_, 0);
    ln_lrelu<<<B_, 256>>>(buf0, buf1, dln1_g, dln1_b, H_);
    gemm_tf32<<<g2H, blk, SM_TOTAL>>>(buf1, dec_w2, dec_b2, buf0, H_, 2 * H_, 0);
    ln_lrelu<<<B_, 256>>>(buf0, buf1, dln2_g, dln2_b, 2 * H_);
    gemm_tf32<<<gD, blk, SM_TOTAL>>>(buf1, dec_w3, dec_b3, out, 2 * H_, D_, 0);
}

// round 6
// speedup vs baseline: 1.0008x; 1.0008x over previous
#include <cuda_runtime.h>
#include <cuda_bf16.h>
#include <cstdint>

#define B_ 32768
#define D_ 768
#define H_ 1024
#define L_ 256

// ---------------- GEMM tiling ----------------
#define TM 128
#define TN 128
#define TK 32                        // fp32 per K-chunk
#define PAD 36                       // smem floats per row (conflict-free)
#define ROW_BYTES (PAD * 4)          // 144
#define TILE_BYTES (128 * ROW_BYTES) // 18432
#define STAGE_BYTES (2 * TILE_BYTES) // A tile + W tile
#define NSTAGE 4
#define SM_TOTAL (NSTAGE * STAGE_BYTES)  // 147456

// ---------------- scratch ----------------
static __device__ float g_buf0[(size_t)B_ * 2048];
static __device__ float g_buf1[(size_t)B_ * 2048];

// ---------------- helpers ----------------
__device__ __forceinline__ uint32_t smem_u32(const void* p) {
    uint32_t a;
    asm("{ .reg .u64 t; cvta.to.shared.u64 t, %1; cvt.u32.u64 %0, t; }" : "=r"(a) : "l"(p));
    return a;
}
__device__ __forceinline__ void cp16(uint32_t sa, const void* g) {
    asm volatile("cp.async.cg.shared.global [%0], [%1], 16;" :: "r"(sa), "l"(g));
}
__device__ __forceinline__ uint32_t f2tf32(float f) {
    uint32_t r;
    asm("cvt.rna.tf32.f32 %0, %1;" : "=r"(r) : "f"(f));
    return r;
}
__device__ __forceinline__ void mma8(float* c, uint32_t a0, uint32_t a1, uint32_t a2, uint32_t a3,
                                     uint32_t b0, uint32_t b1) {
    asm volatile("mma.sync.aligned.m16n8k8.row.col.f32.tf32.tf32.f32 "
                 "{%0,%1,%2,%3}, {%4,%5,%6,%7}, {%8,%9}, {%0,%1,%2,%3};"
                 : "+f"(c[0]), "+f"(c[1]), "+f"(c[2]), "+f"(c[3])
                 : "r"(a0), "r"(a1), "r"(a2), "r"(a3), "r"(b0), "r"(b1));
}

// ===================================================================
// GEMM: C[B, Nt] = A[B, K] @ W[Nt, K]^T + bias ; mode=1 -> leaky relu
// Tile: CTA 128x128, warp 64x32 (warps 2x4), k-chunk 32, 4-stage cp.async.
// ===================================================================
extern "C" __global__ void __launch_bounds__(256, 1)
gemm_tf32(const float* __restrict__ A, const float* __restrict__ W,
          const float* __restrict__ bias, float* __restrict__ C,
          int K, int Nt, int mode)
{
    extern __shared__ char smem[];
    const uint32_t sb = smem_u32(smem);
    const int tid = threadIdx.x;
    const int wid = tid >> 5;
    const int lid = tid & 31;
    const int g = lid >> 2;     // groupID (0..7)
    const int t = lid & 3;      // thread-in-group (0..3)
    const int m0 = blockIdx.y * TM;
    const int n0 = blockIdx.x * TN;
    const int wm = (wid & 1) * 64;    // warp M offset
    const int wn = (wid >> 1) * 32;   // warp N offset

    // per-thread cp.async mapping: 2048 16B chunks/stage, 8 per thread.
    // chunks 0..1023: A tile rows, 1024..2047: W tile rows. 8 chunks per row.
    const char* srcp[8]; uint32_t dstp[8];
#pragma unroll
    for (int i = 0; i < 8; i++) {
        int c = tid + i * 256;
        if (c < 1024) {
            int row = c >> 3, seg = c & 7;
            srcp[i] = (const char*)A + (size_t)(m0 + row) * K * 4 + seg * 16;
            dstp[i] = sb + row * ROW_BYTES + seg * 16;
        } else {
            int row = (c - 1024) >> 3, seg = c & 7;
            srcp[i] = (const char*)W + (size_t)(n0 + row) * K * 4 + seg * 16;
            dstp[i] = sb + TILE_BYTES + row * ROW_BYTES + seg * 16;
        }
    }

    const int KC = K >> 5;   // K-chunks; all layer K's are multiples of 32, KC >= NSTAGE

    // prologue: fill all stages
#pragma unroll
    for (int s = 0; s < NSTAGE; s++) {
#pragma unroll
        for (int i = 0; i < 8; i++) cp16(dstp[i] + s * STAGE_BYTES, srcp[i] + (size_t)s * (TK * 4));
        asm volatile("cp.async.commit_group;" ::: "memory");
    }

    float acc[4][4][4];
#pragma unroll
    for (int mf = 0; mf < 4; mf++)
#pragma unroll
        for (int nf = 0; nf < 4; nf++)
#pragma unroll
            for (int j = 0; j < 4; j++) acc[mf][nf][j] = 0.f;

    for (int kc = 0; kc < KC; kc++) {
        int pend = KC - 1 - kc;
        if (pend >= 3)      asm volatile("cp.async.wait_group 3;" ::: "memory");
        else if (pend == 2) asm volatile("cp.async.wait_group 2;" ::: "memory");
        else if (pend == 1) asm volatile("cp.async.wait_group 1;" ::: "memory");
        else                asm volatile("cp.async.wait_group 0;" ::: "memory");
        __syncthreads();

        const int slot = kc & (NSTAGE - 1);
        const float* sA = (const float*)(smem + slot * STAGE_BYTES);
        const float* sW = (const float*)(smem + slot * STAGE_BYTES + TILE_BYTES);

#pragma unroll
        for (int ks = 0; ks < 4; ks++) {
            const int kb = ks * 8;
            uint32_t a[4][4], b[4][2];
#pragma unroll
            for (int mf = 0; mf < 4; mf++) {
                const int mb = wm + mf * 16;
                a[mf][0] = f2tf32(sA[(mb + g) * PAD + kb + t]);
                a[mf][1] = f2tf32(sA[(mb + 8 + g) * PAD + kb + t]);
                a[mf][2] = f2tf32(sA[(mb + g) * PAD + kb + t + 4]);
                a[mf][3] = f2tf32(sA[(mb + 8 + g) * PAD + kb + t + 4]);
            }
#pragma unroll
            for (int nf = 0; nf < 4; nf++) {
                const int nb = wn + nf * 8;
                b[nf][0] = f2tf32(sW[(nb + g) * PAD + kb + t]);
                b[nf][1] = f2tf32(sW[(nb + g) * PAD + kb + t + 4]);
            }
#pragma unroll
            for (int mf = 0; mf < 4; mf++)
#pragma unroll
                for (int nf = 0; nf < 4; nf++)
                    mma8(acc[mf][nf], a[mf][0], a[mf][1], a[mf][2], a[mf][3],
                         b[nf][0], b[nf][1]);
        }
        __syncthreads();   // all warps done reading slot before refill

        if (kc + NSTAGE < KC) {
            size_t ko = (size_t)(kc + NSTAGE) * (TK * 4);
#pragma unroll
            for (int i = 0; i < 8; i++) cp16(dstp[i] + slot * STAGE_BYTES, srcp[i] + ko);
            asm volatile("cp.async.commit_group;" ::: "memory");
        }
    }

    // ---- epilogue: bias (+lrelu), coalesced float2 stores ----
#pragma unroll
    for (int nf = 0; nf < 4; nf++) {
        const int n = n0 + wn + nf * 8 + t * 2;
        const float2 bn = *(const float2*)(bias + n);
#pragma unroll
        for (int mf = 0; mf < 4; mf++) {
            const int m = m0 + wm + mf * 16 + g;
            float v0 = acc[mf][nf][0] + bn.x;
            float v1 = acc[mf][nf][1] + bn.y;
            float v2 = acc[mf][nf][2] + bn.x;
            float v3 = acc[mf][nf][3] + bn.y;
            if (mode) {
                v0 = v0 >= 0.f ? v0 : 0.2f * v0;
                v1 = v1 >= 0.f ? v1 : 0.2f * v1;
                v2 = v2 >= 0.f ? v2 : 0.2f * v2;
                v3 = v3 >= 0.f ? v3 : 0.2f * v3;
            }
            *(float2*)(C + (size_t)m * Nt + n)       = make_float2(v0, v1);
            *(float2*)(C + (size_t)(m + 8) * Nt + n) = make_float2(v2, v3);
        }
    }
}

// ===================================================================
// LayerNorm + leaky relu; one 256-thread block per row, H in {1024, 2048}
// ===================================================================
extern "C" __global__ void __launch_bounds__(256)
ln_lrelu(const float* __restrict__ X, float* __restrict__ Y,
         const float* __restrict__ g, const float* __restrict__ b, int H)
{
    __shared__ float red[16];
    const int r = blockIdx.x;
    const int t = threadIdx.x;
    const float* x = X + (size_t)r * H;
    float* y = Y + (size_t)r * H;
    const int V = H >> 8;         // 4 or 8
    float v[8];
    float s = 0.f, s2 = 0.f;
#pragma unroll 8
    for (int i = 0; i < V; i++) {
        v[i] = x[t + (i << 8)];
        s += v[i]; s2 += v[i] * v[i];
    }
#pragma unroll
    for (int o = 16; o; o >>= 1) {
        s  += __shfl_xor_sync(~0u, s,  o);
        s2 += __shfl_xor_sync(~0u, s2, o);
    }
    if ((t & 31) == 0) { red[t >> 5] = s; red[8 + (t >> 5)] = s2; }
    __syncthreads();
    if (t < 32) {
        float a  = (t < 8) ? red[t]     : 0.f;
        float a2 = (t < 8) ? red[8 + t] : 0.f;
#pragma unroll
        for (int o = 4; o; o >>= 1) {
            a  += __shfl_xor_sync(~0u, a,  o);
            a2 += __shfl_xor_sync(~0u, a2, o);
        }
        if (t == 0) { red[0] = a; red[8] = a2; }
    }
    __syncthreads();
    const float inv = 1.f / (float)H;
    const float mu = red[0] * inv;
    const float var = red[8] * inv - mu * mu;
    const float rs = rsqrtf(var + 1e-5f);
#pragma unroll 8
    for (int i = 0; i < V; i++) {
        int c = t + (i << 8);
        float o = (v[i] - mu) * rs * g[c] + b[c];
        y[c] = o >= 0.f ? o : 0.2f * o;
    }
}

// ===================================================================
// Reparameterize + context-memory attention. One warp per row.
// z = mu + eps*exp(0.5 lv); attn = softmax(z@ctx^T); zout = z + 0.1*attn@ctx
// ===================================================================
extern "C" __global__ void __launch_bounds__(256)
reparam_attn(const float* __restrict__ mu, const float* __restrict__ lv,
             const float* __restrict__ eps, const float* __restrict__ ctx,
             float* __restrict__ zout)
{
    __shared__ float sctx[32 * 257];
    __shared__ float sz[8][256];
    __shared__ float sat[8][32];
    const int t = threadIdx.x, w = t >> 5, l = t & 31;
    for (int i = t; i < 32 * 256; i += 256) {
        int m = i >> 8, k = i & 255;
        sctx[m * 257 + k] = ctx[i];
    }
    __syncthreads();
    const size_t r = (size_t)blockIdx.x * 8 + w;
    const float* murow = mu + r * 256;
    const float* lvrow = lv + r * 256;
    const float* erow  = eps + r * 256;
    float z[8];
#pragma unroll
    for (int i = 0; i < 8; i++) {
        int k = l + (i << 5);
        z[i] = murow[k] + erow[k] * expf(0.5f * lvrow[k]);
        sz[w][k] = z[i];
    }
    __syncwarp();
    // lane l = context slot m
    float dot = 0.f;
    const float* cm = &sctx[l * 257];
#pragma unroll 8
    for (int k = 0; k < 256; k++) dot += sz[w][k] * cm[k];
    float mx = dot;
#pragma unroll
    for (int o = 16; o; o >>= 1) mx = fmaxf(mx, __shfl_xor_sync(~0u, mx, o));
    float e = expf(dot - mx);
    float sum = e;
#pragma unroll
    for (int o = 16; o; o >>= 1) sum += __shfl_xor_sync(~0u, sum, o);
    sat[w][l] = e / sum;
    __syncwarp();
    float* zo = zout + r * 256;
#pragma unroll
    for (int i = 0; i < 8; i++) {
        int k = l + (i << 5);
        float acc = 0.f;
#pragma unroll
        for (int m = 0; m < 32; m++) acc += sat[w][m] * sctx[m * 257 + k];
        zo[k] = z[i] + 0.1f * acc;
    }
}

// ===================================================================
extern "C" void kernel_launch(void* const* d_in, const int* in_sizes, int n_in,
                              void* d_out, int out_size)
{
    (void)in_sizes; (void)n_in; (void)out_size;
    const float* x      = (const float*)d_in[0];
    const float* eps    = (const float*)d_in[1];
    const float* enc_w1 = (const float*)d_in[2];
    const float* enc_b1 = (const float*)d_in[3];
    const float* ln1_g  = (const float*)d_in[4];
    const float* ln1_b  = (const float*)d_in[5];
    const float* enc_w2 = (const float*)d_in[6];
    const float* enc_b2 = (const float*)d_in[7];
    const float* ln2_g  = (const float*)d_in[8];
    const float* ln2_b  = (const float*)d_in[9];
    const float* mu_w   = (const float*)d_in[10];
    const float* mu_b   = (const float*)d_in[11];
    const float* lv_w   = (const float*)d_in[12];
    const float* lv_b   = (const float*)d_in[13];
    const float* di_w   = (const float*)d_in[14];
    const float* di_b   = (const float*)d_in[15];
    const float* dec_w1 = (const float*)d_in[16];
    const float* dec_b1 = (const float*)d_in[17];
    const float* dln1_g = (const float*)d_in[18];
    const float* dln1_b = (const float*)d_in[19];
    const float* dec_w2 = (const float*)d_in[20];
    const float* dec_b2 = (const float*)d_in[21];
    const float* dln2_g = (const float*)d_in[22];
    const float* dln2_b = (const float*)d_in[23];
    const float* dec_w3 = (const float*)d_in[24];
    const float* dec_b3 = (const float*)d_in[25];
    const float* ctx    = (const float*)d_in[26];

    float* out    = (float*)d_out;
    float* out_mu = out + (size_t)B_ * D_;
    float* out_lv = out_mu + (size_t)B_ * L_;

    float* buf0 = nullptr; float* buf1 = nullptr;
    cudaGetSymbolAddress((void**)&buf0, g_buf0);
    cudaGetSymbolAddress((void**)&buf1, g_buf1);

    cudaFuncSetAttribute(gemm_tf32, cudaFuncAttributeMaxDynamicSharedMemorySize, SM_TOTAL);

    const dim3 blk(256);
    const dim3 gH(H_ / TN, B_ / TM);        // (8, 256)
    const dim3 gL(L_ / TN, B_ / TM);        // (2, 256)
    const dim3 g2H(2 * H_ / TN, B_ / TM);   // (16, 256)
    const dim3 gD(D_ / TN, B_ / TM);        // (6, 256)

    // encoder
    gemm_tf32<<<gH, blk, SM_TOTAL>>>(x, enc_w1, enc_b1, buf0, D_, H_, 0);
    ln_lrelu<<<B_, 256>>>(buf0, buf1, ln1_g, ln1_b, H_);
    gemm_tf32<<<gH, blk, SM_TOTAL>>>(buf1, enc_w2, enc_b2, buf0, H_, H_, 0);
    ln_lrelu<<<B_, 256>>>(buf0, buf1, ln2_g, ln2_b, H_);
    gemm_tf32<<<gL, blk, SM_TOTAL>>>(buf1, mu_w, mu_b, out_mu, H_, L_, 0);
    gemm_tf32<<<gL, blk, SM_TOTAL>>>(buf1, lv_w, lv_b, out_lv, H_, L_, 0);
    // reparameterize + context attention
    reparam_attn<<<B_ / 8, 256>>>(out_mu, out_lv, eps, ctx, buf0);
    // decoder
    gemm_tf32<<<gH, blk, SM_TOTAL>>>(buf0, di_w, di_b, buf1, L_, H_, 1);
    gemm_tf32<<<gH, blk, SM_TOTAL>>>(buf1, dec_w1, dec_b1, buf0, H_, H_, 0);
    ln_lrelu<<<B_, 256>>>(buf0, buf1, dln1_g, dln1_b, H_);
    gemm_tf32<<<g2H, blk, SM_TOTAL>>>(buf1, dec_w2, dec_b2, buf0, H_, 2 * H_, 0);
    ln_lrelu<<<B_, 256>>>(buf0, buf1, dln2_g, dln2_b, 2 * H_);
    gemm_tf32<<<gD, blk, SM_TOTAL>>>(buf1, dec_w3, dec_b3, out, 2 * H_, D_, 0);
}

// round 7
// speedup vs baseline: 1.1531x; 1.1521x over previous
#include <cuda_runtime.h>
#include <cuda_bf16.h>
#include <cstdint>

#define B_ 32768
#define D_ 768
#define H_ 1024
#define L_ 256

// ---------------- GEMM tiling ----------------
#define TM 128
#define TN 256
#define AT_BYTES (128 * 128)          // A tile per stage: 128 rows x 128B
#define WT_BYTES (256 * 128)          // W tile per stage
#define STG_BYTES (AT_BYTES + WT_BYTES)   // 49152
#define NSTAGE 4
#define SM_TOTAL (NSTAGE * STG_BYTES)     // 196608

// ---------------- scratch ----------------
static __device__ float g_act0[(size_t)B_ * 2048];
static __device__ float g_act1[(size_t)B_ * 2048];
static __device__ float g_cvt[32505856];

// offsets into g_cvt (floats)
#define OFF_X    0
#define OFF_EW1  25165824
#define OFF_EW2  25952256
#define OFF_MUW  27000832
#define OFF_LVW  27262976
#define OFF_DIW  27525120
#define OFF_DW1  27787264
#define OFF_DW2  28835840
#define OFF_DW3  30932992

// ---------------- helpers ----------------
__device__ __forceinline__ uint32_t smem_u32(const void* p) {
    uint32_t a;
    asm("{ .reg .u64 t; cvta.to.shared.u64 t, %1; cvt.u32.u64 %0, t; }" : "=r"(a) : "l"(p));
    return a;
}
__device__ __forceinline__ void cp16(uint32_t sa, const void* g) {
    asm volatile("cp.async.cg.shared.global [%0], [%1], 16;" :: "r"(sa), "l"(g));
}
__device__ __forceinline__ float rtf32(float f) {
    uint32_t r;
    asm("cvt.rna.tf32.f32 %0, %1;" : "=r"(r) : "f"(f));
    return __uint_as_float(r);
}
__device__ __forceinline__ void mma8(float* c, uint32_t a0, uint32_t a1, uint32_t a2, uint32_t a3,
                                     uint32_t b0, uint32_t b1) {
    asm volatile("mma.sync.aligned.m16n8k8.row.col.f32.tf32.tf32.f32 "
                 "{%0,%1,%2,%3}, {%4,%5,%6,%7}, {%8,%9}, {%0,%1,%2,%3};"
                 : "+f"(c[0]), "+f"(c[1]), "+f"(c[2]), "+f"(c[3])
                 : "r"(a0), "r"(a1), "r"(a2), "r"(a3), "r"(b0), "r"(b1));
}
// position of original col c (0..31) inside a 32-col chunk, interleaved layout
__device__ __forceinline__ int perm32(int c) { return (c & 3) * 8 + (c >> 2); }

// ===================================================================
// conv_perm: round to tf32 + apply 32-col interleave. Flat over n (n%32==0).
// dst[idx] holds src col (p&7)*4 + (p>>3) of the same 32-chunk.
// ===================================================================
extern "C" __global__ void __launch_bounds__(256)
conv_perm(const float* __restrict__ src, float* __restrict__ dst, int n)
{
    int idx = blockIdx.x * 256 + threadIdx.x;
    if (idx < n) {
        int p = idx & 31;
        int c = (idx & ~31) + (p & 7) * 4 + (p >> 3);
        dst[idx] = rtf32(src[c]);
    }
}

// ===================================================================
// GEMM: C[B, Nt] = A[B, K] @ W[Nt, K]^T + bias
// A, W pre-rounded tf32 + k-interleaved in global. CTA 128x256, warp 64x64.
// mode bit0: lrelu; bit1: output perm+round (staged through smem).
// ===================================================================
extern "C" __global__ void __launch_bounds__(256, 1)
gemm_tf32(const float* __restrict__ A, const float* __restrict__ W,
          const float* __restrict__ bias, float* __restrict__ C,
          int K, int Nt, int mode)
{
    extern __shared__ char smem[];
    const uint32_t sb = smem_u32(smem);
    const int tid = threadIdx.x;
    const int wid = tid >> 5;
    const int lid = tid & 31;
    const int g = lid >> 2;
    const int t = lid & 3;
    const int m0 = blockIdx.y * TM;
    const int n0 = blockIdx.x * TN;
    const int wm = (wid & 1) * 64;
    const int wn = (wid >> 1) * 64;

    // cp.async per-thread bases: seg = tid&7, base row = tid>>3 (rows advance by 32)
    const int brow = tid >> 3, seg = tid & 7;
    const float* srcA = A + (size_t)(m0 + brow) * K + seg * 4;
    const float* srcW = W + (size_t)(n0 + brow) * K + seg * 4;
    const uint32_t dA = sb + brow * 128 + ((seg ^ (brow & 7)) * 16);
    const uint32_t dW = dA + AT_BYTES;
    const size_t rstep = (size_t)32 * K;

    const int KC = K >> 5;

#pragma unroll
    for (int s = 0; s < NSTAGE; s++) {
        const float* pa = srcA + s * 32;
        const float* pw = srcW + s * 32;
        uint32_t off = s * STG_BYTES;
#pragma unroll
        for (int i = 0; i < 4; i++) cp16(dA + off + i * 4096, pa + i * rstep);
#pragma unroll
        for (int i = 0; i < 8; i++) cp16(dW + off + i * 4096, pw + i * rstep);
        asm volatile("cp.async.commit_group;" ::: "memory");
    }

    float acc[4][8][4];
#pragma unroll
    for (int mf = 0; mf < 4; mf++)
#pragma unroll
        for (int nf = 0; nf < 8; nf++)
#pragma unroll
            for (int j = 0; j < 4; j++) acc[mf][nf][j] = 0.f;

    for (int kc = 0; kc < KC; kc++) {
        int pend = KC - 1 - kc;
        if (pend >= 3)      asm volatile("cp.async.wait_group 3;" ::: "memory");
        else if (pend == 2) asm volatile("cp.async.wait_group 2;" ::: "memory");
        else if (pend == 1) asm volatile("cp.async.wait_group 1;" ::: "memory");
        else                asm volatile("cp.async.wait_group 0;" ::: "memory");
        __syncthreads();

        const int slot = kc & (NSTAGE - 1);
        const char* sA = smem + slot * STG_BYTES;
        const char* sW = sA + AT_BYTES;

#pragma unroll
        for (int w = 0; w < 2; w++) {
            const int segx = ((2 * t + w) ^ g) * 16;
            uint4 af[4][2];
#pragma unroll
            for (int mf = 0; mf < 4; mf++) {
                const char* base = sA + (wm + mf * 16 + g) * 128 + segx;
                af[mf][0] = *(const uint4*)(base);
                af[mf][1] = *(const uint4*)(base + 1024);   // +8 rows
            }
#pragma unroll
            for (int h = 0; h < 2; h++) {
                uint4 bf[4];
#pragma unroll
                for (int q = 0; q < 4; q++)
                    bf[q] = *(const uint4*)(sW + (wn + h * 32 + q * 8 + g) * 128 + segx);
#pragma unroll
                for (int kss = 0; kss < 2; kss++) {
#pragma unroll
                    for (int mf = 0; mf < 4; mf++) {
                        uint32_t a0 = kss ? af[mf][0].z : af[mf][0].x;
                        uint32_t a2 = kss ? af[mf][0].w : af[mf][0].y;
                        uint32_t a1 = kss ? af[mf][1].z : af[mf][1].x;
                        uint32_t a3 = kss ? af[mf][1].w : af[mf][1].y;
#pragma unroll
                        for (int q = 0; q < 4; q++) {
                            uint32_t b0 = kss ? bf[q].z : bf[q].x;
                            uint32_t b1 = kss ? bf[q].w : bf[q].y;
                            mma8(acc[mf][h * 4 + q], a0, a1, a2, a3, b0, b1);
                        }
                    }
                }
            }
        }
        __syncthreads();

        if (kc + NSTAGE < KC) {
            const float* pa = srcA + (kc + NSTAGE) * 32;
            const float* pw = srcW + (kc + NSTAGE) * 32;
            uint32_t off = slot * STG_BYTES;
#pragma unroll
            for (int i = 0; i < 4; i++) cp16(dA + off + i * 4096, pa + i * rstep);
#pragma unroll
            for (int i = 0; i < 8; i++) cp16(dW + off + i * 4096, pw + i * rstep);
            asm volatile("cp.async.commit_group;" ::: "memory");
        }
    }

    if (!(mode & 2)) {
        // plain epilogue: bias (+lrelu), coalesced float2 stores
#pragma unroll
        for (int nf = 0; nf < 8; nf++) {
            const int n = n0 + wn + nf * 8 + t * 2;
            const float2 bn = *(const float2*)(bias + n);
#pragma unroll
            for (int mf = 0; mf < 4; mf++) {
                const int m = m0 + wm + mf * 16 + g;
                float v0 = acc[mf][nf][0] + bn.x;
                float v1 = acc[mf][nf][1] + bn.y;
                float v2 = acc[mf][nf][2] + bn.x;
                float v3 = acc[mf][nf][3] + bn.y;
                if (mode & 1) {
                    v0 = v0 >= 0.f ? v0 : 0.2f * v0;
                    v1 = v1 >= 0.f ? v1 : 0.2f * v1;
                    v2 = v2 >= 0.f ? v2 : 0.2f * v2;
                    v3 = v3 >= 0.f ? v3 : 0.2f * v3;
                }
                *(float2*)(C + (size_t)m * Nt + n)       = make_float2(v0, v1);
                *(float2*)(C + (size_t)(m + 8) * Nt + n) = make_float2(v2, v3);
            }
        }
    } else {
        // staged epilogue: perm+round (+lrelu) through smem, float4 stores
        __syncthreads();
        float* se = (float*)smem;   // 128 x 256
#pragma unroll
        for (int nf = 0; nf < 8; nf++) {
            const int n = wn + nf * 8 + t * 2;
            const int nb = n & ~31;
            const int p0 = nb + perm32(n & 31);
            const int p1 = nb + perm32((n + 1) & 31);
            const float2 bn = *(const float2*)(bias + n0 + n);
#pragma unroll
            for (int mf = 0; mf < 4; mf++) {
                const int m = wm + mf * 16 + g;
                float v0 = acc[mf][nf][0] + bn.x;
                float v1 = acc[mf][nf][1] + bn.y;
                float v2 = acc[mf][nf][2] + bn.x;
                float v3 = acc[mf][nf][3] + bn.y;
                if (mode & 1) {
                    v0 = v0 >= 0.f ? v0 : 0.2f * v0;
                    v1 = v1 >= 0.f ? v1 : 0.2f * v1;
                    v2 = v2 >= 0.f ? v2 : 0.2f * v2;
                    v3 = v3 >= 0.f ? v3 : 0.2f * v3;
                }
                se[m * 256 + p0]       = rtf32(v0);
                se[m * 256 + p1]       = rtf32(v1);
                se[(m + 8) * 256 + p0] = rtf32(v2);
                se[(m + 8) * 256 + p1] = rtf32(v3);
            }
        }
        __syncthreads();
#pragma unroll
        for (int i = 0; i < 32; i++) {
            int lin = tid + i * 256;           // float4 index
            int row = lin >> 6, f4 = lin & 63;
            *(float4*)(C + (size_t)(m0 + row) * Nt + n0 + f4 * 4) =
                *(const float4*)(se + row * 256 + f4 * 4);
        }
    }
}

// ===================================================================
// LayerNorm + leaky relu; float4 loads; output perm+rounded (feeds GEMMs).
// One 256-thread block per row, H in {1024, 2048}.
// ===================================================================
extern "C" __global__ void __launch_bounds__(256)
ln_lrelu(const float* __restrict__ X, float* __restrict__ Y,
         const float* __restrict__ gw, const float* __restrict__ bw, int H)
{
    __shared__ float red[16];
    const int r = blockIdx.x;
    const int t = threadIdx.x;
    const float4* x4 = (const float4*)(X + (size_t)r * H);
    float* y = Y + (size_t)r * H;
    const int V = H >> 10;        // 1 or 2
    float4 v[2];
    float s = 0.f, s2 = 0.f;
#pragma unroll 2
    for (int i = 0; i < V; i++) {
        v[i] = x4[t + (i << 8)];
        s  += v[i].x + v[i].y + v[i].z + v[i].w;
        s2 += v[i].x * v[i].x + v[i].y * v[i].y + v[i].z * v[i].z + v[i].w * v[i].w;
    }
#pragma unroll
    for (int o = 16; o; o >>= 1) {
        s  += __shfl_xor_sync(~0u, s,  o);
        s2 += __shfl_xor_sync(~0u, s2, o);
    }
    if ((t & 31) == 0) { red[t >> 5] = s; red[8 + (t >> 5)] = s2; }
    __syncthreads();
    if (t < 32) {
        float a  = (t < 8) ? red[t]     : 0.f;
        float a2 = (t < 8) ? red[8 + t] : 0.f;
#pragma unroll
        for (int o = 4; o; o >>= 1) {
            a  += __shfl_xor_sync(~0u, a,  o);
            a2 += __shfl_xor_sync(~0u, a2, o);
        }
        if (t == 0) { red[0] = a; red[8] = a2; }
    }
    __syncthreads();
    const float inv = 1.f / (float)H;
    const float mu = red[0] * inv;
    const float var = red[8] * inv - mu * mu;
    const float rs = rsqrtf(var + 1e-5f);
#pragma unroll 2
    for (int i = 0; i < V; i++) {
        const int c0 = (t + (i << 8)) * 4;     // first col of this float4
        const float4 gg = ((const float4*)gw)[t + (i << 8)];
        const float4 bb = ((const float4*)bw)[t + (i << 8)];
        float o0 = (v[i].x - mu) * rs * gg.x + bb.x;
        float o1 = (v[i].y - mu) * rs * gg.y + bb.y;
        float o2 = (v[i].z - mu) * rs * gg.z + bb.z;
        float o3 = (v[i].w - mu) * rs * gg.w + bb.w;
        o0 = o0 >= 0.f ? o0 : 0.2f * o0;
        o1 = o1 >= 0.f ? o1 : 0.2f * o1;
        o2 = o2 >= 0.f ? o2 : 0.2f * o2;
        o3 = o3 >= 0.f ? o3 : 0.2f * o3;
        const int base = c0 & ~31;
        y[base + perm32((c0 + 0) & 31)] = rtf32(o0);
        y[base + perm32((c0 + 1) & 31)] = rtf32(o1);
        y[base + perm32((c0 + 2) & 31)] = rtf32(o2);
        y[base + perm32((c0 + 3) & 31)] = rtf32(o3);
    }
}

// ===================================================================
// Reparameterize + context-memory attention. One warp per row.
// Output perm+rounded (feeds decoder GEMM).
// ===================================================================
extern "C" __global__ void __launch_bounds__(256)
reparam_attn(const float* __restrict__ mu, const float* __restrict__ lv,
             const float* __restrict__ eps, const float* __restrict__ ctx,
             float* __restrict__ zout)
{
    __shared__ float sctx[32 * 257];
    __shared__ float sz[8][256];
    __shared__ float sat[8][32];
    const int t = threadIdx.x, w = t >> 5, l = t & 31;
    for (int i = t; i < 32 * 256; i += 256) {
        int m = i >> 8, k = i & 255;
        sctx[m * 257 + k] = ctx[i];
    }
    __syncthreads();
    const size_t r = (size_t)blockIdx.x * 8 + w;
    const float* murow = mu + r * 256;
    const float* lvrow = lv + r * 256;
    const float* erow  = eps + r * 256;
    float z[8];
#pragma unroll
    for (int i = 0; i < 8; i++) {
        int k = l + (i << 5);
        z[i] = murow[k] + erow[k] * expf(0.5f * lvrow[k]);
        sz[w][k] = z[i];
    }
    __syncwarp();
    float dot = 0.f;
    const float* cm = &sctx[l * 257];
#pragma unroll 8
    for (int k = 0; k < 256; k++) dot += sz[w][k] * cm[k];
    float mx = dot;
#pragma unroll
    for (int o = 16; o; o >>= 1) mx = fmaxf(mx, __shfl_xor_sync(~0u, mx, o));
    float e = expf(dot - mx);
    float sum = e;
#pragma unroll
    for (int o = 16; o; o >>= 1) sum += __shfl_xor_sync(~0u, sum, o);
    sat[w][l] = e / sum;
    __syncwarp();
    float* zo = zout + r * 256;
    const int pos = perm32(l);
#pragma unroll
    for (int i = 0; i < 8; i++) {
        int k = l + (i << 5);
        float acc = 0.f;
#pragma unroll
        for (int m = 0; m < 32; m++) acc += sat[w][m] * sctx[m * 257 + k];
        zo[(i << 5) + pos] = rtf32(z[i] + 0.1f * acc);
    }
}

// ===================================================================
extern "C" void kernel_launch(void* const* d_in, const int* in_sizes, int n_in,
                              void* d_out, int out_size)
{
    (void)in_sizes; (void)n_in; (void)out_size;
    const float* x      = (const float*)d_in[0];
    const float* eps    = (const float*)d_in[1];
    const float* enc_w1 = (const float*)d_in[2];
    const float* enc_b1 = (const float*)d_in[3];
    const float* ln1_g  = (const float*)d_in[4];
    const float* ln1_b  = (const float*)d_in[5];
    const float* enc_w2 = (const float*)d_in[6];
    const float* enc_b2 = (const float*)d_in[7];
    const float* ln2_g  = (const float*)d_in[8];
    const float* ln2_b  = (const float*)d_in[9];
    const float* mu_w   = (const float*)d_in[10];
    const float* mu_b   = (const float*)d_in[11];
    const float* lv_w   = (const float*)d_in[12];
    const float* lv_b   = (const float*)d_in[13];
    const float* di_w   = (const float*)d_in[14];
    const float* di_b   = (const float*)d_in[15];
    const float* dec_w1 = (const float*)d_in[16];
    const float* dec_b1 = (const float*)d_in[17];
    const float* dln1_g = (const float*)d_in[18];
    const float* dln1_b = (const float*)d_in[19];
    const float* dec_w2 = (const float*)d_in[20];
    const float* dec_b2 = (const float*)d_in[21];
    const float* dln2_g = (const float*)d_in[22];
    const float* dln2_b = (const float*)d_in[23];
    const float* dec_w3 = (const float*)d_in[24];
    const float* dec_b3 = (const float*)d_in[25];
    const float* ctx    = (const float*)d_in[26];

    float* out    = (float*)d_out;
    float* out_mu = out + (size_t)B_ * D_;
    float* out_lv = out_mu + (size_t)B_ * L_;

    float* buf0 = nullptr; float* buf1 = nullptr; float* cvt = nullptr;
    cudaGetSymbolAddress((void**)&buf0, g_act0);
    cudaGetSymbolAddress((void**)&buf1, g_act1);
    cudaGetSymbolAddress((void**)&cvt,  g_cvt);

    cudaFuncSetAttribute(gemm_tf32, cudaFuncAttributeMaxDynamicSharedMemorySize, SM_TOTAL);

    // --- conversion passes: round to tf32 + k-interleave ---
    struct { const float* s; size_t off; int n; } cv[9] = {
        { x,      OFF_X,   B_ * D_      },
        { enc_w1, OFF_EW1, H_ * D_      },
        { enc_w2, OFF_EW2, H_ * H_      },
        { mu_w,   OFF_MUW, L_ * H_      },
        { lv_w,   OFF_LVW, L_ * H_      },
        { di_w,   OFF_DIW, H_ * L_      },
        { dec_w1, OFF_DW1, H_ * H_      },
        { dec_w2, OFF_DW2, 2 * H_ * H_  },
        { dec_w3, OFF_DW3, D_ * 2 * H_  },
    };
    for (int i = 0; i < 9; i++)
        conv_perm<<<(cv[i].n + 255) / 256, 256>>>(cv[i].s, cvt + cv[i].off, cv[i].n);

    const dim3 blk(256);
    const dim3 gH(H_ / TN, B_ / TM);        // (4, 256)
    const dim3 gL(L_ / TN, B_ / TM);        // (1, 256)
    const dim3 g2H(2 * H_ / TN, B_ / TM);   // (8, 256)
    const dim3 gD(D_ / TN, B_ / TM);        // (3, 256)

    // encoder
    gemm_tf32<<<gH, blk, SM_TOTAL>>>(cvt + OFF_X, cvt + OFF_EW1, enc_b1, buf0, D_, H_, 0);
    ln_lrelu<<<B_, 256>>>(buf0, buf1, ln1_g, ln1_b, H_);
    gemm_tf32<<<gH, blk, SM_TOTAL>>>(buf1, cvt + OFF_EW2, enc_b2, buf0, H_, H_, 0);
    ln_lrelu<<<B_, 256>>>(buf0, buf1, ln2_g, ln2_b, H_);
    gemm_tf32<<<gL, blk, SM_TOTAL>>>(buf1, cvt + OFF_MUW, mu_b, out_mu, H_, L_, 0);
    gemm_tf32<<<gL, blk, SM_TOTAL>>>(buf1, cvt + OFF_LVW, lv_b, out_lv, H_, L_, 0);
    // reparameterize + context attention
    reparam_attn<<<B_ / 8, 256>>>(out_mu, out_lv, eps, ctx, buf0);
    // decoder
    gemm_tf32<<<gH, blk, SM_TOTAL>>>(buf0, cvt + OFF_DIW, di_b, buf1, L_, H_, 3);
    gemm_tf32<<<gH, blk, SM_TOTAL>>>(buf1, cvt + OFF_DW1, dec_b1, buf0, H_, H_, 0);
    ln_lrelu<<<B_, 256>>>(buf0, buf1, dln1_g, dln1_b, H_);
    gemm_tf32<<<g2H, blk, SM_TOTAL>>>(buf1, cvt + OFF_DW2, dec_b2, buf0, H_, 2 * H_, 0);
    ln_lrelu<<<B_, 256>>>(buf0, buf1, dln2_g, dln2_b, 2 * H_);
    gemm_tf32<<<gD, blk, SM_TOTAL>>>(buf1, cvt + OFF_DW3, dec_b3, out, 2 * H_, D_, 0);
}

// round 8
// speedup vs baseline: 1.7332x; 1.5031x over previous
#include <cuda_runtime.h>
#include <cuda_fp16.h>
#include <cstdint>

#define B_ 32768
#define D_ 768
#define H_ 1024
#define L_ 256

// ---------------- GEMM tiling ----------------
#define TM 128
#define TN 256
#define AT_BYTES (128 * 128)              // A tile: 128 rows x 128B (64 halfs)
#define WT_BYTES (256 * 128)              // W tile
#define STG_BYTES (AT_BYTES + WT_BYTES)   // 49152
#define NSTAGE 4
#define SM_TOTAL (NSTAGE * STG_BYTES)     // 196608

// ---------------- scratch ----------------
static __device__ float  g_f32[(size_t)B_ * 2048];          // pre-LN activations
static __device__ __half g_h0[(size_t)B_ * 2048];           // fp16 perm'd activations
static __device__ __half g_h1[(size_t)B_ * 256];            // z_enh
static __device__ __half g_cvt[32505856];                   // x + weights, fp16 perm'd

// offsets into g_cvt (halfs)
#define OFF_X    0
#define OFF_EW1  25165824
#define OFF_EW2  25952256
#define OFF_MUW  27000832
#define OFF_LVW  27262976
#define OFF_DIW  27525120
#define OFF_DW1  27787264
#define OFF_DW2  28835840
#define OFF_DW3  30932992

// ---------------- helpers ----------------
__device__ __forceinline__ uint32_t smem_u32(const void* p) {
    uint32_t a;
    asm("{ .reg .u64 t; cvta.to.shared.u64 t, %1; cvt.u32.u64 %0, t; }" : "=r"(a) : "l"(p));
    return a;
}
__device__ __forceinline__ void cp16(uint32_t sa, const void* g) {
    asm volatile("cp.async.cg.shared.global [%0], [%1], 16;" :: "r"(sa), "l"(g));
}
__device__ __forceinline__ void mma16(float* c, uint32_t a0, uint32_t a1, uint32_t a2, uint32_t a3,
                                      uint32_t b0, uint32_t b1) {
    asm volatile("mma.sync.aligned.m16n8k16.row.col.f32.f16.f16.f32 "
                 "{%0,%1,%2,%3}, {%4,%5,%6,%7}, {%8,%9}, {%0,%1,%2,%3};"
                 : "+f"(c[0]), "+f"(c[1]), "+f"(c[2]), "+f"(c[3])
                 : "r"(a0), "r"(a1), "r"(a2), "r"(a3), "r"(b0), "r"(b1));
}
// position of original col c (0..63) inside a 64-col chunk, fragment-interleaved:
// kstep=c>>4, r=c&15 = 2t+j+8h ->  p = (t + (kstep>>1)*4)*8 + (kstep&1)*4 + h*2 + j
__device__ __forceinline__ int perm64(int c) {
    int kstep = (c >> 4) & 3, r = c & 15;
    return ((r >> 1) & 3) * 8 + (kstep >> 1) * 32 + (kstep & 1) * 4 + (r >> 3) * 2 + (c & 1);
}

// ===================================================================
// conv_h: fp32 -> fp16 with 64-col fragment interleave. n halfs, n%64==0.
// One half2 per thread.
// ===================================================================
extern "C" __global__ void __launch_bounds__(256)
conv_h(const float* __restrict__ src, __half* __restrict__ dst, int n2)
{
    int idx = blockIdx.x * 256 + threadIdx.x;
    if (idx < n2) {
        int p = idx * 2;
        int t = (p >> 3) & 3, ks2 = (p & 63) >> 5, k1 = (p >> 2) & 1, h = (p >> 1) & 1;
        int c = (p & ~63) + (ks2 * 2 + k1) * 16 + 2 * t + 8 * h;
        ((__half2*)dst)[idx] = __floats2half2_rn(src[c], src[c + 1]);
    }
}

// ===================================================================
// GEMM: C[B, Nt] = A[B, K] @ W[Nt, K]^T + bias
// A, W fp16 fragment-interleaved. CTA 128x256, warp 64x64, 4-stage cp.async.
// mode bit0: lrelu; bit1: fp16 perm'd output (staged via smem), else fp32.
// ===================================================================
extern "C" __global__ void __launch_bounds__(256, 1)
gemm_h(const __half* __restrict__ A, const __half* __restrict__ W,
       const float* __restrict__ bias, void* __restrict__ Cv,
       int K, int Nt, int mode)
{
    extern __shared__ char smem[];
    const uint32_t sb = smem_u32(smem);
    const int tid = threadIdx.x;
    const int wid = tid >> 5;
    const int lid = tid & 31;
    const int g = lid >> 2;
    const int t = lid & 3;
    const int m0 = blockIdx.y * TM;
    const int n0 = blockIdx.x * TN;
    const int wm = (wid & 1) * 64;
    const int wn = (wid >> 1) * 64;

    // cp.async mapping: seg = tid&7 (16B), base row = tid>>3, rows advance by 32
    const int brow = tid >> 3, seg = tid & 7;
    const __half* srcA = A + (size_t)(m0 + brow) * K + seg * 8;
    const __half* srcW = W + (size_t)(n0 + brow) * K + seg * 8;
    const uint32_t dA = sb + brow * 128 + ((seg ^ (brow & 7)) * 16);
    const uint32_t dW = dA + AT_BYTES;
    const size_t rstep = (size_t)32 * K;

    const int KC = K >> 6;       // 64-half K-chunks

#pragma unroll
    for (int s = 0; s < NSTAGE; s++) {
        const __half* pa = srcA + s * 64;
        const __half* pw = srcW + s * 64;
        uint32_t off = s * STG_BYTES;
#pragma unroll
        for (int i = 0; i < 4; i++) cp16(dA + off + i * 4096, pa + i * rstep);
#pragma unroll
        for (int i = 0; i < 8; i++) cp16(dW + off + i * 4096, pw + i * rstep);
        asm volatile("cp.async.commit_group;" ::: "memory");
    }

    float acc[4][8][4];
#pragma unroll
    for (int mf = 0; mf < 4; mf++)
#pragma unroll
        for (int nf = 0; nf < 8; nf++)
#pragma unroll
            for (int j = 0; j < 4; j++) acc[mf][nf][j] = 0.f;

    for (int kc = 0; kc < KC; kc++) {
        int pend = KC - 1 - kc;
        if (pend >= 3)      asm volatile("cp.async.wait_group 3;" ::: "memory");
        else if (pend == 2) asm volatile("cp.async.wait_group 2;" ::: "memory");
        else if (pend == 1) asm volatile("cp.async.wait_group 1;" ::: "memory");
        else                asm volatile("cp.async.wait_group 0;" ::: "memory");
        __syncthreads();

        const int slot = kc & (NSTAGE - 1);
        const char* sA = smem + slot * STG_BYTES;
        const char* sW = sA + AT_BYTES;
        const int sgx = (g & 7);

#pragma unroll
        for (int ks2 = 0; ks2 < 2; ks2++) {
            const int segx = ((t + 4 * ks2) ^ sgx) * 16;
            uint4 af[4][2];
#pragma unroll
            for (int mf = 0; mf < 4; mf++) {
                const char* base = sA + (wm + mf * 16 + g) * 128 + segx;
                af[mf][0] = *(const uint4*)(base);
                af[mf][1] = *(const uint4*)(base + 1024);    // +8 rows
            }
#pragma unroll
            for (int nf = 0; nf < 8; nf++) {
                const uint4 bf = *(const uint4*)(sW + (wn + nf * 8 + g) * 128 + segx);
#pragma unroll
                for (int mf = 0; mf < 4; mf++) {
                    mma16(acc[mf][nf], af[mf][0].x, af[mf][1].x, af[mf][0].y, af[mf][1].y,
                          bf.x, bf.y);
                    mma16(acc[mf][nf], af[mf][0].z, af[mf][1].z, af[mf][0].w, af[mf][1].w,
                          bf.z, bf.w);
                }
            }
        }
        __syncthreads();

        if (kc + NSTAGE < KC) {
            const __half* pa = srcA + (kc + NSTAGE) * 64;
            const __half* pw = srcW + (kc + NSTAGE) * 64;
            uint32_t off = slot * STG_BYTES;
#pragma unroll
            for (int i = 0; i < 4; i++) cp16(dA + off + i * 4096, pa + i * rstep);
#pragma unroll
            for (int i = 0; i < 8; i++) cp16(dW + off + i * 4096, pw + i * rstep);
            asm volatile("cp.async.commit_group;" ::: "memory");
        }
    }

    if (!(mode & 2)) {
        float* C = (float*)Cv;
#pragma unroll
        for (int nf = 0; nf < 8; nf++) {
            const int n = n0 + wn + nf * 8 + t * 2;
            const float2 bn = *(const float2*)(bias + n);
#pragma unroll
            for (int mf = 0; mf < 4; mf++) {
                const int m = m0 + wm + mf * 16 + g;
                float v0 = acc[mf][nf][0] + bn.x;
                float v1 = acc[mf][nf][1] + bn.y;
                float v2 = acc[mf][nf][2] + bn.x;
                float v3 = acc[mf][nf][3] + bn.y;
                if (mode & 1) {
                    v0 = v0 >= 0.f ? v0 : 0.2f * v0;
                    v1 = v1 >= 0.f ? v1 : 0.2f * v1;
                    v2 = v2 >= 0.f ? v2 : 0.2f * v2;
                    v3 = v3 >= 0.f ? v3 : 0.2f * v3;
                }
                *(float2*)(C + (size_t)m * Nt + n)       = make_float2(v0, v1);
                *(float2*)(C + (size_t)(m + 8) * Nt + n) = make_float2(v2, v3);
            }
        }
    } else {
        // fp16 perm'd output staged through smem
        __half* C = (__half*)Cv;
        __syncthreads();
        __half2* se = (__half2*)smem;           // 128 x 128 half2
#pragma unroll
        for (int nf = 0; nf < 8; nf++) {
            const int n = wn + nf * 8 + t * 2;              // local, even
            const int p = (n & ~63) + perm64(n & 63);       // even position
            const float2 bn = *(const float2*)(bias + n0 + n);
#pragma unroll
            for (int mf = 0; mf < 4; mf++) {
                const int m = wm + mf * 16 + g;
                float v0 = acc[mf][nf][0] + bn.x;
                float v1 = acc[mf][nf][1] + bn.y;
                float v2 = acc[mf][nf][2] + bn.x;
                float v3 = acc[mf][nf][3] + bn.y;
                if (mode & 1) {
                    v0 = v0 >= 0.f ? v0 : 0.2f * v0;
                    v1 = v1 >= 0.f ? v1 : 0.2f * v1;
                    v2 = v2 >= 0.f ? v2 : 0.2f * v2;
                    v3 = v3 >= 0.f ? v3 : 0.2f * v3;
                }
                se[m * 128 + (p >> 1)]       = __floats2half2_rn(v0, v1);
                se[(m + 8) * 128 + (p >> 1)] = __floats2half2_rn(v2, v3);
            }
        }
        __syncthreads();
#pragma unroll
        for (int i = 0; i < 16; i++) {
            int lin = tid + i * 256;             // uint4 index (8 halfs)
            int row = lin >> 5, f8 = lin & 31;
            *(uint4*)(C + (size_t)(m0 + row) * Nt + n0 + f8 * 8) =
                *(const uint4*)((const char*)smem + row * 512 + f8 * 16);
        }
    }
}

// ===================================================================
// LayerNorm + leaky relu; fp32 in, fp16 perm'd out. Block=256/row.
// ===================================================================
extern "C" __global__ void __launch_bounds__(256)
ln_lrelu(const float* __restrict__ X, __half* __restrict__ Y,
         const float* __restrict__ gw, const float* __restrict__ bw, int H)
{
    __shared__ float red[16];
    const int r = blockIdx.x;
    const int t = threadIdx.x;
    const float4* x4 = (const float4*)(X + (size_t)r * H);
    __half2* y2 = (__half2*)(Y + (size_t)r * H);
    const int V = H >> 10;        // 1 or 2
    float4 v[2];
    float s = 0.f, s2 = 0.f;
#pragma unroll 2
    for (int i = 0; i < V; i++) {
        v[i] = x4[t + (i << 8)];
        s  += v[i].x + v[i].y + v[i].z + v[i].w;
        s2 += v[i].x * v[i].x + v[i].y * v[i].y + v[i].z * v[i].z + v[i].w * v[i].w;
    }
#pragma unroll
    for (int o = 16; o; o >>= 1) {
        s  += __shfl_xor_sync(~0u, s,  o);
        s2 += __shfl_xor_sync(~0u, s2, o);
    }
    if ((t & 31) == 0) { red[t >> 5] = s; red[8 + (t >> 5)] = s2; }
    __syncthreads();
    if (t < 32) {
        float a  = (t < 8) ? red[t]     : 0.f;
        float a2 = (t < 8) ? red[8 + t] : 0.f;
#pragma unroll
        for (int o = 4; o; o >>= 1) {
            a  += __shfl_xor_sync(~0u, a,  o);
            a2 += __shfl_xor_sync(~0u, a2, o);
        }
        if (t == 0) { red[0] = a; red[8] = a2; }
    }
    __syncthreads();
    const float inv = 1.f / (float)H;
    const float mu = red[0] * inv;
    const float var = red[8] * inv - mu * mu;
    const float rs = rsqrtf(var + 1e-5f);
#pragma unroll 2
    for (int i = 0; i < V; i++) {
        const int c0 = (t + (i << 8)) * 4;
        const float4 gg = ((const float4*)gw)[t + (i << 8)];
        const float4 bb = ((const float4*)bw)[t + (i << 8)];
        float o0 = (v[i].x - mu) * rs * gg.x + bb.x;
        float o1 = (v[i].y - mu) * rs * gg.y + bb.y;
        float o2 = (v[i].z - mu) * rs * gg.z + bb.z;
        float o3 = (v[i].w - mu) * rs * gg.w + bb.w;
        o0 = o0 >= 0.f ? o0 : 0.2f * o0;
        o1 = o1 >= 0.f ? o1 : 0.2f * o1;
        o2 = o2 >= 0.f ? o2 : 0.2f * o2;
        o3 = o3 >= 0.f ? o3 : 0.2f * o3;
        const int base = c0 & ~63;
        const int pA = base + perm64(c0 & 63);
        const int pB = base + perm64((c0 + 2) & 63);
        y2[pA >> 1] = __floats2half2_rn(o0, o1);
        y2[pB >> 1] = __floats2half2_rn(o2, o3);
    }
}

// ===================================================================
// Reparameterize + context-memory attention. One warp per row.
// fp32 mu/lv/eps in; fp16 perm'd z_enh out.
// ===================================================================
extern "C" __global__ void __launch_bounds__(256)
reparam_attn(const float* __restrict__ mu, const float* __restrict__ lv,
             const float* __restrict__ eps, const float* __restrict__ ctx,
             __half* __restrict__ zout)
{
    __shared__ float sctx[32 * 257];
    __shared__ float sz[8][256];
    __shared__ float sat[8][32];
    const int t = threadIdx.x, w = t >> 5, l = t & 31;
    for (int i = t; i < 32 * 256; i += 256) {
        int m = i >> 8, k = i & 255;
        sctx[m * 257 + k] = ctx[i];
    }
    __syncthreads();
    const size_t r = (size_t)blockIdx.x * 8 + w;
    const float* murow = mu + r * 256;
    const float* lvrow = lv + r * 256;
    const float* erow  = eps + r * 256;
    float z[8];
#pragma unroll
    for (int j = 0; j < 4; j++) {
        int k = j * 64 + 2 * l;
        z[j * 2]     = murow[k]     + erow[k]     * expf(0.5f * lvrow[k]);
        z[j * 2 + 1] = murow[k + 1] + erow[k + 1] * expf(0.5f * lvrow[k + 1]);
        sz[w][k] = z[j * 2];
        sz[w][k + 1] = z[j * 2 + 1];
    }
    __syncwarp();
    float dot = 0.f;
    const float* cm = &sctx[l * 257];
#pragma unroll 8
    for (int k = 0; k < 256; k++) dot += sz[w][k] * cm[k];
    float mx = dot;
#pragma unroll
    for (int o = 16; o; o >>= 1) mx = fmaxf(mx, __shfl_xor_sync(~0u, mx, o));
    float e = expf(dot - mx);
    float sum = e;
#pragma unroll
    for (int o = 16; o; o >>= 1) sum += __shfl_xor_sync(~0u, sum, o);
    sat[w][l] = e / sum;
    __syncwarp();
    __half2* zo = (__half2*)(zout + r * 256);
#pragma unroll
    for (int j = 0; j < 4; j++) {
        int k = j * 64 + 2 * l;
        float a0 = 0.f, a1 = 0.f;
#pragma unroll
        for (int m = 0; m < 32; m++) {
            a0 += sat[w][m] * sctx[m * 257 + k];
            a1 += sat[w][m] * sctx[m * 257 + k + 1];
        }
        int p = j * 64 + perm64(k & 63);
        zo[p >> 1] = __floats2half2_rn(z[j * 2] + 0.1f * a0, z[j * 2 + 1] + 0.1f * a1);
    }
}

// ===================================================================
extern "C" void kernel_launch(void* const* d_in, const int* in_sizes, int n_in,
                              void* d_out, int out_size)
{
    (void)in_sizes; (void)n_in; (void)out_size;
    const float* x      = (const float*)d_in[0];
    const float* eps    = (const float*)d_in[1];
    const float* enc_w1 = (const float*)d_in[2];
    const float* enc_b1 = (const float*)d_in[3];
    const float* ln1_g  = (const float*)d_in[4];
    const float* ln1_b  = (const float*)d_in[5];
    const float* enc_w2 = (const float*)d_in[6];
    const float* enc_b2 = (const float*)d_in[7];
    const float* ln2_g  = (const float*)d_in[8];
    const float* ln2_b  = (const float*)d_in[9];
    const float* mu_w   = (const float*)d_in[10];
    const float* mu_b   = (const float*)d_in[11];
    const float* lv_w   = (const float*)d_in[12];
    const float* lv_b   = (const float*)d_in[13];
    const float* di_w   = (const float*)d_in[14];
    const float* di_b   = (const float*)d_in[15];
    const float* dec_w1 = (const float*)d_in[16];
    const float* dec_b1 = (const float*)d_in[17];
    const float* dln1_g = (const float*)d_in[18];
    const float* dln1_b = (const float*)d_in[19];
    const float* dec_w2 = (const float*)d_in[20];
    const float* dec_b2 = (const float*)d_in[21];
    const float* dln2_g = (const float*)d_in[22];
    const float* dln2_b = (const float*)d_in[23];
    const float* dec_w3 = (const float*)d_in[24];
    const float* dec_b3 = (const float*)d_in[25];
    const float* ctx    = (const float*)d_in[26];

    float* out    = (float*)d_out;
    float* out_mu = out + (size_t)B_ * D_;
    float* out_lv = out_mu + (size_t)B_ * L_;

    float* f32buf = nullptr; __half* h0 = nullptr; __half* h1 = nullptr; __half* cvt = nullptr;
    cudaGetSymbolAddress((void**)&f32buf, g_f32);
    cudaGetSymbolAddress((void**)&h0, g_h0);
    cudaGetSymbolAddress((void**)&h1, g_h1);
    cudaGetSymbolAddress((void**)&cvt, g_cvt);

    cudaFuncSetAttribute(gemm_h, cudaFuncAttributeMaxDynamicSharedMemorySize, SM_TOTAL);

    // --- conversion: fp32 -> fp16 + fragment interleave ---
    struct { const float* s; size_t off; int n; } cv[9] = {
        { x,      OFF_X,   B_ * D_      },
        { enc_w1, OFF_EW1, H_ * D_      },
        { enc_w2, OFF_EW2, H_ * H_      },
        { mu_w,   OFF_MUW, L_ * H_      },
        { lv_w,   OFF_LVW, L_ * H_      },
        { di_w,   OFF_DIW, H_ * L_      },
        { dec_w1, OFF_DW1, H_ * H_      },
        { dec_w2, OFF_DW2, 2 * H_ * H_  },
        { dec_w3, OFF_DW3, D_ * 2 * H_  },
    };
    for (int i = 0; i < 9; i++) {
        int n2 = cv[i].n / 2;
        conv_h<<<(n2 + 255) / 256, 256>>>(cv[i].s, cvt + cv[i].off, n2);
    }

    const dim3 blk(256);
    const dim3 gH(H_ / TN, B_ / TM);        // (4, 256)
    const dim3 gL(L_ / TN, B_ / TM);        // (1, 256)
    const dim3 g2H(2 * H_ / TN, B_ / TM);   // (8, 256)
    const dim3 gD(D_ / TN, B_ / TM);        // (3, 256)

    // encoder
    gemm_h<<<gH, blk, SM_TOTAL>>>(cvt + OFF_X, cvt + OFF_EW1, enc_b1, f32buf, D_, H_, 0);
    ln_lrelu<<<B_, 256>>>(f32buf, h0, ln1_g, ln1_b, H_);
    gemm_h<<<gH, blk, SM_TOTAL>>>(h0, cvt + OFF_EW2, enc_b2, f32buf, H_, H_, 0);
    ln_lrelu<<<B_, 256>>>(f32buf, h0, ln2_g, ln2_b, H_);
    gemm_h<<<gL, blk, SM_TOTAL>>>(h0, cvt + OFF_MUW, mu_b, out_mu, H_, L_, 0);
    gemm_h<<<gL, blk, SM_TOTAL>>>(h0, cvt + OFF_LVW, lv_b, out_lv, H_, L_, 0);
    // reparameterize + context attention
    reparam_attn<<<B_ / 8, 256>>>(out_mu, out_lv, eps, ctx, h1);
    // decoder
    gemm_h<<<gH, blk, SM_TOTAL>>>(h1, cvt + OFF_DIW, di_b, h0, L_, H_, 3);
    gemm_h<<<gH, blk, SM_TOTAL>>>(h0, cvt + OFF_DW1, dec_b1, f32buf, H_, H_, 0);
    ln_lrelu<<<B_, 256>>>(f32buf, h0, dln1_g, dln1_b, H_);
    gemm_h<<<g2H, blk, SM_TOTAL>>>(h0, cvt + OFF_DW2, dec_b2, f32buf, H_, 2 * H_, 0);
    ln_lrelu<<<B_, 256>>>(f32buf, h0, dln2_g, dln2_b, 2 * H_);
    gemm_h<<<gD, blk, SM_TOTAL>>>(h0, cvt + OFF_DW3, dec_b3, out, 2 * H_, D_, 0);
}

// round 9
// speedup vs baseline: 1.7508x; 1.0102x over previous
#include <cuda_runtime.h>
#include <cuda_fp16.h>
#include <cstdint>

#define B_ 32768
#define D_ 768
#define H_ 1024
#define L_ 256

// ---------------- GEMM tiling ----------------
#define TM 128
#define TN 256
#define AT_BYTES (128 * 128)              // A tile: 128 rows x 128B (64 halfs)
#define WT_BYTES (256 * 128)              // W tile
#define STG_BYTES (AT_BYTES + WT_BYTES)   // 49152
#define NSTAGE 4
#define SM_TOTAL (NSTAGE * STG_BYTES)     // 196608

// ---------------- scratch ----------------
static __device__ float  g_f32[(size_t)B_ * 2048];   // aliased as half buffer A
static __device__ __half g_h0[(size_t)B_ * 2048];    // half buffer B
static __device__ __half g_h1[(size_t)B_ * 256];     // z_enh
static __device__ __half g_cvt[32505856];            // x + weights, fp16 perm'd
static __device__ float  g_lnp[10240];               // perm'd LN gamma/beta

// offsets into g_cvt (halfs)
#define OFF_X    0
#define OFF_EW1  25165824
#define OFF_EW2  25952256
#define OFF_MUW  27000832
#define OFF_LVW  27262976
#define OFF_DIW  27525120
#define OFF_DW1  27787264
#define OFF_DW2  28835840
#define OFF_DW3  30932992

// ---------------- helpers ----------------
__device__ __forceinline__ uint32_t smem_u32(const void* p) {
    uint32_t a;
    asm("{ .reg .u64 t; cvta.to.shared.u64 t, %1; cvt.u32.u64 %0, t; }" : "=r"(a) : "l"(p));
    return a;
}
__device__ __forceinline__ void cp16(uint32_t sa, const void* g) {
    asm volatile("cp.async.cg.shared.global [%0], [%1], 16;" :: "r"(sa), "l"(g));
}
__device__ __forceinline__ void mma16(float* c, uint32_t a0, uint32_t a1, uint32_t a2, uint32_t a3,
                                      uint32_t b0, uint32_t b1) {
    asm volatile("mma.sync.aligned.m16n8k16.row.col.f32.f16.f16.f32 "
                 "{%0,%1,%2,%3}, {%4,%5,%6,%7}, {%8,%9}, {%0,%1,%2,%3};"
                 : "+f"(c[0]), "+f"(c[1]), "+f"(c[2]), "+f"(c[3])
                 : "r"(a0), "r"(a1), "r"(a2), "r"(a3), "r"(b0), "r"(b1));
}
// position of original col c (0..63) inside a 64-col chunk, fragment-interleaved
__device__ __forceinline__ int perm64(int c) {
    int kstep = (c >> 4) & 3, r = c & 15;
    return ((r >> 1) & 3) * 8 + (kstep >> 1) * 32 + (kstep & 1) * 4 + (r >> 3) * 2 + (c & 1);
}
// inverse: source col for perm'd position p (within 64-chunk, p even handled pairwise)
__device__ __forceinline__ int iperm_base(int p) {
    int t = (p >> 3) & 3, ks2 = (p & 63) >> 5, k1 = (p >> 2) & 1, h = (p >> 1) & 1;
    return (p & ~63) + (ks2 * 2 + k1) * 16 + 2 * t + 8 * h;
}

// ===================================================================
// conv_h: fp32 -> fp16 + fragment interleave (for x). One half2/thread.
// ===================================================================
extern "C" __global__ void __launch_bounds__(256)
conv_h(const float* __restrict__ src, __half* __restrict__ dst, int n2)
{
    int idx = blockIdx.x * 256 + threadIdx.x;
    if (idx < n2) {
        int c = iperm_base(idx * 2);
        ((__half2*)dst)[idx] = __floats2half2_rn(src[c], src[c + 1]);
    }
}

// ===================================================================
// conv_w: all 8 weight matrices in one launch (region dispatch by block).
// blocks: 1536,2048,512,512,512,2048,4096,3072 (total 14336)
// ===================================================================
extern "C" __global__ void __launch_bounds__(256)
conv_w(const float* s0, const float* s1, const float* s2, const float* s3,
       const float* s4, const float* s5, const float* s6, const float* s7,
       __half* __restrict__ cvt)
{
    int b = blockIdx.x;
    const float* src; size_t doff; int lb;
    if      (b < 1536)  { src = s0; doff = OFF_EW1; lb = b; }
    else if (b < 3584)  { src = s1; doff = OFF_EW2; lb = b - 1536; }
    else if (b < 4096)  { src = s2; doff = OFF_MUW; lb = b - 3584; }
    else if (b < 4608)  { src = s3; doff = OFF_LVW; lb = b - 4096; }
    else if (b < 5120)  { src = s4; doff = OFF_DIW; lb = b - 4608; }
    else if (b < 7168)  { src = s5; doff = OFF_DW1; lb = b - 5120; }
    else if (b < 11264) { src = s6; doff = OFF_DW2; lb = b - 7168; }
    else                { src = s7; doff = OFF_DW3; lb = b - 11264; }
    int idx = lb * 256 + threadIdx.x;
    int c = iperm_base(idx * 2);
    ((__half2*)(cvt + doff))[idx] = __floats2half2_rn(src[c], src[c + 1]);
}

// ===================================================================
// conv_lnp: permute LN gamma/beta (fp32) into g_lnp.
// blocks: ln1g[0,4) ln1b[4,8) ln2g[8,12) ln2b[12,16) d1g[16,20) d1b[20,24)
//         d2g[24,32) d2b[32,40)
// ===================================================================
extern "C" __global__ void __launch_bounds__(256)
conv_lnp(const float* s0, const float* s1, const float* s2, const float* s3,
         const float* s4, const float* s5, const float* s6, const float* s7,
         float* __restrict__ dst)
{
    int b = blockIdx.x;
    const float* src; int doff, lb;
    if      (b < 4)  { src = s0; doff = 0;    lb = b; }
    else if (b < 8)  { src = s1; doff = 1024; lb = b - 4; }
    else if (b < 12) { src = s2; doff = 2048; lb = b - 8; }
    else if (b < 16) { src = s3; doff = 3072; lb = b - 12; }
    else if (b < 20) { src = s4; doff = 4096; lb = b - 16; }
    else if (b < 24) { src = s5; doff = 5120; lb = b - 20; }
    else if (b < 32) { src = s6; doff = 6144; lb = b - 24; }
    else             { src = s7; doff = 8192; lb = b - 32; }
    int p = lb * 256 + threadIdx.x;
    int c = iperm_base(p) + (p & 1);
    dst[doff + p] = src[c];
}

// ===================================================================
// GEMM: C[B, Nt] = A[B, K] @ W[Nt, K]^T + bias
// A, W fp16 fragment-interleaved. CTA 128x256, warp 64x64.
// 4 slots, 3-deep cp.async pipeline, single sync per chunk.
// mode bit0: lrelu; bit1: fp16 perm'd output (staged via smem), else fp32.
// ===================================================================
extern "C" __global__ void __launch_bounds__(256, 1)
gemm_h(const __half* __restrict__ A, const __half* __restrict__ W,
       const float* __restrict__ bias, void* __restrict__ Cv,
       int K, int Nt, int mode)
{
    extern __shared__ char smem[];
    const uint32_t sb = smem_u32(smem);
    const int tid = threadIdx.x;
    const int wid = tid >> 5;
    const int lid = tid & 31;
    const int g = lid >> 2;
    const int t = lid & 3;
    const int m0 = blockIdx.y * TM;
    const int n0 = blockIdx.x * TN;
    const int wm = (wid & 1) * 64;
    const int wn = (wid >> 1) * 64;

    const int brow = tid >> 3, seg = tid & 7;
    const __half* srcA = A + (size_t)(m0 + brow) * K + seg * 8;
    const __half* srcW = W + (size_t)(n0 + brow) * K + seg * 8;
    const uint32_t dA = sb + brow * 128 + ((seg ^ (brow & 7)) * 16);
    const uint32_t dW = dA + AT_BYTES;
    const size_t rstep = (size_t)32 * K;

    const int KC = K >> 6;

    // prologue: fill 3 of 4 slots
#pragma unroll
    for (int s = 0; s < NSTAGE - 1; s++) {
        const __half* pa = srcA + s * 64;
        const __half* pw = srcW + s * 64;
        uint32_t off = s * STG_BYTES;
#pragma unroll
        for (int i = 0; i < 4; i++) cp16(dA + off + i * 4096, pa + i * rstep);
#pragma unroll
        for (int i = 0; i < 8; i++) cp16(dW + off + i * 4096, pw + i * rstep);
        asm volatile("cp.async.commit_group;" ::: "memory");
    }

    float acc[4][8][4];
#pragma unroll
    for (int mf = 0; mf < 4; mf++)
#pragma unroll
        for (int nf = 0; nf < 8; nf++)
#pragma unroll
            for (int j = 0; j < 4; j++) acc[mf][nf][j] = 0.f;

    for (int kc = 0; kc < KC; kc++) {
        int pend = KC - 1 - kc;
        if (pend >= 2)      asm volatile("cp.async.wait_group 2;" ::: "memory");
        else if (pend == 1) asm volatile("cp.async.wait_group 1;" ::: "memory");
        else                asm volatile("cp.async.wait_group 0;" ::: "memory");
        __syncthreads();

        // refill the free slot before compute (overlap)
        if (kc + 3 < KC) {
            const int fs = (kc + 3) & 3;
            const __half* pa = srcA + (kc + 3) * 64;
            const __half* pw = srcW + (kc + 3) * 64;
            uint32_t off = fs * STG_BYTES;
#pragma unroll
            for (int i = 0; i < 4; i++) cp16(dA + off + i * 4096, pa + i * rstep);
#pragma unroll
            for (int i = 0; i < 8; i++) cp16(dW + off + i * 4096, pw + i * rstep);
            asm volatile("cp.async.commit_group;" ::: "memory");
        }

        const int slot = kc & 3;
        const char* sA = smem + slot * STG_BYTES;
        const char* sW = sA + AT_BYTES;
        const int sgx = g & 7;

#pragma unroll
        for (int ks2 = 0; ks2 < 2; ks2++) {
            const int segx = ((t + 4 * ks2) ^ sgx) * 16;
            uint4 af[4][2];
#pragma unroll
            for (int mf = 0; mf < 4; mf++) {
                const char* base = sA + (wm + mf * 16 + g) * 128 + segx;
                af[mf][0] = *(const uint4*)(base);
                af[mf][1] = *(const uint4*)(base + 1024);
            }
#pragma unroll
            for (int nf = 0; nf < 8; nf++) {
                const uint4 bf = *(const uint4*)(sW + (wn + nf * 8 + g) * 128 + segx);
#pragma unroll
                for (int mf = 0; mf < 4; mf++) {
                    mma16(acc[mf][nf], af[mf][0].x, af[mf][1].x, af[mf][0].y, af[mf][1].y,
                          bf.x, bf.y);
                    mma16(acc[mf][nf], af[mf][0].z, af[mf][1].z, af[mf][0].w, af[mf][1].w,
                          bf.z, bf.w);
                }
            }
        }
    }

    if (!(mode & 2)) {
        float* C = (float*)Cv;
#pragma unroll
        for (int nf = 0; nf < 8; nf++) {
            const int n = n0 + wn + nf * 8 + t * 2;
            const float2 bn = *(const float2*)(bias + n);
#pragma unroll
            for (int mf = 0; mf < 4; mf++) {
                const int m = m0 + wm + mf * 16 + g;
                float v0 = acc[mf][nf][0] + bn.x;
                float v1 = acc[mf][nf][1] + bn.y;
                float v2 = acc[mf][nf][2] + bn.x;
                float v3 = acc[mf][nf][3] + bn.y;
                if (mode & 1) {
                    v0 = v0 >= 0.f ? v0 : 0.2f * v0;
                    v1 = v1 >= 0.f ? v1 : 0.2f * v1;
                    v2 = v2 >= 0.f ? v2 : 0.2f * v2;
                    v3 = v3 >= 0.f ? v3 : 0.2f * v3;
                }
                *(float2*)(C + (size_t)m * Nt + n)       = make_float2(v0, v1);
                *(float2*)(C + (size_t)(m + 8) * Nt + n) = make_float2(v2, v3);
            }
        }
    } else {
        __half* C = (__half*)Cv;
        __syncthreads();
        __half2* se = (__half2*)smem;           // 128 x 128 half2
#pragma unroll
        for (int nf = 0; nf < 8; nf++) {
            const int n = wn + nf * 8 + t * 2;
            const int p = (n & ~63) + perm64(n & 63);
            const float2 bn = *(const float2*)(bias + n0 + n);
#pragma unroll
            for (int mf = 0; mf < 4; mf++) {
                const int m = wm + mf * 16 + g;
                float v0 = acc[mf][nf][0] + bn.x;
                float v1 = acc[mf][nf][1] + bn.y;
                float v2 = acc[mf][nf][2] + bn.x;
                float v3 = acc[mf][nf][3] + bn.y;
                if (mode & 1) {
                    v0 = v0 >= 0.f ? v0 : 0.2f * v0;
                    v1 = v1 >= 0.f ? v1 : 0.2f * v1;
                    v2 = v2 >= 0.f ? v2 : 0.2f * v2;
                    v3 = v3 >= 0.f ? v3 : 0.2f * v3;
                }
                se[m * 128 + (p >> 1)]       = __floats2half2_rn(v0, v1);
                se[(m + 8) * 128 + (p >> 1)] = __floats2half2_rn(v2, v3);
            }
        }
        __syncthreads();
#pragma unroll
        for (int i = 0; i < 16; i++) {
            int lin = tid + i * 256;
            int row = lin >> 5, f8 = lin & 31;
            *(uint4*)(C + (size_t)(m0 + row) * Nt + n0 + f8 * 8) =
                *(const uint4*)((const char*)smem + row * 512 + f8 * 16);
        }
    }
}

// ===================================================================
// LayerNorm + leaky relu over perm'd fp16 (stats are perm-invariant).
// gb: perm'd gamma at [0,H), perm'd beta at [H,2H). Block=256/row.
// ===================================================================
extern "C" __global__ void __launch_bounds__(256)
ln_lrelu(const __half* __restrict__ X, __half* __restrict__ Y,
         const float* __restrict__ gb, int H)
{
    __shared__ float red[16];
    const int r = blockIdx.x;
    const int t = threadIdx.x;
    const __half2* x2 = (const __half2*)(X + (size_t)r * H);
    __half2* y2 = (__half2*)(Y + (size_t)r * H);
    const int V = H >> 9;         // half2 per thread: 2 or 4
    float2 v[4];
    float s = 0.f, s2 = 0.f;
#pragma unroll 4
    for (int i = 0; i < V; i++) {
        v[i] = __half22float2(x2[t + (i << 8)]);
        s  += v[i].x + v[i].y;
        s2 += v[i].x * v[i].x + v[i].y * v[i].y;
    }
#pragma unroll
    for (int o = 16; o; o >>= 1) {
        s  += __shfl_xor_sync(~0u, s,  o);
        s2 += __shfl_xor_sync(~0u, s2, o);
    }
    if ((t & 31) == 0) { red[t >> 5] = s; red[8 + (t >> 5)] = s2; }
    __syncthreads();
    if (t < 32) {
        float a  = (t < 8) ? red[t]     : 0.f;
        float a2 = (t < 8) ? red[8 + t] : 0.f;
#pragma unroll
        for (int o = 4; o; o >>= 1) {
            a  += __shfl_xor_sync(~0u, a,  o);
            a2 += __shfl_xor_sync(~0u, a2, o);
        }
        if (t == 0) { red[0] = a; red[8] = a2; }
    }
    __syncthreads();
    const float inv = 1.f / (float)H;
    const float mu = red[0] * inv;
    const float var = red[8] * inv - mu * mu;
    const float rs = rsqrtf(var + 1e-5f);
    const float2* g2 = (const float2*)gb;
    const float2* b2 = (const float2*)(gb + H);
#pragma unroll 4
    for (int i = 0; i < V; i++) {
        const int idx = t + (i << 8);
        const float2 gg = g2[idx];
        const float2 bb = b2[idx];
        float o0 = (v[i].x - mu) * rs * gg.x + bb.x;
        float o1 = (v[i].y - mu) * rs * gg.y + bb.y;
        o0 = o0 >= 0.f ? o0 : 0.2f * o0;
        o1 = o1 >= 0.f ? o1 : 0.2f * o1;
        y2[idx] = __floats2half2_rn(o0, o1);
    }
}

// ===================================================================
// Reparameterize + context-memory attention. One warp per row.
// fp32 mu/lv/eps in; fp16 perm'd z_enh out.
// ===================================================================
extern "C" __global__ void __launch_bounds__(256)
reparam_attn(const float* __restrict__ mu, const float* __restrict__ lv,
             const float* __restrict__ eps, const float* __restrict__ ctx,
             __half* __restrict__ zout)
{
    __shared__ float sctx[32 * 257];
    __shared__ float sz[8][256];
    __shared__ float sat[8][32];
    const int t = threadIdx.x, w = t >> 5, l = t & 31;
    for (int i = t; i < 32 * 256; i += 256) {
        int m = i >> 8, k = i & 255;
        sctx[m * 257 + k] = ctx[i];
    }
    __syncthreads();
    const size_t r = (size_t)blockIdx.x * 8 + w;
    const float* murow = mu + r * 256;
    const float* lvrow = lv + r * 256;
    const float* erow  = eps + r * 256;
    float z[8];
#pragma unroll
    for (int j = 0; j < 4; j++) {
        int k = j * 64 + 2 * l;
        z[j * 2]     = murow[k]     + erow[k]     * expf(0.5f * lvrow[k]);
        z[j * 2 + 1] = murow[k + 1] + erow[k + 1] * expf(0.5f * lvrow[k + 1]);
        sz[w][k] = z[j * 2];
        sz[w][k + 1] = z[j * 2 + 1];
    }
    __syncwarp();
    float dot = 0.f;
    const float* cm = &sctx[l * 257];
#pragma unroll 8
    for (int k = 0; k < 256; k++) dot += sz[w][k] * cm[k];
    float mx = dot;
#pragma unroll
    for (int o = 16; o; o >>= 1) mx = fmaxf(mx, __shfl_xor_sync(~0u, mx, o));
    float e = expf(dot - mx);
    float sum = e;
#pragma unroll
    for (int o = 16; o; o >>= 1) sum += __shfl_xor_sync(~0u, sum, o);
    sat[w][l] = e / sum;
    __syncwarp();
    __half2* zo = (__half2*)(zout + r * 256);
#pragma unroll
    for (int j = 0; j < 4; j++) {
        int k = j * 64 + 2 * l;
        float a0 = 0.f, a1 = 0.f;
#pragma unroll
        for (int m = 0; m < 32; m++) {
            a0 += sat[w][m] * sctx[m * 257 + k];
            a1 += sat[w][m] * sctx[m * 257 + k + 1];
        }
        int p = j * 64 + perm64(k & 63);
        zo[p >> 1] = __floats2half2_rn(z[j * 2] + 0.1f * a0, z[j * 2 + 1] + 0.1f * a1);
    }
}

// ===================================================================
extern "C" void kernel_launch(void* const* d_in, const int* in_sizes, int n_in,
                              void* d_out, int out_size)
{
    (void)in_sizes; (void)n_in; (void)out_size;
    const float* x      = (const float*)d_in[0];
    const float* eps    = (const float*)d_in[1];
    const float* enc_w1 = (const float*)d_in[2];
    const float* enc_b1 = (const float*)d_in[3];
    const float* ln1_g  = (const float*)d_in[4];
    const float* ln1_b  = (const float*)d_in[5];
    const float* enc_w2 = (const float*)d_in[6];
    const float* enc_b2 = (const float*)d_in[7];
    const float* ln2_g  = (const float*)d_in[8];
    const float* ln2_b  = (const float*)d_in[9];
    const float* mu_w   = (const float*)d_in[10];
    const float* mu_b   = (const float*)d_in[11];
    const float* lv_w   = (const float*)d_in[12];
    const float* lv_b   = (const float*)d_in[13];
    const float* di_w   = (const float*)d_in[14];
    const float* di_b   = (const float*)d_in[15];
    const float* dec_w1 = (const float*)d_in[16];
    const float* dec_b1 = (const float*)d_in[17];
    const float* dln1_g = (const float*)d_in[18];
    const float* dln1_b = (const float*)d_in[19];
    const float* dec_w2 = (const float*)d_in[20];
    const float* dec_b2 = (const float*)d_in[21];
    const float* dln2_g = (const float*)d_in[22];
    const float* dln2_b = (const float*)d_in[23];
    const float* dec_w3 = (const float*)d_in[24];
    const float* dec_b3 = (const float*)d_in[25];
    const float* ctx    = (const float*)d_in[26];

    float* out    = (float*)d_out;
    float* out_mu = out + (size_t)B_ * D_;
    float* out_lv = out_mu + (size_t)B_ * L_;

    float* f32buf = nullptr; __half* hB = nullptr; __half* h1 = nullptr;
    __half* cvt = nullptr; float* lnp = nullptr;
    cudaGetSymbolAddress((void**)&f32buf, g_f32);
    cudaGetSymbolAddress((void**)&hB, g_h0);
    cudaGetSymbolAddress((void**)&h1, g_h1);
    cudaGetSymbolAddress((void**)&cvt, g_cvt);
    cudaGetSymbolAddress((void**)&lnp, g_lnp);
    __half* hA = (__half*)f32buf;   // alias fp32 scratch as half buffer

    cudaFuncSetAttribute(gemm_h, cudaFuncAttributeMaxDynamicSharedMemorySize, SM_TOTAL);

    // conversions
    conv_h<<<(B_ * D_ / 2 + 255) / 256, 256>>>(x, cvt + OFF_X, B_ * D_ / 2);
    conv_w<<<14336, 256>>>(enc_w1, enc_w2, mu_w, lv_w, di_w, dec_w1, dec_w2, dec_w3, cvt);
    conv_lnp<<<40, 256>>>(ln1_g, ln1_b, ln2_g, ln2_b, dln1_g, dln1_b, dln2_g, dln2_b, lnp);

    const dim3 blk(256);
    const dim3 gH(H_ / TN, B_ / TM);        // (4, 256)
    const dim3 gL(L_ / TN, B_ / TM);        // (1, 256)
    const dim3 g2H(2 * H_ / TN, B_ / TM);   // (8, 256)
    const dim3 gD(D_ / TN, B_ / TM);        // (3, 256)

    // encoder
    gemm_h<<<gH, blk, SM_TOTAL>>>(cvt + OFF_X, cvt + OFF_EW1, enc_b1, hA, D_, H_, 2);
    ln_lrelu<<<B_, 256>>>(hA, hB, lnp + 0, H_);
    gemm_h<<<gH, blk, SM_TOTAL>>>(hB, cvt + OFF_EW2, enc_b2, hA, H_, H_, 2);
    ln_lrelu<<<B_, 256>>>(hA, hB, lnp + 2048, H_);
    gemm_h<<<gL, blk, SM_TOTAL>>>(hB, cvt + OFF_MUW, mu_b, out_mu, H_, L_, 0);
    gemm_h<<<gL, blk, SM_TOTAL>>>(hB, cvt + OFF_LVW, lv_b, out_lv, H_, L_, 0);
    // reparameterize + context attention
    reparam_attn<<<B_ / 8, 256>>>(out_mu, out_lv, eps, ctx, h1);
    // decoder
    gemm_h<<<gH, blk, SM_TOTAL>>>(h1, cvt + OFF_DIW, di_b, hA, L_, H_, 3);
    gemm_h<<<gH, blk, SM_TOTAL>>>(hA, cvt + OFF_DW1, dec_b1, hB, H_, H_, 2);
    ln_lrelu<<<B_, 256>>>(hB, hA, lnp + 4096, H_);
    gemm_h<<<g2H, blk, SM_TOTAL>>>(hA, cvt + OFF_DW2, dec_b2, hB, H_, 2 * H_, 2);
    ln_lrelu<<<B_, 256>>>(hB, hA, lnp + 6144, 2 * H_);
    gemm_h<<<gD, blk, SM_TOTAL>>>(hA, cvt + OFF_DW3, dec_b3, out, 2 * H_, D_, 0);
}

// round 10
// speedup vs baseline: 1.7787x; 1.0159x over previous
#include <cuda_runtime.h>
#include <cuda_fp16.h>
#include <cstdint>

#define B_ 32768
#define D_ 768
#define H_ 1024
#define L_ 256

// ---------------- GEMM tiling ----------------
#define TM 128
#define TN 256
#define NTHREAD 512
#define AT_BYTES (128 * 128)              // A tile: 128 rows x 128B (64 halfs)
#define WT_BYTES (256 * 128)              // W tile
#define STG_BYTES (AT_BYTES + WT_BYTES)   // 49152
#define NSTAGE 4
#define SM_TOTAL (NSTAGE * STG_BYTES)     // 196608

// ---------------- scratch ----------------
static __device__ float  g_f32[(size_t)B_ * 2048];   // aliased as half buffer A
static __device__ __half g_h0[(size_t)B_ * 2048];    // half buffer B
static __device__ __half g_h1[(size_t)B_ * 256];     // z_enh
static __device__ __half g_cvt[32505856];            // x + weights, fp16 perm'd
static __device__ float  g_lnp[10240];               // perm'd LN gamma/beta

// offsets into g_cvt (halfs)
#define OFF_X    0
#define OFF_EW1  25165824
#define OFF_EW2  25952256
#define OFF_MUW  27000832
#define OFF_LVW  27262976
#define OFF_DIW  27525120
#define OFF_DW1  27787264
#define OFF_DW2  28835840
#define OFF_DW3  30932992

// ---------------- helpers ----------------
__device__ __forceinline__ uint32_t smem_u32(const void* p) {
    uint32_t a;
    asm("{ .reg .u64 t; cvta.to.shared.u64 t, %1; cvt.u32.u64 %0, t; }" : "=r"(a) : "l"(p));
    return a;
}
__device__ __forceinline__ void cp16(uint32_t sa, const void* g) {
    asm volatile("cp.async.cg.shared.global [%0], [%1], 16;" :: "r"(sa), "l"(g));
}
__device__ __forceinline__ void mma16(float* c, uint32_t a0, uint32_t a1, uint32_t a2, uint32_t a3,
                                      uint32_t b0, uint32_t b1) {
    asm volatile("mma.sync.aligned.m16n8k16.row.col.f32.f16.f16.f32 "
                 "{%0,%1,%2,%3}, {%4,%5,%6,%7}, {%8,%9}, {%0,%1,%2,%3};"
                 : "+f"(c[0]), "+f"(c[1]), "+f"(c[2]), "+f"(c[3])
                 : "r"(a0), "r"(a1), "r"(a2), "r"(a3), "r"(b0), "r"(b1));
}
// position of original col c (0..63) inside a 64-col chunk, fragment-interleaved
__device__ __forceinline__ int perm64(int c) {
    int kstep = (c >> 4) & 3, r = c & 15;
    return ((r >> 1) & 3) * 8 + (kstep >> 1) * 32 + (kstep & 1) * 4 + (r >> 3) * 2 + (c & 1);
}
// inverse: source col (even base) for perm'd position p
__device__ __forceinline__ int iperm_base(int p) {
    int t = (p >> 3) & 3, ks2 = (p & 63) >> 5, k1 = (p >> 2) & 1, h = (p >> 1) & 1;
    return (p & ~63) + (ks2 * 2 + k1) * 16 + 2 * t + 8 * h;
}

// ===================================================================
// conv_h: fp32 -> fp16 + fragment interleave (for x). One half2/thread.
// ===================================================================
extern "C" __global__ void __launch_bounds__(256)
conv_h(const float* __restrict__ src, __half* __restrict__ dst, int n2)
{
    int idx = blockIdx.x * 256 + threadIdx.x;
    if (idx < n2) {
        int c = iperm_base(idx * 2);
        ((__half2*)dst)[idx] = __floats2half2_rn(src[c], src[c + 1]);
    }
}

// ===================================================================
// conv_w: all 8 weight matrices in one launch (region dispatch by block).
// ===================================================================
extern "C" __global__ void __launch_bounds__(256)
conv_w(const float* s0, const float* s1, const float* s2, const float* s3,
       const float* s4, const float* s5, const float* s6, const float* s7,
       __half* __restrict__ cvt)
{
    int b = blockIdx.x;
    const float* src; size_t doff; int lb;
    if      (b < 1536)  { src = s0; doff = OFF_EW1; lb = b; }
    else if (b < 3584)  { src = s1; doff = OFF_EW2; lb = b - 1536; }
    else if (b < 4096)  { src = s2; doff = OFF_MUW; lb = b - 3584; }
    else if (b < 4608)  { src = s3; doff = OFF_LVW; lb = b - 4096; }
    else if (b < 5120)  { src = s4; doff = OFF_DIW; lb = b - 4608; }
    else if (b < 7168)  { src = s5; doff = OFF_DW1; lb = b - 5120; }
    else if (b < 11264) { src = s6; doff = OFF_DW2; lb = b - 7168; }
    else                { src = s7; doff = OFF_DW3; lb = b - 11264; }
    int idx = lb * 256 + threadIdx.x;
    int c = iperm_base(idx * 2);
    ((__half2*)(cvt + doff))[idx] = __floats2half2_rn(src[c], src[c + 1]);
}

// ===================================================================
// conv_lnp: permute LN gamma/beta (fp32) into g_lnp.
// ===================================================================
extern "C" __global__ void __launch_bounds__(256)
conv_lnp(const float* s0, const float* s1, const float* s2, const float* s3,
         const float* s4, const float* s5, const float* s6, const float* s7,
         float* __restrict__ dst)
{
    int b = blockIdx.x;
    const float* src; int doff, lb;
    if      (b < 4)  { src = s0; doff = 0;    lb = b; }
    else if (b < 8)  { src = s1; doff = 1024; lb = b - 4; }
    else if (b < 12) { src = s2; doff = 2048; lb = b - 8; }
    else if (b < 16) { src = s3; doff = 3072; lb = b - 12; }
    else if (b < 20) { src = s4; doff = 4096; lb = b - 16; }
    else if (b < 24) { src = s5; doff = 5120; lb = b - 20; }
    else if (b < 32) { src = s6; doff = 6144; lb = b - 24; }
    else             { src = s7; doff = 8192; lb = b - 32; }
    int p = lb * 256 + threadIdx.x;
    int c = iperm_base(p) + (p & 1);
    dst[doff + p] = src[c];
}

// ===================================================================
// GEMM: C[B, Nt] = A[B, K] @ W[Nt, K]^T + bias
// CTA 128x256, 512 threads, 16 warps, warp tile 32x64. 4-slot cp.async.
// mode bit0: lrelu; bit1: fp16 perm'd output; bit2: split fp32 output
//   (Nt=512: cols [0,256)->Cv w/ bias, [256,512)->Cv2 w/ bias2, stride 256).
// ===================================================================
extern "C" __global__ void __launch_bounds__(NTHREAD, 1)
gemm_h(const __half* __restrict__ A, const __half* __restrict__ W,
       const float* __restrict__ bias, const float* __restrict__ bias2,
       void* __restrict__ Cv, void* __restrict__ Cv2,
       int K, int Nt, int mode)
{
    extern __shared__ char smem[];
    const uint32_t sb = smem_u32(smem);
    const int tid = threadIdx.x;
    const int wid = tid >> 5;
    const int lid = tid & 31;
    const int g = lid >> 2;
    const int t = lid & 3;
    const int m0 = blockIdx.y * TM;
    const int n0 = blockIdx.x * TN;
    const int wm = (wid & 3) * 32;     // 4 m positions
    const int wn = (wid >> 2) * 64;    // 4 n positions

    // cp.async: 3072 16B chunks/stage; 6 per thread (2 A rows, 4 W rows)
    const int brow = tid >> 3, seg = tid & 7;      // brow 0..63
    const __half* srcA = A + (size_t)(m0 + brow) * K + seg * 8;
    const __half* srcW = W + (size_t)(n0 + brow) * K + seg * 8;
    const uint32_t dA = sb + brow * 128 + ((seg ^ (brow & 7)) * 16);
    const uint32_t dW = dA + AT_BYTES;
    const size_t rstep = (size_t)64 * K;           // 64 rows per iteration

    const int KC = K >> 6;

    // prologue: fill 3 of 4 slots
#pragma unroll
    for (int s = 0; s < NSTAGE - 1; s++) {
        const __half* pa = srcA + s * 64;
        const __half* pw = srcW + s * 64;
        uint32_t off = s * STG_BYTES;
#pragma unroll
        for (int i = 0; i < 2; i++) cp16(dA + off + i * 8192, pa + i * rstep);
#pragma unroll
        for (int i = 0; i < 4; i++) cp16(dW + off + i * 8192, pw + i * rstep);
        asm volatile("cp.async.commit_group;" ::: "memory");
    }

    float acc[2][8][4];
#pragma unroll
    for (int mf = 0; mf < 2; mf++)
#pragma unroll
        for (int nf = 0; nf < 8; nf++)
#pragma unroll
            for (int j = 0; j < 4; j++) acc[mf][nf][j] = 0.f;

    for (int kc = 0; kc < KC; kc++) {
        int pend = KC - 1 - kc;
        if (pend >= 2)      asm volatile("cp.async.wait_group 2;" ::: "memory");
        else if (pend == 1) asm volatile("cp.async.wait_group 1;" ::: "memory");
        else                asm volatile("cp.async.wait_group 0;" ::: "memory");
        __syncthreads();

        // refill free slot before compute
        if (kc + 3 < KC) {
            const int fs = (kc + 3) & 3;
            const __half* pa = srcA + (kc + 3) * 64;
            const __half* pw = srcW + (kc + 3) * 64;
            uint32_t off = fs * STG_BYTES;
#pragma unroll
            for (int i = 0; i < 2; i++) cp16(dA + off + i * 8192, pa + i * rstep);
#pragma unroll
            for (int i = 0; i < 4; i++) cp16(dW + off + i * 8192, pw + i * rstep);
            asm volatile("cp.async.commit_group;" ::: "memory");
        }

        const int slot = kc & 3;
        const char* sA = smem + slot * STG_BYTES;
        const char* sW = sA + AT_BYTES;
        const int sgx = g & 7;

#pragma unroll
        for (int ks2 = 0; ks2 < 2; ks2++) {
            const int segx = ((t + 4 * ks2) ^ sgx) * 16;
            uint4 af[2][2];
#pragma unroll
            for (int mf = 0; mf < 2; mf++) {
                const char* base = sA + (wm + mf * 16 + g) * 128 + segx;
                af[mf][0] = *(const uint4*)(base);
                af[mf][1] = *(const uint4*)(base + 1024);   // +8 rows
            }
#pragma unroll
            for (int h = 0; h < 2; h++) {
                uint4 bf[4];
#pragma unroll
                for (int q = 0; q < 4; q++)
                    bf[q] = *(const uint4*)(sW + (wn + h * 32 + q * 8 + g) * 128 + segx);
#pragma unroll
                for (int mf = 0; mf < 2; mf++)
#pragma unroll
                    for (int q = 0; q < 4; q++) {
                        float* a = acc[mf][h * 4 + q];
                        mma16(a, af[mf][0].x, af[mf][1].x, af[mf][0].y, af[mf][1].y,
                              bf[q].x, bf[q].y);
                        mma16(a, af[mf][0].z, af[mf][1].z, af[mf][0].w, af[mf][1].w,
                              bf[q].z, bf[q].w);
                    }
            }
        }
    }

    if (mode & 4) {
        // split fp32 output: Nt==512, cols<256 -> Cv/bias, else Cv2/bias2
#pragma unroll
        for (int nf = 0; nf < 8; nf++) {
            const int ng = n0 + wn + nf * 8 + t * 2;   // 0..511
            float* C = (ng < 256) ? (float*)Cv : (float*)Cv2;
            const float* bp = (ng < 256) ? bias : bias2;
            const int n = ng & 255;
            const float2 bn = *(const float2*)(bp + n);
#pragma unroll
            for (int mf = 0; mf < 2; mf++) {
                const int m = m0 + wm + mf * 16 + g;
                *(float2*)(C + (size_t)m * 256 + n) =
                    make_float2(acc[mf][nf][0] + bn.x, acc[mf][nf][1] + bn.y);
                *(float2*)(C + (size_t)(m + 8) * 256 + n) =
                    make_float2(acc[mf][nf][2] + bn.x, acc[mf][nf][3] + bn.y);
            }
        }
    } else if (!(mode & 2)) {
        float* C = (float*)Cv;
#pragma unroll
        for (int nf = 0; nf < 8; nf++) {
            const int n = n0 + wn + nf * 8 + t * 2;
            const float2 bn = *(const float2*)(bias + n);
#pragma unroll
            for (int mf = 0; mf < 2; mf++) {
                const int m = m0 + wm + mf * 16 + g;
                float v0 = acc[mf][nf][0] + bn.x;
                float v1 = acc[mf][nf][1] + bn.y;
                float v2 = acc[mf][nf][2] + bn.x;
                float v3 = acc[mf][nf][3] + bn.y;
                if (mode & 1) {
                    v0 = v0 >= 0.f ? v0 : 0.2f * v0;
                    v1 = v1 >= 0.f ? v1 : 0.2f * v1;
                    v2 = v2 >= 0.f ? v2 : 0.2f * v2;
                    v3 = v3 >= 0.f ? v3 : 0.2f * v3;
                }
                *(float2*)(C + (size_t)m * Nt + n)       = make_float2(v0, v1);
                *(float2*)(C + (size_t)(m + 8) * Nt + n) = make_float2(v2, v3);
            }
        }
    } else {
        __half* C = (__half*)Cv;
        __syncthreads();
        __half2* se = (__half2*)smem;           // 128 x 128 half2
#pragma unroll
        for (int nf = 0; nf < 8; nf++) {
            const int n = wn + nf * 8 + t * 2;
            const int p = (n & ~63) + perm64(n & 63);
            const float2 bn = *(const float2*)(bias + n0 + n);
#pragma unroll
            for (int mf = 0; mf < 2; mf++) {
                const int m = wm + mf * 16 + g;
                float v0 = acc[mf][nf][0] + bn.x;
                float v1 = acc[mf][nf][1] + bn.y;
                float v2 = acc[mf][nf][2] + bn.x;
                float v3 = acc[mf][nf][3] + bn.y;
                if (mode & 1) {
                    v0 = v0 >= 0.f ? v0 : 0.2f * v0;
                    v1 = v1 >= 0.f ? v1 : 0.2f * v1;
                    v2 = v2 >= 0.f ? v2 : 0.2f * v2;
                    v3 = v3 >= 0.f ? v3 : 0.2f * v3;
                }
                se[m * 128 + (p >> 1)]       = __floats2half2_rn(v0, v1);
                se[(m + 8) * 128 + (p >> 1)] = __floats2half2_rn(v2, v3);
            }
        }
        __syncthreads();
#pragma unroll
        for (int i = 0; i < 8; i++) {
            int lin = tid + i * NTHREAD;
            int row = lin >> 5, f8 = lin & 31;
            *(uint4*)(C + (size_t)(m0 + row) * Nt + n0 + f8 * 8) =
                *(const uint4*)((const char*)smem + row * 512 + f8 * 16);
        }
    }
}

// ===================================================================
// LayerNorm + leaky relu over perm'd fp16 (stats perm-invariant).
// gb: perm'd gamma [0,H), perm'd beta [H,2H). Block=256/row.
// ===================================================================
extern "C" __global__ void __launch_bounds__(256)
ln_lrelu(const __half* __restrict__ X, __half* __restrict__ Y,
         const float* __restrict__ gb, int H)
{
    __shared__ float red[16];
    const int r = blockIdx.x;
    const int t = threadIdx.x;
    const __half2* x2 = (const __half2*)(X + (size_t)r * H);
    __half2* y2 = (__half2*)(Y + (size_t)r * H);
    const int V = H >> 9;
    float2 v[4];
    float s = 0.f, s2 = 0.f;
#pragma unroll 4
    for (int i = 0; i < V; i++) {
        v[i] = __half22float2(x2[t + (i << 8)]);
        s  += v[i].x + v[i].y;
        s2 += v[i].x * v[i].x + v[i].y * v[i].y;
    }
#pragma unroll
    for (int o = 16; o; o >>= 1) {
        s  += __shfl_xor_sync(~0u, s,  o);
        s2 += __shfl_xor_sync(~0u, s2, o);
    }
    if ((t & 31) == 0) { red[t >> 5] = s; red[8 + (t >> 5)] = s2; }
    __syncthreads();
    if (t < 32) {
        float a  = (t < 8) ? red[t]     : 0.f;
        float a2 = (t < 8) ? red[8 + t] : 0.f;
#pragma unroll
        for (int o = 4; o; o >>= 1) {
            a  += __shfl_xor_sync(~0u, a,  o);
            a2 += __shfl_xor_sync(~0u, a2, o);
        }
        if (t == 0) { red[0] = a; red[8] = a2; }
    }
    __syncthreads();
    const float inv = 1.f / (float)H;
    const float mu = red[0] * inv;
    const float var = red[8] * inv - mu * mu;
    const float rs = rsqrtf(var + 1e-5f);
    const float2* g2 = (const float2*)gb;
    const float2* b2 = (const float2*)(gb + H);
#pragma unroll 4
    for (int i = 0; i < V; i++) {
        const int idx = t + (i << 8);
        const float2 gg = g2[idx];
        const float2 bb = b2[idx];
        float o0 = (v[i].x - mu) * rs * gg.x + bb.x;
        float o1 = (v[i].y - mu) * rs * gg.y + bb.y;
        o0 = o0 >= 0.f ? o0 : 0.2f * o0;
        o1 = o1 >= 0.f ? o1 : 0.2f * o1;
        y2[idx] = __floats2half2_rn(o0, o1);
    }
}

// ===================================================================
// Reparameterize + context-memory attention. One warp per row.
// ===================================================================
extern "C" __global__ void __launch_bounds__(256)
reparam_attn(const float* __restrict__ mu, const float* __restrict__ lv,
             const float* __restrict__ eps, const float* __restrict__ ctx,
             __half* __restrict__ zout)
{
    __shared__ float sctx[32 * 257];
    __shared__ float sz[8][256];
    __shared__ float sat[8][32];
    const int t = threadIdx.x, w = t >> 5, l = t & 31;
    for (int i = t; i < 32 * 256; i += 256) {
        int m = i >> 8, k = i & 255;
        sctx[m * 257 + k] = ctx[i];
    }
    __syncthreads();
    const size_t r = (size_t)blockIdx.x * 8 + w;
    const float* murow = mu + r * 256;
    const float* lvrow = lv + r * 256;
    const float* erow  = eps + r * 256;
    float z[8];
#pragma unroll
    for (int j = 0; j < 4; j++) {
        int k = j * 64 + 2 * l;
        z[j * 2]     = murow[k]     + erow[k]     * expf(0.5f * lvrow[k]);
        z[j * 2 + 1] = murow[k + 1] + erow[k + 1] * expf(0.5f * lvrow[k + 1]);
        sz[w][k] = z[j * 2];
        sz[w][k + 1] = z[j * 2 + 1];
    }
    __syncwarp();
    float dot = 0.f;
    const float* cm = &sctx[l * 257];
#pragma unroll 8
    for (int k = 0; k < 256; k++) dot += sz[w][k] * cm[k];
    float mx = dot;
#pragma unroll
    for (int o = 16; o; o >>= 1) mx = fmaxf(mx, __shfl_xor_sync(~0u, mx, o));
    float e = expf(dot - mx);
    float sum = e;
#pragma unroll
    for (int o = 16; o; o >>= 1) sum += __shfl_xor_sync(~0u, sum, o);
    sat[w][l] = e / sum;
    __syncwarp();
    __half2* zo = (__half2*)(zout + r * 256);
#pragma unroll
    for (int j = 0; j < 4; j++) {
        int k = j * 64 + 2 * l;
        float a0 = 0.f, a1 = 0.f;
#pragma unroll
        for (int m = 0; m < 32; m++) {
            a0 += sat[w][m] * sctx[m * 257 + k];
            a1 += sat[w][m] * sctx[m * 257 + k + 1];
        }
        int p = j * 64 + perm64(k & 63);
        zo[p >> 1] = __floats2half2_rn(z[j * 2] + 0.1f * a0, z[j * 2 + 1] + 0.1f * a1);
    }
}

// ===================================================================
extern "C" void kernel_launch(void* const* d_in, const int* in_sizes, int n_in,
                              void* d_out, int out_size)
{
    (void)in_sizes; (void)n_in; (void)out_size;
    const float* x      = (const float*)d_in[0];
    const float* eps    = (const float*)d_in[1];
    const float* enc_w1 = (const float*)d_in[2];
    const float* enc_b1 = (const float*)d_in[3];
    const float* ln1_g  = (const float*)d_in[4];
    const float* ln1_b  = (const float*)d_in[5];
    const float* enc_w2 = (const float*)d_in[6];
    const float* enc_b2 = (const float*)d_in[7];
    const float* ln2_g  = (const float*)d_in[8];
    const float* ln2_b  = (const float*)d_in[9];
    const float* mu_w   = (const float*)d_in[10];
    const float* mu_b   = (const float*)d_in[11];
    const float* lv_w   = (const float*)d_in[12];
    const float* lv_b   = (const float*)d_in[13];
    const float* di_w   = (const float*)d_in[14];
    const float* di_b   = (const float*)d_in[15];
    const float* dec_w1 = (const float*)d_in[16];
    const float* dec_b1 = (const float*)d_in[17];
    const float* dln1_g = (const float*)d_in[18];
    const float* dln1_b = (const float*)d_in[19];
    const float* dec_w2 = (const float*)d_in[20];
    const float* dec_b2 = (const float*)d_in[21];
    const float* dln2_g = (const float*)d_in[22];
    const float* dln2_b = (const float*)d_in[23];
    const float* dec_w3 = (const float*)d_in[24];
    const float* dec_b3 = (const float*)d_in[25];
    const float* ctx    = (const float*)d_in[26];

    float* out    = (float*)d_out;
    float* out_mu = out + (size_t)B_ * D_;
    float* out_lv = out_mu + (size_t)B_ * L_;

    float* f32buf = nullptr; __half* hB = nullptr; __half* h1 = nullptr;
    __half* cvt = nullptr; float* lnp = nullptr;
    cudaGetSymbolAddress((void**)&f32buf, g_f32);
    cudaGetSymbolAddress((void**)&hB, g_h0);
    cudaGetSymbolAddress((void**)&h1, g_h1);
    cudaGetSymbolAddress((void**)&cvt, g_cvt);
    cudaGetSymbolAddress((void**)&lnp, g_lnp);
    __half* hA = (__half*)f32buf;

    cudaFuncSetAttribute(gemm_h, cudaFuncAttributeMaxDynamicSharedMemorySize, SM_TOTAL);

    conv_h<<<(B_ * D_ / 2 + 255) / 256, 256>>>(x, cvt + OFF_X, B_ * D_ / 2);
    conv_w<<<14336, 256>>>(enc_w1, enc_w2, mu_w, lv_w, di_w, dec_w1, dec_w2, dec_w3, cvt);
    conv_lnp<<<40, 256>>>(ln1_g, ln1_b, ln2_g, ln2_b, dln1_g, dln1_b, dln2_g, dln2_b, lnp);

    const dim3 blk(NTHREAD);
    const dim3 gH(H_ / TN, B_ / TM);        // (4, 256)
    const dim3 gML(512 / TN, B_ / TM);      // (2, 256) merged mu+lv
    const dim3 g2H(2 * H_ / TN, B_ / TM);   // (8, 256)
    const dim3 gD(D_ / TN, B_ / TM);        // (3, 256)

    // encoder
    gemm_h<<<gH, blk, SM_TOTAL>>>(cvt + OFF_X, cvt + OFF_EW1, enc_b1, nullptr,
                                  hA, nullptr, D_, H_, 2);
    ln_lrelu<<<B_, 256>>>(hA, hB, lnp + 0, H_);
    gemm_h<<<gH, blk, SM_TOTAL>>>(hB, cvt + OFF_EW2, enc_b2, nullptr,
                                  hA, nullptr, H_, H_, 2);
    ln_lrelu<<<B_, 256>>>(hA, hB, lnp + 2048, H_);
    // merged mu + logvar (weights contiguous at OFF_MUW)
    gemm_h<<<gML, blk, SM_TOTAL>>>(hB, cvt + OFF_MUW, mu_b, lv_b,
                                   out_mu, out_lv, H_, 512, 4);
    // reparameterize + context attention
    reparam_attn<<<B_ / 8, 256>>>(out_mu, out_lv, eps, ctx, h1);
    // decoder
    gemm_h<<<gH, blk, SM_TOTAL>>>(h1, cvt + OFF_DIW, di_b, nullptr,
                                  hA, nullptr, L_, H_, 3);
    gemm_h<<<gH, blk, SM_TOTAL>>>(hA, cvt + OFF_DW1, dec_b1, nullptr,
                                  hB, nullptr, H_, H_, 2);
    ln_lrelu<<<B_, 256>>>(hB, hA, lnp + 4096, H_);
    gemm_h<<<g2H, blk, SM_TOTAL>>>(hA, cvt + OFF_DW2, dec_b2, nullptr,
                                   hB, nullptr, H_, 2 * H_, 2);
    ln_lrelu<<<B_, 256>>>(hB, hA, lnp + 6144, 2 * H_);
    gemm_h<<<gD, blk, SM_TOTAL>>>(hA, cvt + OFF_DW3, dec_b3, nullptr,
                                  out, nullptr, 2 * H_, D_, 0);
}

// round 11
// speedup vs baseline: 2.0974x; 1.1792x over previous
#include <cuda_runtime.h>
#include <cuda_fp16.h>
#include <cstdint>

#define B_ 32768
#define D_ 768
#define H_ 1024
#define L_ 256

// ---------------- GEMM tiling ----------------
#define TM 128
#define TN 256
#define NTHREAD 256
#define AT_BYTES (128 * 128)              // A tile: 128 rows x 128B (64 halfs)
#define WT_BYTES (256 * 128)              // W tile
#define STG_BYTES (AT_BYTES + WT_BYTES)   // 49152
#define NSTAGE 4
#define SM_TOTAL (NSTAGE * STG_BYTES)     // 196608

// ---------------- scratch ----------------
static __device__ float  g_f32[(size_t)B_ * 2048];   // aliased as half buffer A
static __device__ __half g_h0[(size_t)B_ * 2048];    // half buffer B
static __device__ __half g_h1[(size_t)B_ * 256];     // z_enh
static __device__ __half g_cvt[32505856];            // x + weights, fp16

// offsets into g_cvt (halfs)
#define OFF_X    0
#define OFF_EW1  25165824
#define OFF_EW2  25952256
#define OFF_MUW  27000832
#define OFF_LVW  27262976
#define OFF_DIW  27525120
#define OFF_DW1  27787264
#define OFF_DW2  28835840
#define OFF_DW3  30932992

// ---------------- helpers ----------------
__device__ __forceinline__ uint32_t smem_u32(const void* p) {
    uint32_t a;
    asm("{ .reg .u64 t; cvta.to.shared.u64 t, %1; cvt.u32.u64 %0, t; }" : "=r"(a) : "l"(p));
    return a;
}
__device__ __forceinline__ void cp16(uint32_t sa, const void* g) {
    asm volatile("cp.async.cg.shared.global [%0], [%1], 16;" :: "r"(sa), "l"(g));
}
__device__ __forceinline__ void mma16(float* c, uint32_t a0, uint32_t a1, uint32_t a2, uint32_t a3,
                                      uint32_t b0, uint32_t b1) {
    asm volatile("mma.sync.aligned.m16n8k16.row.col.f32.f16.f16.f32 "
                 "{%0,%1,%2,%3}, {%4,%5,%6,%7}, {%8,%9}, {%0,%1,%2,%3};"
                 : "+f"(c[0]), "+f"(c[1]), "+f"(c[2]), "+f"(c[3])
                 : "r"(a0), "r"(a1), "r"(a2), "r"(a3), "r"(b0), "r"(b1));
}
__device__ __forceinline__ void ldm4(uint32_t* r, uint32_t addr) {
    asm volatile("ldmatrix.sync.aligned.m8n8.x4.shared.b16 {%0,%1,%2,%3}, [%4];"
                 : "=r"(r[0]), "=r"(r[1]), "=r"(r[2]), "=r"(r[3]) : "r"(addr));
}

// ===================================================================
// conv_h: fp32 -> fp16 plain. One half2 per thread.
// ===================================================================
extern "C" __global__ void __launch_bounds__(256)
conv_h(const float* __restrict__ src, __half* __restrict__ dst, int n2)
{
    int idx = blockIdx.x * 256 + threadIdx.x;
    if (idx < n2)
        ((__half2*)dst)[idx] = __floats2half2_rn(src[idx * 2], src[idx * 2 + 1]);
}

// ===================================================================
// conv_w: all 8 weight matrices in one launch.
// ===================================================================
extern "C" __global__ void __launch_bounds__(256)
conv_w(const float* s0, const float* s1, const float* s2, const float* s3,
       const float* s4, const float* s5, const float* s6, const float* s7,
       __half* __restrict__ cvt)
{
    int b = blockIdx.x;
    const float* src; size_t doff; int lb;
    if      (b < 1536)  { src = s0; doff = OFF_EW1; lb = b; }
    else if (b < 3584)  { src = s1; doff = OFF_EW2; lb = b - 1536; }
    else if (b < 4096)  { src = s2; doff = OFF_MUW; lb = b - 3584; }
    else if (b < 4608)  { src = s3; doff = OFF_LVW; lb = b - 4096; }
    else if (b < 5120)  { src = s4; doff = OFF_DIW; lb = b - 4608; }
    else if (b < 7168)  { src = s5; doff = OFF_DW1; lb = b - 5120; }
    else if (b < 11264) { src = s6; doff = OFF_DW2; lb = b - 7168; }
    else                { src = s7; doff = OFF_DW3; lb = b - 11264; }
    int idx = lb * 256 + threadIdx.x;
    ((__half2*)(cvt + doff))[idx] = __floats2half2_rn(src[idx * 2], src[idx * 2 + 1]);
}

// ===================================================================
// GEMM: C[B, Nt] = A[B, K] @ W[Nt, K]^T + bias
// CTA 128x256, 256 threads, 8 warps (2m x 4n), warp tile 64x64.
// ldmatrix fragment loads (conflict-free with XOR-seg swizzle).
// mode bit0: lrelu; bit1: fp16 output (staged via smem); bit2: split fp32
//   output (Nt=512: cols<256 -> Cv/bias, else Cv2/bias2, stride 256).
// ===================================================================
extern "C" __global__ void __launch_bounds__(NTHREAD, 1)
gemm_h(const __half* __restrict__ A, const __half* __restrict__ W,
       const float* __restrict__ bias, const float* __restrict__ bias2,
       void* __restrict__ Cv, void* __restrict__ Cv2,
       int K, int Nt, int mode)
{
    extern __shared__ char smem[];
    const uint32_t sb = smem_u32(smem);
    const int tid = threadIdx.x;
    const int wid = tid >> 5;
    const int lid = tid & 31;
    const int g = lid >> 2;
    const int t = lid & 3;
    const int m0 = blockIdx.y * TM;
    const int n0 = blockIdx.x * TN;
    const int wm = (wid & 1) * 64;     // 2 m warp-positions
    const int wn = (wid >> 1) * 64;    // 4 n warp-positions

    // ldmatrix lane constants
    const int e    = lid & 7;          // row-within-8
    const int bsel = (lid >> 3) & 1;   // +8 rows (second m8/n8 tile)
    const int hsel = lid >> 4;         // +1 seg (k8..k16)
    const uint32_t rowA = (uint32_t)(wm + e + bsel * 8) * 128;
    const uint32_t rowB = (uint32_t)(wn + e + bsel * 8) * 128;

    // cp.async mapping: 3072 16B chunks/stage; 12 per thread (4 A + 8 W rows)
    const int brow = tid >> 3, seg = tid & 7;      // brow 0..31
    const __half* srcA = A + (size_t)(m0 + brow) * K + seg * 8;
    const __half* srcW = W + (size_t)(n0 + brow) * K + seg * 8;
    const uint32_t dA = sb + brow * 128 + ((seg ^ (brow & 7)) * 16);
    const uint32_t dW = dA + AT_BYTES;
    const size_t rstep = (size_t)32 * K;

    const int KC = K >> 6;

    // prologue: fill 3 of 4 slots
#pragma unroll
    for (int s = 0; s < NSTAGE - 1; s++) {
        const __half* pa = srcA + s * 64;
        const __half* pw = srcW + s * 64;
        uint32_t off = s * STG_BYTES;
#pragma unroll
        for (int i = 0; i < 4; i++) cp16(dA + off + i * 4096, pa + i * rstep);
#pragma unroll
        for (int i = 0; i < 8; i++) cp16(dW + off + i * 4096, pw + i * rstep);
        asm volatile("cp.async.commit_group;" ::: "memory");
    }

    float acc[4][8][4];
#pragma unroll
    for (int mf = 0; mf < 4; mf++)
#pragma unroll
        for (int nf = 0; nf < 8; nf++)
#pragma unroll
            for (int j = 0; j < 4; j++) acc[mf][nf][j] = 0.f;

    for (int kc = 0; kc < KC; kc++) {
        int pend = KC - 1 - kc;
        if (pend >= 2)      asm volatile("cp.async.wait_group 2;" ::: "memory");
        else if (pend == 1) asm volatile("cp.async.wait_group 1;" ::: "memory");
        else                asm volatile("cp.async.wait_group 0;" ::: "memory");
        __syncthreads();

        // refill free slot before compute
        if (kc + 3 < KC) {
            const int fs = (kc + 3) & 3;
            const __half* pa = srcA + (kc + 3) * 64;
            const __half* pw = srcW + (kc + 3) * 64;
            uint32_t off = fs * STG_BYTES;
#pragma unroll
            for (int i = 0; i < 4; i++) cp16(dA + off + i * 4096, pa + i * rstep);
#pragma unroll
            for (int i = 0; i < 8; i++) cp16(dW + off + i * 4096, pw + i * rstep);
            asm volatile("cp.async.commit_group;" ::: "memory");
        }

        const int slot = kc & 3;
        const uint32_t sAc = sb + slot * STG_BYTES;
        const uint32_t sWc = sAc + AT_BYTES;

        // double-buffered fragments over 4 k16-steps
        uint32_t af[2][4][4], bf[2][4][4];
        {
            const uint32_t so = (uint32_t)((hsel ^ e) * 16);   // j=0
#pragma unroll
            for (int mf = 0; mf < 4; mf++) ldm4(af[0][mf], sAc + rowA + mf * 2048 + so);
#pragma unroll
            for (int q = 0; q < 4; q++)  ldm4(bf[0][q], sWc + rowB + q * 2048 + so);
        }
#pragma unroll
        for (int j = 0; j < 4; j++) {
            const int cur = j & 1, nxt = cur ^ 1;
            if (j < 3) {
                const uint32_t so = (uint32_t)(((2 * (j + 1) + hsel) ^ e) * 16);
#pragma unroll
                for (int mf = 0; mf < 4; mf++) ldm4(af[nxt][mf], sAc + rowA + mf * 2048 + so);
#pragma unroll
                for (int q = 0; q < 4; q++)  ldm4(bf[nxt][q], sWc + rowB + q * 2048 + so);
            }
#pragma unroll
            for (int mf = 0; mf < 4; mf++)
#pragma unroll
                for (int q = 0; q < 4; q++) {
                    mma16(acc[mf][2 * q],     af[cur][mf][0], af[cur][mf][1],
                          af[cur][mf][2], af[cur][mf][3], bf[cur][q][0], bf[cur][q][2]);
                    mma16(acc[mf][2 * q + 1], af[cur][mf][0], af[cur][mf][1],
                          af[cur][mf][2], af[cur][mf][3], bf[cur][q][1], bf[cur][q][3]);
                }
        }
    }

    if (mode & 4) {
        // split fp32 output: Nt==512
#pragma unroll
        for (int nf = 0; nf < 8; nf++) {
            const int ng = n0 + wn + nf * 8 + t * 2;
            float* C = (ng < 256) ? (float*)Cv : (float*)Cv2;
            const float* bp = (ng < 256) ? bias : bias2;
            const int n = ng & 255;
            const float2 bn = *(const float2*)(bp + n);
#pragma unroll
            for (int mf = 0; mf < 4; mf++) {
                const int m = m0 + wm + mf * 16 + g;
                *(float2*)(C + (size_t)m * 256 + n) =
                    make_float2(acc[mf][nf][0] + bn.x, acc[mf][nf][1] + bn.y);
                *(float2*)(C + (size_t)(m + 8) * 256 + n) =
                    make_float2(acc[mf][nf][2] + bn.x, acc[mf][nf][3] + bn.y);
            }
        }
    } else if (!(mode & 2)) {
        float* C = (float*)Cv;
#pragma unroll
        for (int nf = 0; nf < 8; nf++) {
            const int n = n0 + wn + nf * 8 + t * 2;
            const float2 bn = *(const float2*)(bias + n);
#pragma unroll
            for (int mf = 0; mf < 4; mf++) {
                const int m = m0 + wm + mf * 16 + g;
                float v0 = acc[mf][nf][0] + bn.x;
                float v1 = acc[mf][nf][1] + bn.y;
                float v2 = acc[mf][nf][2] + bn.x;
                float v3 = acc[mf][nf][3] + bn.y;
                if (mode & 1) {
                    v0 = v0 >= 0.f ? v0 : 0.2f * v0;
                    v1 = v1 >= 0.f ? v1 : 0.2f * v1;
                    v2 = v2 >= 0.f ? v2 : 0.2f * v2;
                    v3 = v3 >= 0.f ? v3 : 0.2f * v3;
                }
                *(float2*)(C + (size_t)m * Nt + n)       = make_float2(v0, v1);
                *(float2*)(C + (size_t)(m + 8) * Nt + n) = make_float2(v2, v3);
            }
        }
    } else {
        __half* C = (__half*)Cv;
        __syncthreads();
        __half2* se = (__half2*)smem;           // 128 x 128 half2
#pragma unroll
        for (int nf = 0; nf < 8; nf++) {
            const int n = wn + nf * 8 + t * 2;
            const float2 bn = *(const float2*)(bias + n0 + n);
#pragma unroll
            for (int mf = 0; mf < 4; mf++) {
                const int m = wm + mf * 16 + g;
                float v0 = acc[mf][nf][0] + bn.x;
                float v1 = acc[mf][nf][1] + bn.y;
                float v2 = acc[mf][nf][2] + bn.x;
                float v3 = acc[mf][nf][3] + bn.y;
                if (mode & 1) {
                    v0 = v0 >= 0.f ? v0 : 0.2f * v0;
                    v1 = v1 >= 0.f ? v1 : 0.2f * v1;
                    v2 = v2 >= 0.f ? v2 : 0.2f * v2;
                    v3 = v3 >= 0.f ? v3 : 0.2f * v3;
                }
                se[m * 128 + (n >> 1)]       = __floats2half2_rn(v0, v1);
                se[(m + 8) * 128 + (n >> 1)] = __floats2half2_rn(v2, v3);
            }
        }
        __syncthreads();
#pragma unroll
        for (int i = 0; i < 16; i++) {
            int lin = tid + i * NTHREAD;
            int row = lin >> 5, f8 = lin & 31;
            *(uint4*)(C + (size_t)(m0 + row) * Nt + n0 + f8 * 8) =
                *(const uint4*)((const char*)smem + row * 512 + f8 * 16);
        }
    }
}

// ===================================================================
// LayerNorm + leaky relu over fp16. Block=256/row, H in {1024, 2048}.
// ===================================================================
extern "C" __global__ void __launch_bounds__(256)
ln_lrelu(const __half* __restrict__ X, __half* __restrict__ Y,
         const float* __restrict__ gw, const float* __restrict__ bw, int H)
{
    __shared__ float red[16];
    const int r = blockIdx.x;
    const int t = threadIdx.x;
    const __half2* x2 = (const __half2*)(X + (size_t)r * H);
    __half2* y2 = (__half2*)(Y + (size_t)r * H);
    const int V = H >> 9;
    float2 v[4];
    float s = 0.f, s2 = 0.f;
#pragma unroll 4
    for (int i = 0; i < V; i++) {
        v[i] = __half22float2(x2[t + (i << 8)]);
        s  += v[i].x + v[i].y;
        s2 += v[i].x * v[i].x + v[i].y * v[i].y;
    }
#pragma unroll
    for (int o = 16; o; o >>= 1) {
        s  += __shfl_xor_sync(~0u, s,  o);
        s2 += __shfl_xor_sync(~0u, s2, o);
    }
    if ((t & 31) == 0) { red[t >> 5] = s; red[8 + (t >> 5)] = s2; }
    __syncthreads();
    if (t < 32) {
        float a  = (t < 8) ? red[t]     : 0.f;
        float a2 = (t < 8) ? red[8 + t] : 0.f;
#pragma unroll
        for (int o = 4; o; o >>= 1) {
            a  += __shfl_xor_sync(~0u, a,  o);
            a2 += __shfl_xor_sync(~0u, a2, o);
        }
        if (t == 0) { red[0] = a; red[8] = a2; }
    }
    __syncthreads();
    const float inv = 1.f / (float)H;
    const float mu = red[0] * inv;
    const float var = red[8] * inv - mu * mu;
    const float rs = rsqrtf(var + 1e-5f);
    const float2* g2 = (const float2*)gw;
    const float2* b2 = (const float2*)bw;
#pragma unroll 4
    for (int i = 0; i < V; i++) {
        const int idx = t + (i << 8);
        const float2 gg = g2[idx];
        const float2 bb = b2[idx];
        float o0 = (v[i].x - mu) * rs * gg.x + bb.x;
        float o1 = (v[i].y - mu) * rs * gg.y + bb.y;
        o0 = o0 >= 0.f ? o0 : 0.2f * o0;
        o1 = o1 >= 0.f ? o1 : 0.2f * o1;
        y2[idx] = __floats2half2_rn(o0, o1);
    }
}

// ===================================================================
// Reparameterize + context-memory attention. One warp per row.
// ===================================================================
extern "C" __global__ void __launch_bounds__(256)
reparam_attn(const float* __restrict__ mu, const float* __restrict__ lv,
             const float* __restrict__ eps, const float* __restrict__ ctx,
             __half* __restrict__ zout)
{
    __shared__ float sctx[32 * 257];
    __shared__ float sz[8][256];
    __shared__ float sat[8][32];
    const int t = threadIdx.x, w = t >> 5, l = t & 31;
    for (int i = t; i < 32 * 256; i += 256) {
        int m = i >> 8, k = i & 255;
        sctx[m * 257 + k] = ctx[i];
    }
    __syncthreads();
    const size_t r = (size_t)blockIdx.x * 8 + w;
    const float* murow = mu + r * 256;
    const float* lvrow = lv + r * 256;
    const float* erow  = eps + r * 256;
    float z[8];
#pragma unroll
    for (int j = 0; j < 4; j++) {
        int k = j * 64 + 2 * l;
        z[j * 2]     = murow[k]     + erow[k]     * expf(0.5f * lvrow[k]);
        z[j * 2 + 1] = murow[k + 1] + erow[k + 1] * expf(0.5f * lvrow[k + 1]);
        sz[w][k] = z[j * 2];
        sz[w][k + 1] = z[j * 2 + 1];
    }
    __syncwarp();
    float dot = 0.f;
    const float* cm = &sctx[l * 257];
#pragma unroll 8
    for (int k = 0; k < 256; k++) dot += sz[w][k] * cm[k];
    float mx = dot;
#pragma unroll
    for (int o = 16; o; o >>= 1) mx = fmaxf(mx, __shfl_xor_sync(~0u, mx, o));
    float e = expf(dot - mx);
    float sum = e;
#pragma unroll
    for (int o = 16; o; o >>= 1) sum += __shfl_xor_sync(~0u, sum, o);
    sat[w][l] = e / sum;
    __syncwarp();
    __half2* zo = (__half2*)(zout + r * 256);
#pragma unroll
    for (int j = 0; j < 4; j++) {
        int k = j * 64 + 2 * l;
        float a0 = 0.f, a1 = 0.f;
#pragma unroll
        for (int m = 0; m < 32; m++) {
            a0 += sat[w][m] * sctx[m * 257 + k];
            a1 += sat[w][m] * sctx[m * 257 + k + 1];
        }
        zo[k >> 1] = __floats2half2_rn(z[j * 2] + 0.1f * a0, z[j * 2 + 1] + 0.1f * a1);
    }
}

// ===================================================================
extern "C" void kernel_launch(void* const* d_in, const int* in_sizes, int n_in,
                              void* d_out, int out_size)
{
    (void)in_sizes; (void)n_in; (void)out_size;
    const float* x      = (const float*)d_in[0];
    const float* eps    = (const float*)d_in[1];
    const float* enc_w1 = (const float*)d_in[2];
    const float* enc_b1 = (const float*)d_in[3];
    const float* ln1_g  = (const float*)d_in[4];
    const float* ln1_b  = (const float*)d_in[5];
    const float* enc_w2 = (const float*)d_in[6];
    const float* enc_b2 = (const float*)d_in[7];
    const float* ln2_g  = (const float*)d_in[8];
    const float* ln2_b  = (const float*)d_in[9];
    const float* mu_w   = (const float*)d_in[10];
    const float* mu_b   = (const float*)d_in[11];
    const float* lv_w   = (const float*)d_in[12];
    const float* lv_b   = (const float*)d_in[13];
    const float* di_w   = (const float*)d_in[14];
    const float* di_b   = (const float*)d_in[15];
    const float* dec_w1 = (const float*)d_in[16];
    const float* dec_b1 = (const float*)d_in[17];
    const float* dln1_g = (const float*)d_in[18];
    const float* dln1_b = (const float*)d_in[19];
    const float* dec_w2 = (const float*)d_in[20];
    const float* dec_b2 = (const float*)d_in[21];
    const float* dln2_g = (const float*)d_in[22];
    const float* dln2_b = (const float*)d_in[23];
    const float* dec_w3 = (const float*)d_in[24];
    const float* dec_b3 = (const float*)d_in[25];
    const float* ctx    = (const float*)d_in[26];

    float* out    = (float*)d_out;
    float* out_mu = out + (size_t)B_ * D_;
    float* out_lv = out_mu + (size_t)B_ * L_;

    float* f32buf = nullptr; __half* hB = nullptr; __half* h1 = nullptr; __half* cvt = nullptr;
    cudaGetSymbolAddress((void**)&f32buf, g_f32);
    cudaGetSymbolAddress((void**)&hB, g_h0);
    cudaGetSymbolAddress((void**)&h1, g_h1);
    cudaGetSymbolAddress((void**)&cvt, g_cvt);
    __half* hA = (__half*)f32buf;

    cudaFuncSetAttribute(gemm_h, cudaFuncAttributeMaxDynamicSharedMemorySize, SM_TOTAL);

    conv_h<<<(B_ * D_ / 2 + 255) / 256, 256>>>(x, cvt + OFF_X, B_ * D_ / 2);
    conv_w<<<14336, 256>>>(enc_w1, enc_w2, mu_w, lv_w, di_w, dec_w1, dec_w2, dec_w3, cvt);

    const dim3 blk(NTHREAD);
    const dim3 gH(H_ / TN, B_ / TM);        // (4, 256)
    const dim3 gML(512 / TN, B_ / TM);      // (2, 256) merged mu+lv
    const dim3 g2H(2 * H_ / TN, B_ / TM);   // (8, 256)
    const dim3 gD(D_ / TN, B_ / TM);        // (3, 256)

    // encoder
    gemm_h<<<gH, blk, SM_TOTAL>>>(cvt + OFF_X, cvt + OFF_EW1, enc_b1, nullptr,
                                  hA, nullptr, D_, H_, 2);
    ln_lrelu<<<B_, 256>>>(hA, hB, ln1_g, ln1_b, H_);
    gemm_h<<<gH, blk, SM_TOTAL>>>(hB, cvt + OFF_EW2, enc_b2, nullptr,
                                  hA, nullptr, H_, H_, 2);
    ln_lrelu<<<B_, 256>>>(hA, hB, ln2_g, ln2_b, H_);
    // merged mu + logvar (weights contiguous at OFF_MUW)
    gemm_h<<<gML, blk, SM_TOTAL>>>(hB, cvt + OFF_MUW, mu_b, lv_b,
                                   out_mu, out_lv, H_, 512, 4);
    // reparameterize + context attention
    reparam_attn<<<B_ / 8, 256>>>(out_mu, out_lv, eps, ctx, h1);
    // decoder
    gemm_h<<<gH, blk, SM_TOTAL>>>(h1, cvt + OFF_DIW, di_b, nullptr,
                                  hA, nullptr, L_, H_, 3);
    gemm_h<<<gH, blk, SM_TOTAL>>>(hA, cvt + OFF_DW1, dec_b1, nullptr,
                                  hB, nullptr, H_, H_, 2);
    ln_lrelu<<<B_, 256>>>(hB, hA, dln1_g, dln1_b, H_);
    gemm_h<<<g2H, blk, SM_TOTAL>>>(hA, cvt + OFF_DW2, dec_b2, nullptr,
                                   hB, nullptr, H_, 2 * H_, 2);
    ln_lrelu<<<B_, 256>>>(hB, hA, dln2_g, dln2_b, 2 * H_);
    gemm_h<<<gD, blk, SM_TOTAL>>>(hA, cvt + OFF_DW3, dec_b3, nullptr,
                                  out, nullptr, 2 * H_, D_, 0);
}

// round 12
// speedup vs baseline: 2.1034x; 1.0029x over previous
#include <cuda_runtime.h>
#include <cuda_fp16.h>
#include <cstdint>

#define B_ 32768
#define D_ 768
#define H_ 1024
#define L_ 256

// ---------------- GEMM tiling ----------------
#define TM 128
#define TN 256
#define NTHREAD 256
#define AT_BYTES (128 * 128)              // A tile: 128 rows x 128B (64 halfs)
#define WT_BYTES (256 * 128)              // W tile
#define STG_BYTES (AT_BYTES + WT_BYTES)   // 49152
#define NSTAGE 4
#define SM_TOTAL (NSTAGE * STG_BYTES)     // 196608

// ---------------- scratch ----------------
static __device__ float  g_f32[(size_t)B_ * 2048];   // aliased as half buffer A
static __device__ __half g_h0[(size_t)B_ * 2048];    // half buffer B
static __device__ __half g_h1[(size_t)B_ * 256];     // z_enh
static __device__ __half g_cvt[32505856];            // x + weights, fp16

// offsets into g_cvt (halfs)
#define OFF_X    0
#define OFF_EW1  25165824
#define OFF_EW2  25952256
#define OFF_MUW  27000832
#define OFF_LVW  27262976
#define OFF_DIW  27525120
#define OFF_DW1  27787264
#define OFF_DW2  28835840
#define OFF_DW3  30932992

// ---------------- helpers ----------------
__device__ __forceinline__ uint32_t smem_u32(const void* p) {
    uint32_t a;
    asm("{ .reg .u64 t; cvta.to.shared.u64 t, %1; cvt.u32.u64 %0, t; }" : "=r"(a) : "l"(p));
    return a;
}
__device__ __forceinline__ void cp16(uint32_t sa, const void* g) {
    asm volatile("cp.async.cg.shared.global [%0], [%1], 16;" :: "r"(sa), "l"(g));
}
__device__ __forceinline__ void mma16(float* c, uint32_t a0, uint32_t a1, uint32_t a2, uint32_t a3,
                                      uint32_t b0, uint32_t b1) {
    asm volatile("mma.sync.aligned.m16n8k16.row.col.f32.f16.f16.f32 "
                 "{%0,%1,%2,%3}, {%4,%5,%6,%7}, {%8,%9}, {%0,%1,%2,%3};"
                 : "+f"(c[0]), "+f"(c[1]), "+f"(c[2]), "+f"(c[3])
                 : "r"(a0), "r"(a1), "r"(a2), "r"(a3), "r"(b0), "r"(b1));
}
__device__ __forceinline__ void ldm4(uint32_t* r, uint32_t addr) {
    asm volatile("ldmatrix.sync.aligned.m8n8.x4.shared.b16 {%0,%1,%2,%3}, [%4];"
                 : "=r"(r[0]), "=r"(r[1]), "=r"(r[2]), "=r"(r[3]) : "r"(addr));
}

// ===================================================================
// conv_h: fp32 -> fp16 plain. One half2 per thread.
// ===================================================================
extern "C" __global__ void __launch_bounds__(256)
conv_h(const float* __restrict__ src, __half* __restrict__ dst, int n2)
{
    int idx = blockIdx.x * 256 + threadIdx.x;
    if (idx < n2)
        ((__half2*)dst)[idx] = __floats2half2_rn(src[idx * 2], src[idx * 2 + 1]);
}

// ===================================================================
// conv_w: all 8 weight matrices in one launch.
// ===================================================================
extern "C" __global__ void __launch_bounds__(256)
conv_w(const float* s0, const float* s1, const float* s2, const float* s3,
       const float* s4, const float* s5, const float* s6, const float* s7,
       __half* __restrict__ cvt)
{
    int b = blockIdx.x;
    const float* src; size_t doff; int lb;
    if      (b < 1536)  { src = s0; doff = OFF_EW1; lb = b; }
    else if (b < 3584)  { src = s1; doff = OFF_EW2; lb = b - 1536; }
    else if (b < 4096)  { src = s2; doff = OFF_MUW; lb = b - 3584; }
    else if (b < 4608)  { src = s3; doff = OFF_LVW; lb = b - 4096; }
    else if (b < 5120)  { src = s4; doff = OFF_DIW; lb = b - 4608; }
    else if (b < 7168)  { src = s5; doff = OFF_DW1; lb = b - 5120; }
    else if (b < 11264) { src = s6; doff = OFF_DW2; lb = b - 7168; }
    else                { src = s7; doff = OFF_DW3; lb = b - 11264; }
    int idx = lb * 256 + threadIdx.x;
    ((__half2*)(cvt + doff))[idx] = __floats2half2_rn(src[idx * 2], src[idx * 2 + 1]);
}

// ===================================================================
// GEMM: C[B, Nt] = A[B, K] @ W[Nt, K]^T + bias
// CTA 128x256, 256 threads, 8 warps (2m x 4n), warp tile 64x64.
// ldmatrix fragment loads (conflict-free with XOR-seg swizzle).
// mode bit0: lrelu; bit1: fp16 output (staged via smem); bit2: split fp32
//   output (Nt=512: cols<256 -> Cv/bias, else Cv2/bias2, stride 256).
// ===================================================================
extern "C" __global__ void __launch_bounds__(NTHREAD, 1)
gemm_h(const __half* __restrict__ A, const __half* __restrict__ W,
       const float* __restrict__ bias, const float* __restrict__ bias2,
       void* __restrict__ Cv, void* __restrict__ Cv2,
       int K, int Nt, int mode)
{
    extern __shared__ char smem[];
    const uint32_t sb = smem_u32(smem);
    const int tid = threadIdx.x;
    const int wid = tid >> 5;
    const int lid = tid & 31;
    const int g = lid >> 2;
    const int t = lid & 3;
    const int m0 = blockIdx.y * TM;
    const int n0 = blockIdx.x * TN;
    const int wm = (wid & 1) * 64;     // 2 m warp-positions
    const int wn = (wid >> 1) * 64;    // 4 n warp-positions

    // ldmatrix lane constants
    const int e    = lid & 7;          // row-within-8
    const int bsel = (lid >> 3) & 1;   // +8 rows (second m8/n8 tile)
    const int hsel = lid >> 4;         // +1 seg (k8..k16)
    const uint32_t rowA = (uint32_t)(wm + e + bsel * 8) * 128;
    const uint32_t rowB = (uint32_t)(wn + e + bsel * 8) * 128;

    // cp.async mapping: 3072 16B chunks/stage; 12 per thread (4 A + 8 W rows)
    const int brow = tid >> 3, seg = tid & 7;      // brow 0..31
    const __half* srcA = A + (size_t)(m0 + brow) * K + seg * 8;
    const __half* srcW = W + (size_t)(n0 + brow) * K + seg * 8;
    const uint32_t dA = sb + brow * 128 + ((seg ^ (brow & 7)) * 16);
    const uint32_t dW = dA + AT_BYTES;
    const size_t rstep = (size_t)32 * K;

    const int KC = K >> 6;

    // prologue: fill 3 of 4 slots
#pragma unroll
    for (int s = 0; s < NSTAGE - 1; s++) {
        const __half* pa = srcA + s * 64;
        const __half* pw = srcW + s * 64;
        uint32_t off = s * STG_BYTES;
#pragma unroll
        for (int i = 0; i < 4; i++) cp16(dA + off + i * 4096, pa + i * rstep);
#pragma unroll
        for (int i = 0; i < 8; i++) cp16(dW + off + i * 4096, pw + i * rstep);
        asm volatile("cp.async.commit_group;" ::: "memory");
    }

    float acc[4][8][4];
#pragma unroll
    for (int mf = 0; mf < 4; mf++)
#pragma unroll
        for (int nf = 0; nf < 8; nf++)
#pragma unroll
            for (int j = 0; j < 4; j++) acc[mf][nf][j] = 0.f;

    for (int kc = 0; kc < KC; kc++) {
        int pend = KC - 1 - kc;
        if (pend >= 2)      asm volatile("cp.async.wait_group 2;" ::: "memory");
        else if (pend == 1) asm volatile("cp.async.wait_group 1;" ::: "memory");
        else                asm volatile("cp.async.wait_group 0;" ::: "memory");
        __syncthreads();

        // refill free slot before compute
        if (kc + 3 < KC) {
            const int fs = (kc + 3) & 3;
            const __half* pa = srcA + (kc + 3) * 64;
            const __half* pw = srcW + (kc + 3) * 64;
            uint32_t off = fs * STG_BYTES;
#pragma unroll
            for (int i = 0; i < 4; i++) cp16(dA + off + i * 4096, pa + i * rstep);
#pragma unroll
            for (int i = 0; i < 8; i++) cp16(dW + off + i * 4096, pw + i * rstep);
            asm volatile("cp.async.commit_group;" ::: "memory");
        }

        const int slot = kc & 3;
        const uint32_t sAc = sb + slot * STG_BYTES;
        const uint32_t sWc = sAc + AT_BYTES;

        // double-buffered fragments over 4 k16-steps
        uint32_t af[2][4][4], bf[2][4][4];
        {
            const uint32_t so = (uint32_t)((hsel ^ e) * 16);   // j=0
#pragma unroll
            for (int mf = 0; mf < 4; mf++) ldm4(af[0][mf], sAc + rowA + mf * 2048 + so);
#pragma unroll
            for (int q = 0; q < 4; q++)  ldm4(bf[0][q], sWc + rowB + q * 2048 + so);
        }
#pragma unroll
        for (int j = 0; j < 4; j++) {
            const int cur = j & 1, nxt = cur ^ 1;
            if (j < 3) {
                const uint32_t so = (uint32_t)(((2 * (j + 1) + hsel) ^ e) * 16);
#pragma unroll
                for (int mf = 0; mf < 4; mf++) ldm4(af[nxt][mf], sAc + rowA + mf * 2048 + so);
#pragma unroll
                for (int q = 0; q < 4; q++)  ldm4(bf[nxt][q], sWc + rowB + q * 2048 + so);
            }
#pragma unroll
            for (int mf = 0; mf < 4; mf++)
#pragma unroll
                for (int q = 0; q < 4; q++) {
                    mma16(acc[mf][2 * q],     af[cur][mf][0], af[cur][mf][1],
                          af[cur][mf][2], af[cur][mf][3], bf[cur][q][0], bf[cur][q][2]);
                    mma16(acc[mf][2 * q + 1], af[cur][mf][0], af[cur][mf][1],
                          af[cur][mf][2], af[cur][mf][3], bf[cur][q][1], bf[cur][q][3]);
                }
        }
    }

    if (mode & 4) {
        // split fp32 output: Nt==512
#pragma unroll
        for (int nf = 0; nf < 8; nf++) {
            const int ng = n0 + wn + nf * 8 + t * 2;
            float* C = (ng < 256) ? (float*)Cv : (float*)Cv2;
            const float* bp = (ng < 256) ? bias : bias2;
            const int n = ng & 255;
            const float2 bn = *(const float2*)(bp + n);
#pragma unroll
            for (int mf = 0; mf < 4; mf++) {
                const int m = m0 + wm + mf * 16 + g;
                *(float2*)(C + (size_t)m * 256 + n) =
                    make_float2(acc[mf][nf][0] + bn.x, acc[mf][nf][1] + bn.y);
                *(float2*)(C + (size_t)(m + 8) * 256 + n) =
                    make_float2(acc[mf][nf][2] + bn.x, acc[mf][nf][3] + bn.y);
            }
        }
    } else if (!(mode & 2)) {
        float* C = (float*)Cv;
#pragma unroll
        for (int nf = 0; nf < 8; nf++) {
            const int n = n0 + wn + nf * 8 + t * 2;
            const float2 bn = *(const float2*)(bias + n);
#pragma unroll
            for (int mf = 0; mf < 4; mf++) {
                const int m = m0 + wm + mf * 16 + g;
                float v0 = acc[mf][nf][0] + bn.x;
                float v1 = acc[mf][nf][1] + bn.y;
                float v2 = acc[mf][nf][2] + bn.x;
                float v3 = acc[mf][nf][3] + bn.y;
                if (mode & 1) {
                    v0 = v0 >= 0.f ? v0 : 0.2f * v0;
                    v1 = v1 >= 0.f ? v1 : 0.2f * v1;
                    v2 = v2 >= 0.f ? v2 : 0.2f * v2;
                    v3 = v3 >= 0.f ? v3 : 0.2f * v3;
                }
                *(float2*)(C + (size_t)m * Nt + n)       = make_float2(v0, v1);
                *(float2*)(C + (size_t)(m + 8) * Nt + n) = make_float2(v2, v3);
            }
        }
    } else {
        __half* C = (__half*)Cv;
        __syncthreads();
        __half2* se = (__half2*)smem;           // 128 x 128 half2
#pragma unroll
        for (int nf = 0; nf < 8; nf++) {
            const int n = wn + nf * 8 + t * 2;
            const float2 bn = *(const float2*)(bias + n0 + n);
#pragma unroll
            for (int mf = 0; mf < 4; mf++) {
                const int m = wm + mf * 16 + g;
                float v0 = acc[mf][nf][0] + bn.x;
                float v1 = acc[mf][nf][1] + bn.y;
                float v2 = acc[mf][nf][2] + bn.x;
                float v3 = acc[mf][nf][3] + bn.y;
                if (mode & 1) {
                    v0 = v0 >= 0.f ? v0 : 0.2f * v0;
                    v1 = v1 >= 0.f ? v1 : 0.2f * v1;
                    v2 = v2 >= 0.f ? v2 : 0.2f * v2;
                    v3 = v3 >= 0.f ? v3 : 0.2f * v3;
                }
                se[m * 128 + (n >> 1)]       = __floats2half2_rn(v0, v1);
                se[(m + 8) * 128 + (n >> 1)] = __floats2half2_rn(v2, v3);
            }
        }
        __syncthreads();
#pragma unroll
        for (int i = 0; i < 16; i++) {
            int lin = tid + i * NTHREAD;
            int row = lin >> 5, f8 = lin & 31;
            *(uint4*)(C + (size_t)(m0 + row) * Nt + n0 + f8 * 8) =
                *(const uint4*)((const char*)smem + row * 512 + f8 * 16);
        }
    }
}

// ===================================================================
// LayerNorm + leaky relu, warp-per-row. uint4 (8-half) loads, pure
// shfl reduction. Block = 8 warps = 8 rows; grid = B/8.
// ===================================================================
extern "C" __global__ void __launch_bounds__(256)
ln_lrelu(const __half* __restrict__ X, __half* __restrict__ Y,
         const float* __restrict__ gw, const float* __restrict__ bw, int H)
{
    const int w = threadIdx.x >> 5, l = threadIdx.x & 31;
    const size_t r = (size_t)blockIdx.x * 8 + w;
    const uint4* x4 = (const uint4*)(X + r * H);
    uint4* y4 = (uint4*)(Y + r * H);
    const int V = H >> 8;          // uint4 per lane: 4 (H=1024) or 8 (H=2048)

    uint4 v[8];
    float2 f[8][4];
    float s = 0.f, s2 = 0.f;
#pragma unroll 8
    for (int i = 0; i < V; i++) {
        v[i] = x4[l + (i << 5)];
        const __half2* h2 = (const __half2*)&v[i];
#pragma unroll
        for (int j = 0; j < 4; j++) {
            f[i][j] = __half22float2(h2[j]);
            s  += f[i][j].x + f[i][j].y;
            s2 += f[i][j].x * f[i][j].x + f[i][j].y * f[i][j].y;
        }
    }
#pragma unroll
    for (int o = 16; o; o >>= 1) {
        s  += __shfl_xor_sync(~0u, s,  o);
        s2 += __shfl_xor_sync(~0u, s2, o);
    }
    const float inv = 1.f / (float)H;
    const float mu = s * inv;
    const float var = s2 * inv - mu * mu;
    const float rs = rsqrtf(var + 1e-5f);

#pragma unroll 8
    for (int i = 0; i < V; i++) {
        const int c8 = (l + (i << 5)) * 2;    // float4-pair index
        const float4 g0 = ((const float4*)gw)[c8];
        const float4 g1 = ((const float4*)gw)[c8 + 1];
        const float4 b0 = ((const float4*)bw)[c8];
        const float4 b1 = ((const float4*)bw)[c8 + 1];
        float o0 = (f[i][0].x - mu) * rs * g0.x + b0.x;
        float o1 = (f[i][0].y - mu) * rs * g0.y + b0.y;
        float o2 = (f[i][1].x - mu) * rs * g0.z + b0.z;
        float o3 = (f[i][1].y - mu) * rs * g0.w + b0.w;
        float o4 = (f[i][2].x - mu) * rs * g1.x + b1.x;
        float o5 = (f[i][2].y - mu) * rs * g1.y + b1.y;
        float o6 = (f[i][3].x - mu) * rs * g1.z + b1.z;
        float o7 = (f[i][3].y - mu) * rs * g1.w + b1.w;
        o0 = o0 >= 0.f ? o0 : 0.2f * o0;  o1 = o1 >= 0.f ? o1 : 0.2f * o1;
        o2 = o2 >= 0.f ? o2 : 0.2f * o2;  o3 = o3 >= 0.f ? o3 : 0.2f * o3;
        o4 = o4 >= 0.f ? o4 : 0.2f * o4;  o5 = o5 >= 0.f ? o5 : 0.2f * o5;
        o6 = o6 >= 0.f ? o6 : 0.2f * o6;  o7 = o7 >= 0.f ? o7 : 0.2f * o7;
        uint4 ov;
        __half2* oh = (__half2*)&ov;
        oh[0] = __floats2half2_rn(o0, o1);
        oh[1] = __floats2half2_rn(o2, o3);
        oh[2] = __floats2half2_rn(o4, o5);
        oh[3] = __floats2half2_rn(o6, o7);
        y4[l + (i << 5)] = ov;
    }
}

// ===================================================================
// Reparameterize + context-memory attention. One warp per row.
// ===================================================================
extern "C" __global__ void __launch_bounds__(256)
reparam_attn(const float* __restrict__ mu, const float* __restrict__ lv,
             const float* __restrict__ eps, const float* __restrict__ ctx,
             __half* __restrict__ zout)
{
    __shared__ float sctx[32 * 257];
    __shared__ float sz[8][256];
    __shared__ float sat[8][32];
    const int t = threadIdx.x, w = t >> 5, l = t & 31;
    for (int i = t; i < 32 * 256; i += 256) {
        int m = i >> 8, k = i & 255;
        sctx[m * 257 + k] = ctx[i];
    }
    __syncthreads();
    const size_t r = (size_t)blockIdx.x * 8 + w;
    const float* murow = mu + r * 256;
    const float* lvrow = lv + r * 256;
    const float* erow  = eps + r * 256;
    float z[8];
#pragma unroll
    for (int j = 0; j < 4; j++) {
        int k = j * 64 + 2 * l;
        z[j * 2]     = murow[k]     + erow[k]     * expf(0.5f * lvrow[k]);
        z[j * 2 + 1] = murow[k + 1] + erow[k + 1] * expf(0.5f * lvrow[k + 1]);
        sz[w][k] = z[j * 2];
        sz[w][k + 1] = z[j * 2 + 1];
    }
    __syncwarp();
    float dot = 0.f;
    const float* cm = &sctx[l * 257];
#pragma unroll 8
    for (int k = 0; k < 256; k++) dot += sz[w][k] * cm[k];
    float mx = dot;
#pragma unroll
    for (int o = 16; o; o >>= 1) mx = fmaxf(mx, __shfl_xor_sync(~0u, mx, o));
    float e = expf(dot - mx);
    float sum = e;
#pragma unroll
    for (int o = 16; o; o >>= 1) sum += __shfl_xor_sync(~0u, sum, o);
    sat[w][l] = e / sum;
    __syncwarp();
    __half2* zo = (__half2*)(zout + r * 256);
#pragma unroll
    for (int j = 0; j < 4; j++) {
        int k = j * 64 + 2 * l;
        float a0 = 0.f, a1 = 0.f;
#pragma unroll
        for (int m = 0; m < 32; m++) {
            a0 += sat[w][m] * sctx[m * 257 + k];
            a1 += sat[w][m] * sctx[m * 257 + k + 1];
        }
        zo[k >> 1] = __floats2half2_rn(z[j * 2] + 0.1f * a0, z[j * 2 + 1] + 0.1f * a1);
    }
}

// ===================================================================
extern "C" void kernel_launch(void* const* d_in, const int* in_sizes, int n_in,
                              void* d_out, int out_size)
{
    (void)in_sizes; (void)n_in; (void)out_size;
    const float* x      = (const float*)d_in[0];
    const float* eps    = (const float*)d_in[1];
    const float* enc_w1 = (const float*)d_in[2];
    const float* enc_b1 = (const float*)d_in[3];
    const float* ln1_g  = (const float*)d_in[4];
    const float* ln1_b  = (const float*)d_in[5];
    const float* enc_w2 = (const float*)d_in[6];
    const float* enc_b2 = (const float*)d_in[7];
    const float* ln2_g  = (const float*)d_in[8];
    const float* ln2_b  = (const float*)d_in[9];
    const float* mu_w   = (const float*)d_in[10];
    const float* mu_b   = (const float*)d_in[11];
    const float* lv_w   = (const float*)d_in[12];
    const float* lv_b   = (const float*)d_in[13];
    const float* di_w   = (const float*)d_in[14];
    const float* di_b   = (const float*)d_in[15];
    const float* dec_w1 = (const float*)d_in[16];
    const float* dec_b1 = (const float*)d_in[17];
    const float* dln1_g = (const float*)d_in[18];
    const float* dln1_b = (const float*)d_in[19];
    const float* dec_w2 = (const float*)d_in[20];
    const float* dec_b2 = (const float*)d_in[21];
    const float* dln2_g = (const float*)d_in[22];
    const float* dln2_b = (const float*)d_in[23];
    const float* dec_w3 = (const float*)d_in[24];
    const float* dec_b3 = (const float*)d_in[25];
    const float* ctx    = (const float*)d_in[26];

    float* out    = (float*)d_out;
    float* out_mu = out + (size_t)B_ * D_;
    float* out_lv = out_mu + (size_t)B_ * L_;

    float* f32buf = nullptr; __half* hB = nullptr; __half* h1 = nullptr; __half* cvt = nullptr;
    cudaGetSymbolAddress((void**)&f32buf, g_f32);
    cudaGetSymbolAddress((void**)&hB, g_h0);
    cudaGetSymbolAddress((void**)&h1, g_h1);
    cudaGetSymbolAddress((void**)&cvt, g_cvt);
    __half* hA = (__half*)f32buf;

    cudaFuncSetAttribute(gemm_h, cudaFuncAttributeMaxDynamicSharedMemorySize, SM_TOTAL);

    conv_h<<<(B_ * D_ / 2 + 255) / 256, 256>>>(x, cvt + OFF_X, B_ * D_ / 2);
    conv_w<<<14336, 256>>>(enc_w1, enc_w2, mu_w, lv_w, di_w, dec_w1, dec_w2, dec_w3, cvt);

    const dim3 blk(NTHREAD);
    const dim3 gH(H_ / TN, B_ / TM);        // (4, 256)
    const dim3 gML(512 / TN, B_ / TM);      // (2, 256) merged mu+lv
    const dim3 g2H(2 * H_ / TN, B_ / TM);   // (8, 256)
    const dim3 gD(D_ / TN, B_ / TM);        // (3, 256)

    // encoder
    gemm_h<<<gH, blk, SM_TOTAL>>>(cvt + OFF_X, cvt + OFF_EW1, enc_b1, nullptr,
                                  hA, nullptr, D_, H_, 2);
    ln_lrelu<<<B_ / 8, 256>>>(hA, hB, ln1_g, ln1_b, H_);
    gemm_h<<<gH, blk, SM_TOTAL>>>(hB, cvt + OFF_EW2, enc_b2, nullptr,
                                  hA, nullptr, H_, H_, 2);
    ln_lrelu<<<B_ / 8, 256>>>(hA, hB, ln2_g, ln2_b, H_);
    // merged mu + logvar (weights contiguous at OFF_MUW)
    gemm_h<<<gML, blk, SM_TOTAL>>>(hB, cvt + OFF_MUW, mu_b, lv_b,
                                   out_mu, out_lv, H_, 512, 4);
    // reparameterize + context attention
    reparam_attn<<<B_ / 8, 256>>>(out_mu, out_lv, eps, ctx, h1);
    // decoder
    gemm_h<<<gH, blk, SM_TOTAL>>>(h1, cvt + OFF_DIW, di_b, nullptr,
                                  hA, nullptr, L_, H_, 3);
    gemm_h<<<gH, blk, SM_TOTAL>>>(hA, cvt + OFF_DW1, dec_b1, nullptr,
                                  hB, nullptr, H_, H_, 2);
    ln_lrelu<<<B_ / 8, 256>>>(hB, hA, dln1_g, dln1_b, H_);
    gemm_h<<<g2H, blk, SM_TOTAL>>>(hA, cvt + OFF_DW2, dec_b2, nullptr,
                                   hB, nullptr, H_, 2 * H_, 2);
    ln_lrelu<<<B_ / 8, 256>>>(hB, hA, dln2_g, dln2_b, 2 * H_);
    gemm_h<<<gD, blk, SM_TOTAL>>>(hA, cvt + OFF_DW3, dec_b3, nullptr,
                                  out, nullptr, 2 * H_, D_, 0);
}

// round 14
// speedup vs baseline: 2.3943x; 1.1383x over previous
#include <cuda_runtime.h>
#include <cuda_fp16.h>
#include <cstdint>

#define B_ 32768
#define D_ 768
#define H_ 1024
#define L_ 256

// ---------------- GEMM tiling ----------------
#define TM 128
#define TN 128
#define NTHREAD 128
#define AT_BYTES (128 * 128)              // A tile: 128 rows x 128B
#define WT_BYTES (128 * 128)              // W tile: 128 rows x 128B
#define STG_BYTES (AT_BYTES + WT_BYTES)   // 32768
#define NSTAGE 3
#define SM_TOTAL (NSTAGE * STG_BYTES)     // 98304 -> 2 CTAs/SM

// ---------------- scratch ----------------
static __device__ float  g_f32[(size_t)B_ * 2048];   // aliased as half buffer A
static __device__ __half g_h0[(size_t)B_ * 2048];    // half buffer B
static __device__ __half g_h1[(size_t)B_ * 256];     // z_enh
static __device__ __half g_cvt[32505856];            // x + weights, fp16

// offsets into g_cvt (halfs)
#define OFF_X    0
#define OFF_EW1  25165824
#define OFF_EW2  25952256
#define OFF_MUW  27000832
#define OFF_LVW  27262976
#define OFF_DIW  27525120
#define OFF_DW1  27787264
#define OFF_DW2  28835840
#define OFF_DW3  30932992

// ---------------- helpers ----------------
__device__ __forceinline__ uint32_t smem_u32(const void* p) {
    uint32_t a;
    asm("{ .reg .u64 t; cvta.to.shared.u64 t, %1; cvt.u32.u64 %0, t; }" : "=r"(a) : "l"(p));
    return a;
}
__device__ __forceinline__ void cp16(uint32_t sa, const void* g) {
    asm volatile("cp.async.cg.shared.global [%0], [%1], 16;" :: "r"(sa), "l"(g));
}
__device__ __forceinline__ void mma16(float* c, uint32_t a0, uint32_t a1, uint32_t a2, uint32_t a3,
                                      uint32_t b0, uint32_t b1) {
    asm volatile("mma.sync.aligned.m16n8k16.row.col.f32.f16.f16.f32 "
                 "{%0,%1,%2,%3}, {%4,%5,%6,%7}, {%8,%9}, {%0,%1,%2,%3};"
                 : "+f"(c[0]), "+f"(c[1]), "+f"(c[2]), "+f"(c[3])
                 : "r"(a0), "r"(a1), "r"(a2), "r"(a3), "r"(b0), "r"(b1));
}
__device__ __forceinline__ void ldm4(uint32_t* r, uint32_t addr) {
    asm volatile("ldmatrix.sync.aligned.m8n8.x4.shared.b16 {%0,%1,%2,%3}, [%4];"
                 : "=r"(r[0]), "=r"(r[1]), "=r"(r[2]), "=r"(r[3]) : "r"(addr));
}

// ===================================================================
// conv_h: fp32 -> fp16 plain. One half2 per thread.
// ===================================================================
extern "C" __global__ void __launch_bounds__(256)
conv_h(const float* __restrict__ src, __half* __restrict__ dst, int n2)
{
    int idx = blockIdx.x * 256 + threadIdx.x;
    if (idx < n2)
        ((__half2*)dst)[idx] = __floats2half2_rn(src[idx * 2], src[idx * 2 + 1]);
}

// ===================================================================
// conv_w: all 8 weight matrices in one launch.
// ===================================================================
extern "C" __global__ void __launch_bounds__(256)
conv_w(const float* s0, const float* s1, const float* s2, const float* s3,
       const float* s4, const float* s5, const float* s6, const float* s7,
       __half* __restrict__ cvt)
{
    int b = blockIdx.x;
    const float* src; size_t doff; int lb;
    if      (b < 1536)  { src = s0; doff = OFF_EW1; lb = b; }
    else if (b < 3584)  { src = s1; doff = OFF_EW2; lb = b - 1536; }
    else if (b < 4096)  { src = s2; doff = OFF_MUW; lb = b - 3584; }
    else if (b < 4608)  { src = s3; doff = OFF_LVW; lb = b - 4096; }
    else if (b < 5120)  { src = s4; doff = OFF_DIW; lb = b - 4608; }
    else if (b < 7168)  { src = s5; doff = OFF_DW1; lb = b - 5120; }
    else if (b < 11264) { src = s6; doff = OFF_DW2; lb = b - 7168; }
    else                { src = s7; doff = OFF_DW3; lb = b - 11264; }
    int idx = lb * 256 + threadIdx.x;
    ((__half2*)(cvt + doff))[idx] = __floats2half2_rn(src[idx * 2], src[idx * 2 + 1]);
}

// ===================================================================
// GEMM: C[B, Nt] = A[B, K] @ W[Nt, K]^T + bias
// CTA 128x128, 128 threads, 4 warps (2m x 2n), warp tile 64x64.
// 3-stage cp.async, 96KB smem -> 2 CTAs/SM. ldmatrix fragment loads.
// mode bit0: lrelu; bit1: fp16 output (staged via smem); bit2: split fp32
//   output (Nt=512: cols<256 -> Cv/bias, else Cv2/bias2, stride 256).
// ===================================================================
extern "C" __global__ void __launch_bounds__(NTHREAD, 2)
gemm_h(const __half* __restrict__ A, const __half* __restrict__ W,
       const float* __restrict__ bias, const float* __restrict__ bias2,
       void* __restrict__ Cv, void* __restrict__ Cv2,
       int K, int Nt, int mode)
{
    extern __shared__ char smem[];
    const uint32_t sb = smem_u32(smem);
    const int tid = threadIdx.x;
    const int wid = tid >> 5;
    const int lid = tid & 31;
    const int g = lid >> 2;
    const int t = lid & 3;
    const int m0 = blockIdx.y * TM;
    const int n0 = blockIdx.x * TN;
    const int wm = (wid & 1) * 64;     // 2 m warp-positions
    const int wn = (wid >> 1) * 64;    // 2 n warp-positions

    // ldmatrix lane constants
    const int e    = lid & 7;
    const int bsel = (lid >> 3) & 1;
    const int hsel = lid >> 4;
    const uint32_t rowA = (uint32_t)(wm + e + bsel * 8) * 128;
    const uint32_t rowB = (uint32_t)(wn + e + bsel * 8) * 128;

    // cp.async mapping: 2048 16B chunks/stage; 16 per thread (8 A + 8 W rows)
    const int brow = tid >> 3, seg = tid & 7;      // brow 0..15
    const __half* srcA = A + (size_t)(m0 + brow) * K + seg * 8;
    const __half* srcW = W + (size_t)(n0 + brow) * K + seg * 8;
    const uint32_t dA = sb + brow * 128 + ((seg ^ (brow & 7)) * 16);
    const uint32_t dW = dA + AT_BYTES;
    const size_t rstep = (size_t)16 * K;           // 16 rows per sub-iteration

    const int KC = K >> 6;

    // prologue: fill 2 of 3 slots
#pragma unroll
    for (int s = 0; s < 2; s++) {
        const __half* pa = srcA + s * 64;
        const __half* pw = srcW + s * 64;
        uint32_t off = s * STG_BYTES;
#pragma unroll
        for (int i = 0; i < 8; i++) cp16(dA + off + i * 2048, pa + i * rstep);
#pragma unroll
        for (int i = 0; i < 8; i++) cp16(dW + off + i * 2048, pw + i * rstep);
        asm volatile("cp.async.commit_group;" ::: "memory");
    }

    float acc[4][8][4];
#pragma unroll
    for (int mf = 0; mf < 4; mf++)
#pragma unroll
        for (int nf = 0; nf < 8; nf++)
#pragma unroll
            for (int j = 0; j < 4; j++) acc[mf][nf][j] = 0.f;

    for (int kc = 0; kc < KC; kc++) {
        if (kc < KC - 1) asm volatile("cp.async.wait_group 1;" ::: "memory");
        else             asm volatile("cp.async.wait_group 0;" ::: "memory");
        __syncthreads();

        // refill: chunk kc+2 into slot (kc+2)%3 (its compute ended last iter)
        if (kc + 2 < KC) {
            int fs = (kc + 2) % 3;
            const __half* pa = srcA + (kc + 2) * 64;
            const __half* pw = srcW + (kc + 2) * 64;
            uint32_t off = fs * STG_BYTES;
#pragma unroll
            for (int i = 0; i < 8; i++) cp16(dA + off + i * 2048, pa + i * rstep);
#pragma unroll
            for (int i = 0; i < 8; i++) cp16(dW + off + i * 2048, pw + i * rstep);
            asm volatile("cp.async.commit_group;" ::: "memory");
        }

        const int slot = kc % 3;
        const uint32_t sAc = sb + slot * STG_BYTES;
        const uint32_t sWc = sAc + AT_BYTES;

        // double-buffered fragments over 4 k16-steps
        uint32_t af[2][4][4], bf[2][4][4];
        {
            const uint32_t so = (uint32_t)((hsel ^ e) * 16);
#pragma unroll
            for (int mf = 0; mf < 4; mf++) ldm4(af[0][mf], sAc + rowA + mf * 2048 + so);
#pragma unroll
            for (int q = 0; q < 4; q++)  ldm4(bf[0][q], sWc + rowB + q * 2048 + so);
        }
#pragma unroll
        for (int j = 0; j < 4; j++) {
            const int cur = j & 1, nxt = cur ^ 1;
            if (j < 3) {
                const uint32_t so = (uint32_t)(((2 * (j + 1) + hsel) ^ e) * 16);
#pragma unroll
                for (int mf = 0; mf < 4; mf++) ldm4(af[nxt][mf], sAc + rowA + mf * 2048 + so);
#pragma unroll
                for (int q = 0; q < 4; q++)  ldm4(bf[nxt][q], sWc + rowB + q * 2048 + so);
            }
#pragma unroll
            for (int mf = 0; mf < 4; mf++)
#pragma unroll
                for (int q = 0; q < 4; q++) {
                    mma16(acc[mf][2 * q],     af[cur][mf][0], af[cur][mf][1],
                          af[cur][mf][2], af[cur][mf][3], bf[cur][q][0], bf[cur][q][2]);
                    mma16(acc[mf][2 * q + 1], af[cur][mf][0], af[cur][mf][1],
                          af[cur][mf][2], af[cur][mf][3], bf[cur][q][1], bf[cur][q][3]);
                }
        }
    }

    if (mode & 4) {
        // split fp32 output: Nt==512
#pragma unroll
        for (int nf = 0; nf < 8; nf++) {
            const int ng = n0 + wn + nf * 8 + t * 2;
            float* C = (ng < 256) ? (float*)Cv : (float*)Cv2;
            const float* bp = (ng < 256) ? bias : bias2;
            const int n = ng & 255;
            const float2 bn = *(const float2*)(bp + n);
#pragma unroll
            for (int mf = 0; mf < 4; mf++) {
                const int m = m0 + wm + mf * 16 + g;
                *(float2*)(C + (size_t)m * 256 + n) =
                    make_float2(acc[mf][nf][0] + bn.x, acc[mf][nf][1] + bn.y);
                *(float2*)(C + (size_t)(m + 8) * 256 + n) =
                    make_float2(acc[mf][nf][2] + bn.x, acc[mf][nf][3] + bn.y);
            }
        }
    } else if (!(mode & 2)) {
        float* C = (float*)Cv;
#pragma unroll
        for (int nf = 0; nf < 8; nf++) {
            const int n = n0 + wn + nf * 8 + t * 2;
            const float2 bn = *(const float2*)(bias + n);
#pragma unroll
            for (int mf = 0; mf < 4; mf++) {
                const int m = m0 + wm + mf * 16 + g;
                float v0 = acc[mf][nf][0] + bn.x;
                float v1 = acc[mf][nf][1] + bn.y;
                float v2 = acc[mf][nf][2] + bn.x;
                float v3 = acc[mf][nf][3] + bn.y;
                if (mode & 1) {
                    v0 = v0 >= 0.f ? v0 : 0.2f * v0;
                    v1 = v1 >= 0.f ? v1 : 0.2f * v1;
                    v2 = v2 >= 0.f ? v2 : 0.2f * v2;
                    v3 = v3 >= 0.f ? v3 : 0.2f * v3;
                }
                *(float2*)(C + (size_t)m * Nt + n)       = make_float2(v0, v1);
                *(float2*)(C + (size_t)(m + 8) * Nt + n) = make_float2(v2, v3);
            }
        }
    } else {
        // fp16 output staged through smem (stride 68 half2 rows, conflict-free)
        __half* C = (__half*)Cv;
        __syncthreads();
        __half2* se = (__half2*)smem;           // 128 rows x 68 half2 (34.8KB)
#pragma unroll
        for (int nf = 0; nf < 8; nf++) {
            const int n = wn + nf * 8 + t * 2;
            const float2 bn = *(const float2*)(bias + n0 + n);
#pragma unroll
            for (int mf = 0; mf < 4; mf++) {
                const int m = wm + mf * 16 + g;
                float v0 = acc[mf][nf][0] + bn.x;
                float v1 = acc[mf][nf][1] + bn.y;
                float v2 = acc[mf][nf][2] + bn.x;
                float v3 = acc[mf][nf][3] + bn.y;
                if (mode & 1) {
                    v0 = v0 >= 0.f ? v0 : 0.2f * v0;
                    v1 = v1 >= 0.f ? v1 : 0.2f * v1;
                    v2 = v2 >= 0.f ? v2 : 0.2f * v2;
                    v3 = v3 >= 0.f ? v3 : 0.2f * v3;
                }
                se[m * 68 + (n >> 1)]       = __floats2half2_rn(v0, v1);
                se[(m + 8) * 68 + (n >> 1)] = __floats2half2_rn(v2, v3);
            }
        }
        __syncthreads();
        // 128 rows x 16 uint4 per row = 2048 uint4; 16 iters x 128 threads
#pragma unroll
        for (int i = 0; i < 16; i++) {
            int lin = tid + i * NTHREAD;
            int row = lin >> 4, f8 = lin & 15;
            *(uint4*)(C + (size_t)(m0 + row) * Nt + n0 + f8 * 8) =
                *(const uint4*)((const __half2*)smem + row * 68 + f8 * 4);
        }
    }
}

// ===================================================================
// LayerNorm + leaky relu, warp-per-row. uint4 loads, convert-on-use.
// ===================================================================
extern "C" __global__ void __launch_bounds__(256)
ln_lrelu(const __half* __restrict__ X, __half* __restrict__ Y,
         const float* __restrict__ gw, const float* __restrict__ bw, int H)
{
    const int w = threadIdx.x >> 5, l = threadIdx.x & 31;
    const size_t r = (size_t)blockIdx.x * 8 + w;
    const uint4* x4 = (const uint4*)(X + r * H);
    uint4* y4 = (uint4*)(Y + r * H);
    const int V = H >> 8;

    uint4 v[8];
    float s = 0.f, s2 = 0.f;
#pragma unroll 8
    for (int i = 0; i < V; i++) {
        v[i] = x4[l + (i << 5)];
        const __half2* h2 = (const __half2*)&v[i];
#pragma unroll
        for (int j = 0; j < 4; j++) {
            float2 f = __half22float2(h2[j]);
            s  += f.x + f.y;
            s2 += f.x * f.x + f.y * f.y;
        }
    }
#pragma unroll
    for (int o = 16; o; o >>= 1) {
        s  += __shfl_xor_sync(~0u, s,  o);
        s2 += __shfl_xor_sync(~0u, s2, o);
    }
    const float inv = 1.f / (float)H;
    const float mu = s * inv;
    const float var = s2 * inv - mu * mu;
    const float rs = rsqrtf(var + 1e-5f);

#pragma unroll 8
    for (int i = 0; i < V; i++) {
        const int c8 = (l + (i << 5)) * 2;
        const float4 g0 = ((const float4*)gw)[c8];
        const float4 g1 = ((const float4*)gw)[c8 + 1];
        const float4 b0 = ((const float4*)bw)[c8];
        const float4 b1 = ((const float4*)bw)[c8 + 1];
        const __half2* h2 = (const __half2*)&v[i];
        float2 f0 = __half22float2(h2[0]);
        float2 f1 = __half22float2(h2[1]);
        float2 f2 = __half22float2(h2[2]);
        float2 f3 = __half22float2(h2[3]);
        float o0 = (f0.x - mu) * rs * g0.x + b0.x;
        float o1 = (f0.y - mu) * rs * g0.y + b0.y;
        float o2 = (f1.x - mu) * rs * g0.z + b0.z;
        float o3 = (f1.y - mu) * rs * g0.w + b0.w;
        float o4 = (f2.x - mu) * rs * g1.x + b1.x;
        float o5 = (f2.y - mu) * rs * g1.y + b1.y;
        float o6 = (f3.x - mu) * rs * g1.z + b1.z;
        float o7 = (f3.y - mu) * rs * g1.w + b1.w;
        o0 = o0 >= 0.f ? o0 : 0.2f * o0;  o1 = o1 >= 0.f ? o1 : 0.2f * o1;
        o2 = o2 >= 0.f ? o2 : 0.2f * o2;  o3 = o3 >= 0.f ? o3 : 0.2f * o3;
        o4 = o4 >= 0.f ? o4 : 0.2f * o4;  o5 = o5 >= 0.f ? o5 : 0.2f * o5;
        o6 = o6 >= 0.f ? o6 : 0.2f * o6;  o7 = o7 >= 0.f ? o7 : 0.2f * o7;
        uint4 ov;
        __half2* oh = (__half2*)&ov;
        oh[0] = __floats2half2_rn(o0, o1);
        oh[1] = __floats2half2_rn(o2, o3);
        oh[2] = __floats2half2_rn(o4, o5);
        oh[3] = __floats2half2_rn(o6, o7);
        y4[l + (i << 5)] = ov;
    }
}

// ===================================================================
// Reparameterize + context-memory attention. One warp per row.
// ===================================================================
extern "C" __global__ void __launch_bounds__(256)
reparam_attn(const float* __restrict__ mu, const float* __restrict__ lv,
             const float* __restrict__ eps, const float* __restrict__ ctx,
             __half* __restrict__ zout)
{
    __shared__ float sctx[32 * 257];
    __shared__ float sz[8][256];
    __shared__ float sat[8][32];
    const int t = threadIdx.x, w = t >> 5, l = t & 31;
    for (int i = t; i < 32 * 256; i += 256) {
        int m = i >> 8, k = i & 255;
        sctx[m * 257 + k] = ctx[i];
    }
    __syncthreads();
    const size_t r = (size_t)blockIdx.x * 8 + w;
    const float* murow = mu + r * 256;
    const float* lvrow = lv + r * 256;
    const float* erow  = eps + r * 256;
    float z[8];
#pragma unroll
    for (int j = 0; j < 4; j++) {
        int k = j * 64 + 2 * l;
        z[j * 2]     = murow[k]     + erow[k]     * expf(0.5f * lvrow[k]);
        z[j * 2 + 1] = murow[k + 1] + erow[k + 1] * expf(0.5f * lvrow[k + 1]);
        sz[w][k] = z[j * 2];
        sz[w][k + 1] = z[j * 2 + 1];
    }
    __syncwarp();
    float dot = 0.f;
    const float* cm = &sctx[l * 257];
#pragma unroll 8
    for (int k = 0; k < 256; k++) dot += sz[w][k] * cm[k];
    float mx = dot;
#pragma unroll
    for (int o = 16; o; o >>= 1) mx = fmaxf(mx, __shfl_xor_sync(~0u, mx, o));
    float e = expf(dot - mx);
    float sum = e;
#pragma unroll
    for (int o = 16; o; o >>= 1) sum += __shfl_xor_sync(~0u, sum, o);
    sat[w][l] = e / sum;
    __syncwarp();
    __half2* zo = (__half2*)(zout + r * 256);
#pragma unroll
    for (int j = 0; j < 4; j++) {
        int k = j * 64 + 2 * l;
        float a0 = 0.f, a1 = 0.f;
#pragma unroll
        for (int m = 0; m < 32; m++) {
            a0 += sat[w][m] * sctx[m * 257 + k];
            a1 += sat[w][m] * sctx[m * 257 + k + 1];
        }
        zo[k >> 1] = __floats2half2_rn(z[j * 2] + 0.1f * a0, z[j * 2 + 1] + 0.1f * a1);
    }
}

// ===================================================================
extern "C" void kernel_launch(void* const* d_in, const int* in_sizes, int n_in,
                              void* d_out, int out_size)
{
    (void)in_sizes; (void)n_in; (void)out_size;
    const float* x      = (const float*)d_in[0];
    const float* eps    = (const float*)d_in[1];
    const float* enc_w1 = (const float*)d_in[2];
    const float* enc_b1 = (const float*)d_in[3];
    const float* ln1_g  = (const float*)d_in[4];
    const float* ln1_b  = (const float*)d_in[5];
    const float* enc_w2 = (const float*)d_in[6];
    const float* enc_b2 = (const float*)d_in[7];
    const float* ln2_g  = (const float*)d_in[8];
    const float* ln2_b  = (const float*)d_in[9];
    const float* mu_w   = (const float*)d_in[10];
    const float* mu_b   = (const float*)d_in[11];
    const float* lv_w   = (const float*)d_in[12];
    const float* lv_b   = (const float*)d_in[13];
    const float* di_w   = (const float*)d_in[14];
    const float* di_b   = (const float*)d_in[15];
    const float* dec_w1 = (const float*)d_in[16];
    const float* dec_b1 = (const float*)d_in[17];
    const float* dln1_g = (const float*)d_in[18];
    const float* dln1_b = (const float*)d_in[19];
    const float* dec_w2 = (const float*)d_in[20];
    const float* dec_b2 = (const float*)d_in[21];
    const float* dln2_g = (const float*)d_in[22];
    const float* dln2_b = (const float*)d_in[23];
    const float* dec_w3 = (const float*)d_in[24];
    const float* dec_b3 = (const float*)d_in[25];
    const float* ctx    = (const float*)d_in[26];

    float* out    = (float*)d_out;
    float* out_mu = out + (size_t)B_ * D_;
    float* out_lv = out_mu + (size_t)B_ * L_;

    float* f32buf = nullptr; __half* hB = nullptr; __half* h1 = nullptr; __half* cvt = nullptr;
    cudaGetSymbolAddress((void**)&f32buf, g_f32);
    cudaGetSymbolAddress((void**)&hB, g_h0);
    cudaGetSymbolAddress((void**)&h1, g_h1);
    cudaGetSymbolAddress((void**)&cvt, g_cvt);
    __half* hA = (__half*)f32buf;

    cudaFuncSetAttribute(gemm_h, cudaFuncAttributeMaxDynamicSharedMemorySize, SM_TOTAL);

    conv_h<<<(B_ * D_ / 2 + 255) / 256, 256>>>(x, cvt + OFF_X, B_ * D_ / 2);
    conv_w<<<14336, 256>>>(enc_w1, enc_w2, mu_w, lv_w, di_w, dec_w1, dec_w2, dec_w3, cvt);

    const dim3 blk(NTHREAD);
    const dim3 gH(H_ / TN, B_ / TM);        // (8, 256)
    const dim3 gML(512 / TN, B_ / TM);      // (4, 256) merged mu+lv
    const dim3 g2H(2 * H_ / TN, B_ / TM);   // (16, 256)
    const dim3 gD(D_ / TN, B_ / TM);        // (6, 256)

    // encoder
    gemm_h<<<gH, blk, SM_TOTAL>>>(cvt + OFF_X, cvt + OFF_EW1, enc_b1, nullptr,
                                  hA, nullptr, D_, H_, 2);
    ln_lrelu<<<B_ / 8, 256>>>(hA, hB, ln1_g, ln1_b, H_);
    gemm_h<<<gH, blk, SM_TOTAL>>>(hB, cvt + OFF_EW2, enc_b2, nullptr,
                                  hA, nullptr, H_, H_, 2);
    ln_lrelu<<<B_ / 8, 256>>>(hA, hB, ln2_g, ln2_b, H_);
    // merged mu + logvar (weights contiguous at OFF_MUW)
    gemm_h<<<gML, blk, SM_TOTAL>>>(hB, cvt + OFF_MUW, mu_b, lv_b,
                                   out_mu, out_lv, H_, 512, 4);
    // reparameterize + context attention
    reparam_attn<<<B_ / 8, 256>>>(out_mu, out_lv, eps, ctx, h1);
    // decoder
    gemm_h<<<gH, blk, SM_TOTAL>>>(h1, cvt + OFF_DIW, di_b, nullptr,
                                  hA, nullptr, L_, H_, 3);
    gemm_h<<<gH, blk, SM_TOTAL>>>(hA, cvt + OFF_DW1, dec_b1, nullptr,
                                  hB, nullptr, H_, H_, 2);
    ln_lrelu<<<B_ / 8, 256>>>(hB, hA, dln1_g, dln1_b, H_);
    gemm_h<<<g2H, blk, SM_TOTAL>>>(hA, cvt + OFF_DW2, dec_b2, nullptr,
                                   hB, nullptr, H_, 2 * H_, 2);
    ln_lrelu<<<B_ / 8, 256>>>(hB, hA, dln2_g, dln2_b, 2 * H_);
    gemm_h<<<gD, blk, SM_TOTAL>>>(hA, cvt + OFF_DW3, dec_b3, nullptr,
                                  out, nullptr, 2 * H_, D_, 0);
}

// round 15
// speedup vs baseline: 2.5134x; 1.0497x over previous
#include <cuda_runtime.h>
#include <cuda_fp16.h>
#include <cstdint>

#define B_ 32768
#define D_ 768
#define H_ 1024
#define L_ 256

// ---------------- GEMM tiling ----------------
#define TM 128
#define TN 128
#define NTHREAD 128
#define AT_BYTES (128 * 128)              // A tile: 128 rows x 128B
#define WT_BYTES (128 * 128)              // W tile: 128 rows x 128B
#define STG_BYTES (AT_BYTES + WT_BYTES)   // 32768
#define NSTAGE 3
#define SM_TOTAL (NSTAGE * STG_BYTES)     // 98304 -> 2 CTAs/SM

// ---------------- scratch ----------------
static __device__ float  g_f32[(size_t)B_ * 2048];   // aliased as half buffer A
static __device__ __half g_h0[(size_t)B_ * 2048];    // half buffer B
static __device__ __half g_h1[(size_t)B_ * 256];     // z_enh
static __device__ __half g_cvt[32505856];            // x + weights, fp16

// offsets into g_cvt (halfs)
#define OFF_X    0
#define OFF_EW1  25165824
#define OFF_EW2  25952256
#define OFF_MUW  27000832
#define OFF_LVW  27262976
#define OFF_DIW  27525120
#define OFF_DW1  27787264
#define OFF_DW2  28835840
#define OFF_DW3  30932992

// ---------------- helpers ----------------
__device__ __forceinline__ uint32_t smem_u32(const void* p) {
    uint32_t a;
    asm("{ .reg .u64 t; cvta.to.shared.u64 t, %1; cvt.u32.u64 %0, t; }" : "=r"(a) : "l"(p));
    return a;
}
__device__ __forceinline__ void cp16(uint32_t sa, const void* g) {
    asm volatile("cp.async.cg.shared.global [%0], [%1], 16;" :: "r"(sa), "l"(g));
}
__device__ __forceinline__ void mma16(float* c, uint32_t a0, uint32_t a1, uint32_t a2, uint32_t a3,
                                      uint32_t b0, uint32_t b1) {
    asm volatile("mma.sync.aligned.m16n8k16.row.col.f32.f16.f16.f32 "
                 "{%0,%1,%2,%3}, {%4,%5,%6,%7}, {%8,%9}, {%0,%1,%2,%3};"
                 : "+f"(c[0]), "+f"(c[1]), "+f"(c[2]), "+f"(c[3])
                 : "r"(a0), "r"(a1), "r"(a2), "r"(a3), "r"(b0), "r"(b1));
}
__device__ __forceinline__ void ldm4(uint32_t* r, uint32_t addr) {
    asm volatile("ldmatrix.sync.aligned.m8n8.x4.shared.b16 {%0,%1,%2,%3}, [%4];"
                 : "=r"(r[0]), "=r"(r[1]), "=r"(r[2]), "=r"(r[3]) : "r"(addr));
}

// ===================================================================
// conv_h: fp32 -> fp16 plain. One half2 per thread.
// ===================================================================
extern "C" __global__ void __launch_bounds__(256)
conv_h(const float* __restrict__ src, __half* __restrict__ dst, int n2)
{
    int idx = blockIdx.x * 256 + threadIdx.x;
    if (idx < n2)
        ((__half2*)dst)[idx] = __floats2half2_rn(src[idx * 2], src[idx * 2 + 1]);
}

// ===================================================================
// conv_w: all 8 weight matrices in one launch.
// ===================================================================
extern "C" __global__ void __launch_bounds__(256)
conv_w(const float* s0, const float* s1, const float* s2, const float* s3,
       const float* s4, const float* s5, const float* s6, const float* s7,
       __half* __restrict__ cvt)
{
    int b = blockIdx.x;
    const float* src; size_t doff; int lb;
    if      (b < 1536)  { src = s0; doff = OFF_EW1; lb = b; }
    else if (b < 3584)  { src = s1; doff = OFF_EW2; lb = b - 1536; }
    else if (b < 4096)  { src = s2; doff = OFF_MUW; lb = b - 3584; }
    else if (b < 4608)  { src = s3; doff = OFF_LVW; lb = b - 4096; }
    else if (b < 5120)  { src = s4; doff = OFF_DIW; lb = b - 4608; }
    else if (b < 7168)  { src = s5; doff = OFF_DW1; lb = b - 5120; }
    else if (b < 11264) { src = s6; doff = OFF_DW2; lb = b - 7168; }
    else                { src = s7; doff = OFF_DW3; lb = b - 11264; }
    int idx = lb * 256 + threadIdx.x;
    ((__half2*)(cvt + doff))[idx] = __floats2half2_rn(src[idx * 2], src[idx * 2 + 1]);
}

// ===================================================================
// GEMM: C[B, Nt] = A[B, K] @ W[Nt, K]^T + bias
// CTA 128x128, 128 threads, 4 warps (2m x 2n), warp tile 64x64.
// 3-stage cp.async, 96KB smem -> 2 CTAs/SM. ldmatrix fragment loads.
// mode bit0: lrelu; bit1: fp16 output (staged via smem); bit2: split fp32
//   output (Nt=512: cols<256 -> Cv/bias, else Cv2/bias2, stride 256).
// ===================================================================
extern "C" __global__ void __launch_bounds__(NTHREAD, 2)
gemm_h(const __half* __restrict__ A, const __half* __restrict__ W,
       const float* __restrict__ bias, const float* __restrict__ bias2,
       void* __restrict__ Cv, void* __restrict__ Cv2,
       int K, int Nt, int mode)
{
    extern __shared__ char smem[];
    const uint32_t sb = smem_u32(smem);
    const int tid = threadIdx.x;
    const int wid = tid >> 5;
    const int lid = tid & 31;
    const int g = lid >> 2;
    const int t = lid & 3;
    const int m0 = blockIdx.y * TM;
    const int n0 = blockIdx.x * TN;
    const int wm = (wid & 1) * 64;     // 2 m warp-positions
    const int wn = (wid >> 1) * 64;    // 2 n warp-positions

    // ldmatrix lane constants
    const int e    = lid & 7;
    const int bsel = (lid >> 3) & 1;
    const int hsel = lid >> 4;
    const uint32_t rowA = (uint32_t)(wm + e + bsel * 8) * 128;
    const uint32_t rowB = (uint32_t)(wn + e + bsel * 8) * 128;

    // cp.async mapping: 2048 16B chunks/stage; 16 per thread (8 A + 8 W rows)
    const int brow = tid >> 3, seg = tid & 7;      // brow 0..15
    const __half* srcA = A + (size_t)(m0 + brow) * K + seg * 8;
    const __half* srcW = W + (size_t)(n0 + brow) * K + seg * 8;
    const uint32_t dA = sb + brow * 128 + ((seg ^ (brow & 7)) * 16);
    const uint32_t dW = dA + AT_BYTES;
    const size_t rstep = (size_t)16 * K;           // 16 rows per sub-iteration

    const int KC = K >> 6;

    // prologue: fill 2 of 3 slots
#pragma unroll
    for (int s = 0; s < 2; s++) {
        const __half* pa = srcA + s * 64;
        const __half* pw = srcW + s * 64;
        uint32_t off = s * STG_BYTES;
#pragma unroll
        for (int i = 0; i < 8; i++) cp16(dA + off + i * 2048, pa + i * rstep);
#pragma unroll
        for (int i = 0; i < 8; i++) cp16(dW + off + i * 2048, pw + i * rstep);
        asm volatile("cp.async.commit_group;" ::: "memory");
    }

    float acc[4][8][4];
#pragma unroll
    for (int mf = 0; mf < 4; mf++)
#pragma unroll
        for (int nf = 0; nf < 8; nf++)
#pragma unroll
            for (int j = 0; j < 4; j++) acc[mf][nf][j] = 0.f;

    for (int kc = 0; kc < KC; kc++) {
        if (kc < KC - 1) asm volatile("cp.async.wait_group 1;" ::: "memory");
        else             asm volatile("cp.async.wait_group 0;" ::: "memory");
        __syncthreads();

        // refill: chunk kc+2 into slot (kc+2)%3 (its compute ended last iter)
        if (kc + 2 < KC) {
            int fs = (kc + 2) % 3;
            const __half* pa = srcA + (kc + 2) * 64;
            const __half* pw = srcW + (kc + 2) * 64;
            uint32_t off = fs * STG_BYTES;
#pragma unroll
            for (int i = 0; i < 8; i++) cp16(dA + off + i * 2048, pa + i * rstep);
#pragma unroll
            for (int i = 0; i < 8; i++) cp16(dW + off + i * 2048, pw + i * rstep);
            asm volatile("cp.async.commit_group;" ::: "memory");
        }

        const int slot = kc % 3;
        const uint32_t sAc = sb + slot * STG_BYTES;
        const uint32_t sWc = sAc + AT_BYTES;

        // double-buffered fragments over 4 k16-steps
        uint32_t af[2][4][4], bf[2][4][4];
        {
            const uint32_t so = (uint32_t)((hsel ^ e) * 16);
#pragma unroll
            for (int mf = 0; mf < 4; mf++) ldm4(af[0][mf], sAc + rowA + mf * 2048 + so);
#pragma unroll
            for (int q = 0; q < 4; q++)  ldm4(bf[0][q], sWc + rowB + q * 2048 + so);
        }
#pragma unroll
        for (int j = 0; j < 4; j++) {
            const int cur = j & 1, nxt = cur ^ 1;
            if (j < 3) {
                const uint32_t so = (uint32_t)(((2 * (j + 1) + hsel) ^ e) * 16);
#pragma unroll
                for (int mf = 0; mf < 4; mf++) ldm4(af[nxt][mf], sAc + rowA + mf * 2048 + so);
#pragma unroll
                for (int q = 0; q < 4; q++)  ldm4(bf[nxt][q], sWc + rowB + q * 2048 + so);
            }
#pragma unroll
            for (int mf = 0; mf < 4; mf++)
#pragma unroll
                for (int q = 0; q < 4; q++) {
                    mma16(acc[mf][2 * q],     af[cur][mf][0], af[cur][mf][1],
                          af[cur][mf][2], af[cur][mf][3], bf[cur][q][0], bf[cur][q][2]);
                    mma16(acc[mf][2 * q + 1], af[cur][mf][0], af[cur][mf][1],
                          af[cur][mf][2], af[cur][mf][3], bf[cur][q][1], bf[cur][q][3]);
                }
        }
    }

    if (mode & 4) {
        // split fp32 output: Nt==512
#pragma unroll
        for (int nf = 0; nf < 8; nf++) {
            const int ng = n0 + wn + nf * 8 + t * 2;
            float* C = (ng < 256) ? (float*)Cv : (float*)Cv2;
            const float* bp = (ng < 256) ? bias : bias2;
            const int n = ng & 255;
            const float2 bn = *(const float2*)(bp + n);
#pragma unroll
            for (int mf = 0; mf < 4; mf++) {
                const int m = m0 + wm + mf * 16 + g;
                *(float2*)(C + (size_t)m * 256 + n) =
                    make_float2(acc[mf][nf][0] + bn.x, acc[mf][nf][1] + bn.y);
                *(float2*)(C + (size_t)(m + 8) * 256 + n) =
                    make_float2(acc[mf][nf][2] + bn.x, acc[mf][nf][3] + bn.y);
            }
        }
    } else if (!(mode & 2)) {
        float* C = (float*)Cv;
#pragma unroll
        for (int nf = 0; nf < 8; nf++) {
            const int n = n0 + wn + nf * 8 + t * 2;
            const float2 bn = *(const float2*)(bias + n);
#pragma unroll
            for (int mf = 0; mf < 4; mf++) {
                const int m = m0 + wm + mf * 16 + g;
                float v0 = acc[mf][nf][0] + bn.x;
                float v1 = acc[mf][nf][1] + bn.y;
                float v2 = acc[mf][nf][2] + bn.x;
                float v3 = acc[mf][nf][3] + bn.y;
                if (mode & 1) {
                    v0 = v0 >= 0.f ? v0 : 0.2f * v0;
                    v1 = v1 >= 0.f ? v1 : 0.2f * v1;
                    v2 = v2 >= 0.f ? v2 : 0.2f * v2;
                    v3 = v3 >= 0.f ? v3 : 0.2f * v3;
                }
                *(float2*)(C + (size_t)m * Nt + n)       = make_float2(v0, v1);
                *(float2*)(C + (size_t)(m + 8) * Nt + n) = make_float2(v2, v3);
            }
        }
    } else {
        // fp16 output staged through smem (stride 68 half2 rows, conflict-free)
        __half* C = (__half*)Cv;
        __syncthreads();
        __half2* se = (__half2*)smem;           // 128 rows x 68 half2 (34.8KB)
#pragma unroll
        for (int nf = 0; nf < 8; nf++) {
            const int n = wn + nf * 8 + t * 2;
            const float2 bn = *(const float2*)(bias + n0 + n);
#pragma unroll
            for (int mf = 0; mf < 4; mf++) {
                const int m = wm + mf * 16 + g;
                float v0 = acc[mf][nf][0] + bn.x;
                float v1 = acc[mf][nf][1] + bn.y;
                float v2 = acc[mf][nf][2] + bn.x;
                float v3 = acc[mf][nf][3] + bn.y;
                if (mode & 1) {
                    v0 = v0 >= 0.f ? v0 : 0.2f * v0;
                    v1 = v1 >= 0.f ? v1 : 0.2f * v1;
                    v2 = v2 >= 0.f ? v2 : 0.2f * v2;
                    v3 = v3 >= 0.f ? v3 : 0.2f * v3;
                }
                se[m * 68 + (n >> 1)]       = __floats2half2_rn(v0, v1);
                se[(m + 8) * 68 + (n >> 1)] = __floats2half2_rn(v2, v3);
            }
        }
        __syncthreads();
        // 128 rows x 16 uint4 per row = 2048 uint4; 16 iters x 128 threads
#pragma unroll
        for (int i = 0; i < 16; i++) {
            int lin = tid + i * NTHREAD;
            int row = lin >> 4, f8 = lin & 15;
            *(uint4*)(C + (size_t)(m0 + row) * Nt + n0 + f8 * 8) =
                *(const uint4*)((const __half2*)smem + row * 68 + f8 * 4);
        }
    }
}

// ===================================================================
// LayerNorm + leaky relu, warp-per-row, TWO-PASS (no data cached in
// regs -> low register count, high occupancy; 2nd read hits L2).
// ===================================================================
extern "C" __global__ void __launch_bounds__(256)
ln_lrelu(const __half* __restrict__ X, __half* __restrict__ Y,
         const float* __restrict__ gw, const float* __restrict__ bw, int H)
{
    const int w = threadIdx.x >> 5, l = threadIdx.x & 31;
    const size_t r = (size_t)blockIdx.x * 8 + w;
    const uint4* x4 = (const uint4*)(X + r * H);
    uint4* y4 = (uint4*)(Y + r * H);
    const int V = H >> 8;          // uint4 per lane: 4 (H=1024) or 8 (H=2048)

    // pass 1: stats
    float s = 0.f, s2 = 0.f;
    for (int i = 0; i < V; i++) {
        uint4 v = x4[l + (i << 5)];
        const __half2* h2 = (const __half2*)&v;
#pragma unroll
        for (int j = 0; j < 4; j++) {
            float2 f = __half22float2(h2[j]);
            s  += f.x + f.y;
            s2 += f.x * f.x + f.y * f.y;
        }
    }
#pragma unroll
    for (int o = 16; o; o >>= 1) {
        s  += __shfl_xor_sync(~0u, s,  o);
        s2 += __shfl_xor_sync(~0u, s2, o);
    }
    const float inv = 1.f / (float)H;
    const float mu = s * inv;
    const float var = s2 * inv - mu * mu;
    const float rs = rsqrtf(var + 1e-5f);

    // pass 2: re-read (L2-hot), normalize, write
    for (int i = 0; i < V; i++) {
        uint4 v = x4[l + (i << 5)];
        const int c8 = (l + (i << 5)) * 2;
        const float4 g0 = ((const float4*)gw)[c8];
        const float4 g1 = ((const float4*)gw)[c8 + 1];
        const float4 b0 = ((const float4*)bw)[c8];
        const float4 b1 = ((const float4*)bw)[c8 + 1];
        const __half2* h2 = (const __half2*)&v;
        float2 f0 = __half22float2(h2[0]);
        float2 f1 = __half22float2(h2[1]);
        float2 f2 = __half22float2(h2[2]);
        float2 f3 = __half22float2(h2[3]);
        float o0 = (f0.x - mu) * rs * g0.x + b0.x;
        float o1 = (f0.y - mu) * rs * g0.y + b0.y;
        float o2 = (f1.x - mu) * rs * g0.z + b0.z;
        float o3 = (f1.y - mu) * rs * g0.w + b0.w;
        float o4 = (f2.x - mu) * rs * g1.x + b1.x;
        float o5 = (f2.y - mu) * rs * g1.y + b1.y;
        float o6 = (f3.x - mu) * rs * g1.z + b1.z;
        float o7 = (f3.y - mu) * rs * g1.w + b1.w;
        o0 = o0 >= 0.f ? o0 : 0.2f * o0;  o1 = o1 >= 0.f ? o1 : 0.2f * o1;
        o2 = o2 >= 0.f ? o2 : 0.2f * o2;  o3 = o3 >= 0.f ? o3 : 0.2f * o3;
        o4 = o4 >= 0.f ? o4 : 0.2f * o4;  o5 = o5 >= 0.f ? o5 : 0.2f * o5;
        o6 = o6 >= 0.f ? o6 : 0.2f * o6;  o7 = o7 >= 0.f ? o7 : 0.2f * o7;
        uint4 ov;
        __half2* oh = (__half2*)&ov;
        oh[0] = __floats2half2_rn(o0, o1);
        oh[1] = __floats2half2_rn(o2, o3);
        oh[2] = __floats2half2_rn(o4, o5);
        oh[3] = __floats2half2_rn(o6, o7);
        y4[l + (i << 5)] = ov;
    }
}

// ===================================================================
// Reparameterize + context-memory attention. One warp per row.
// ===================================================================
extern "C" __global__ void __launch_bounds__(256)
reparam_attn(const float* __restrict__ mu, const float* __restrict__ lv,
             const float* __restrict__ eps, const float* __restrict__ ctx,
             __half* __restrict__ zout)
{
    __shared__ float sctx[32 * 257];
    __shared__ float sz[8][256];
    __shared__ float sat[8][32];
    const int t = threadIdx.x, w = t >> 5, l = t & 31;
    for (int i = t; i < 32 * 256; i += 256) {
        int m = i >> 8, k = i & 255;
        sctx[m * 257 + k] = ctx[i];
    }
    __syncthreads();
    const size_t r = (size_t)blockIdx.x * 8 + w;
    const float* murow = mu + r * 256;
    const float* lvrow = lv + r * 256;
    const float* erow  = eps + r * 256;
    float z[8];
#pragma unroll
    for (int j = 0; j < 4; j++) {
        int k = j * 64 + 2 * l;
        z[j * 2]     = murow[k]     + erow[k]     * expf(0.5f * lvrow[k]);
        z[j * 2 + 1] = murow[k + 1] + erow[k + 1] * expf(0.5f * lvrow[k + 1]);
        sz[w][k] = z[j * 2];
        sz[w][k + 1] = z[j * 2 + 1];
    }
    __syncwarp();
    float dot = 0.f;
    const float* cm = &sctx[l * 257];
#pragma unroll 8
    for (int k = 0; k < 256; k++) dot += sz[w][k] * cm[k];
    float mx = dot;
#pragma unroll
    for (int o = 16; o; o >>= 1) mx = fmaxf(mx, __shfl_xor_sync(~0u, mx, o));
    float e = expf(dot - mx);
    float sum = e;
#pragma unroll
    for (int o = 16; o; o >>= 1) sum += __shfl_xor_sync(~0u, sum, o);
    sat[w][l] = e / sum;
    __syncwarp();
    __half2* zo = (__half2*)(zout + r * 256);
#pragma unroll
    for (int j = 0; j < 4; j++) {
        int k = j * 64 + 2 * l;
        float a0 = 0.f, a1 = 0.f;
#pragma unroll
        for (int m = 0; m < 32; m++) {
            a0 += sat[w][m] * sctx[m * 257 + k];
            a1 += sat[w][m] * sctx[m * 257 + k + 1];
        }
        zo[k >> 1] = __floats2half2_rn(z[j * 2] + 0.1f * a0, z[j * 2 + 1] + 0.1f * a1);
    }
}

// ===================================================================
extern "C" void kernel_launch(void* const* d_in, const int* in_sizes, int n_in,
                              void* d_out, int out_size)
{
    (void)in_sizes; (void)n_in; (void)out_size;
    const float* x      = (const float*)d_in[0];
    const float* eps    = (const float*)d_in[1];
    const float* enc_w1 = (const float*)d_in[2];
    const float* enc_b1 = (const float*)d_in[3];
    const float* ln1_g  = (const float*)d_in[4];
    const float* ln1_b  = (const float*)d_in[5];
    const float* enc_w2 = (const float*)d_in[6];
    const float* enc_b2 = (const float*)d_in[7];
    const float* ln2_g  = (const float*)d_in[8];
    const float* ln2_b  = (const float*)d_in[9];
    const float* mu_w   = (const float*)d_in[10];
    const float* mu_b   = (const float*)d_in[11];
    const float* lv_w   = (const float*)d_in[12];
    const float* lv_b   = (const float*)d_in[13];
    const float* di_w   = (const float*)d_in[14];
    const float* di_b   = (const float*)d_in[15];
    const float* dec_w1 = (const float*)d_in[16];
    const float* dec_b1 = (const float*)d_in[17];
    const float* dln1_g = (const float*)d_in[18];
    const float* dln1_b = (const float*)d_in[19];
    const float* dec_w2 = (const float*)d_in[20];
    const float* dec_b2 = (const float*)d_in[21];
    const float* dln2_g = (const float*)d_in[22];
    const float* dln2_b = (const float*)d_in[23];
    const float* dec_w3 = (const float*)d_in[24];
    const float* dec_b3 = (const float*)d_in[25];
    const float* ctx    = (const float*)d_in[26];

    float* out    = (float*)d_out;
    float* out_mu = out + (size_t)B_ * D_;
    float* out_lv = out_mu + (size_t)B_ * L_;

    float* f32buf = nullptr; __half* hB = nullptr; __half* h1 = nullptr; __half* cvt = nullptr;
    cudaGetSymbolAddress((void**)&f32buf, g_f32);
    cudaGetSymbolAddress((void**)&hB, g_h0);
    cudaGetSymbolAddress((void**)&h1, g_h1);
    cudaGetSymbolAddress((void**)&cvt, g_cvt);
    __half* hA = (__half*)f32buf;

    cudaFuncSetAttribute(gemm_h, cudaFuncAttributeMaxDynamicSharedMemorySize, SM_TOTAL);

    conv_h<<<(B_ * D_ / 2 + 255) / 256, 256>>>(x, cvt + OFF_X, B_ * D_ / 2);
    conv_w<<<14336, 256>>>(enc_w1, enc_w2, mu_w, lv_w, di_w, dec_w1, dec_w2, dec_w3, cvt);

    const dim3 blk(NTHREAD);
    const dim3 gH(H_ / TN, B_ / TM);        // (8, 256)
    const dim3 gML(512 / TN, B_ / TM);      // (4, 256) merged mu+lv
    const dim3 g2H(2 * H_ / TN, B_ / TM);   // (16, 256)
    const dim3 gD(D_ / TN, B_ / TM);        // (6, 256)

    // encoder
    gemm_h<<<gH, blk, SM_TOTAL>>>(cvt + OFF_X, cvt + OFF_EW1, enc_b1, nullptr,
                                  hA, nullptr, D_, H_, 2);
    ln_lrelu<<<B_ / 8, 256>>>(hA, hB, ln1_g, ln1_b, H_);
    gemm_h<<<gH, blk, SM_TOTAL>>>(hB, cvt + OFF_EW2, enc_b2, nullptr,
                                  hA, nullptr, H_, H_, 2);
    ln_lrelu<<<B_ / 8, 256>>>(hA, hB, ln2_g, ln2_b, H_);
    // merged mu + logvar (weights contiguous at OFF_MUW)
    gemm_h<<<gML, blk, SM_TOTAL>>>(hB, cvt + OFF_MUW, mu_b, lv_b,
                                   out_mu, out_lv, H_, 512, 4);
    // reparameterize + context attention
    reparam_attn<<<B_ / 8, 256>>>(out_mu, out_lv, eps, ctx, h1);
    // decoder
    gemm_h<<<gH, blk, SM_TOTAL>>>(h1, cvt + OFF_DIW, di_b, nullptr,
                                  hA, nullptr, L_, H_, 3);
    gemm_h<<<gH, blk, SM_TOTAL>>>(hA, cvt + OFF_DW1, dec_b1, nullptr,
                                  hB, nullptr, H_, H_, 2);
    ln_lrelu<<<B_ / 8, 256>>>(hB, hA, dln1_g, dln1_b, H_);
    gemm_h<<<g2H, blk, SM_TOTAL>>>(hA, cvt + OFF_DW2, dec_b2, nullptr,
                                   hB, nullptr, H_, 2 * H_, 2);
    ln_lrelu<<<B_ / 8, 256>>>(hB, hA, dln2_g, dln2_b, 2 * H_);
    gemm_h<<<gD, blk, SM_TOTAL>>>(hA, cvt + OFF_DW3, dec_b3, nullptr,
                                  out, nullptr, 2 * H_, D_, 0);
}